// round 11
// baseline (speedup 1.0000x reference)
#include <cuda_runtime.h>
#include <cuda_bf16.h>
#include <math.h>
#include <stdint.h>

#define NPIX 16384            // 128*128

// ---------------------------------------------------------------------------
// Scratch (static device globals)
// ---------------------------------------------------------------------------
__device__ float g_i2h[6 * 2 * 192 * NPIX]; // i2h conv out, all t      151 MB
__device__ float g_f1p0[6 * 2 * 32 * NPIX]; // f1 input-half partials    50 MB
__device__ float g_fl [2 *  26 * NPIX];     // flows                    3.4 MB

// bf16-split packed operands (channel pairs per 32-bit word)
__device__ uint32_t g_ysbf_h[2 * 192 * NPIX], g_ysbf_l[2 * 192 * NPIX]; // stem out (c,c+1)
__device__ uint32_t g_hbf_h [2 *  32 * NPIX], g_hbf_l [2 *  32 * NPIX]; // hprev (c,c+1)
__device__ uint32_t g_f1bf_h[2 *  16 * NPIX], g_f1bf_l[2 *  16 * NPIX]; // f1 out (c,c+8)

// pre-converted weights: layouts match smem consumption order
__device__ uint32_t g_wi2h_h[3 * 4 * 9 * 8 * 64],  g_wi2h_l[3 * 4 * 9 * 8 * 64];
__device__ uint32_t g_wf1_h [2 * 4 * 25 * 8 * 32], g_wf1_l [2 * 4 * 25 * 8 * 32];
__device__ uint32_t g_wfl_h [2 * 25 * 8 * 32],     g_wfl_l [2 * 25 * 8 * 32];
__device__ uint32_t g_wret_h[2 * 13 * 4 * 8 * 96], g_wret_l[2 * 13 * 4 * 8 * 96];

__device__ __forceinline__ float leaky_f(float x) { return x >= 0.f ? x : 0.2f * x; }

// split two floats into packed bf16 hi-pair and lo-pair (v = hi + lo)
__device__ __forceinline__ void split2(float v0, float v1, uint32_t& h, uint32_t& l) {
    __nv_bfloat162 hb = __floats2bfloat162_rn(v0, v1);
    float h0 = __low2float(hb), h1 = __high2float(hb);
    __nv_bfloat162 lb = __floats2bfloat162_rn(v0 - h0, v1 - h1);
    h = *reinterpret_cast<uint32_t*>(&hb);
    l = *reinterpret_cast<uint32_t*>(&lb);
}

#define MMA_BF16(c0,c1,c2,c3, a0,a1,a2,a3, b0,b1)                              \
    asm volatile("mma.sync.aligned.m16n8k16.row.col.f32.bf16.bf16.f32 "        \
        "{%0,%1,%2,%3}, {%4,%5,%6,%7}, {%8,%9}, {%0,%1,%2,%3};"                \
        : "+f"(c0), "+f"(c1), "+f"(c2), "+f"(c3)                               \
        : "r"(a0), "r"(a1), "r"(a2), "r"(a3), "r"(b0), "r"(b1))

// ---------------------------------------------------------------------------
// Weight prep (run once per launch; weights are t-invariant)
// ---------------------------------------------------------------------------
__global__ void wprep_i2h_k(const float* __restrict__ w)
{
    int idx = blockIdx.x * 256 + threadIdx.x;
    if (idx >= 55296) return;
    int oc = idx & 63;
    int kp = (idx >> 6) & 7;
    int q  = idx >> 9;
    int tap = q % 9;
    int qc  = q / 9;
    int chunk = qc & 3, ocg = qc >> 2;
    int ic = chunk * 16 + 2 * kp;
    int o  = ocg * 64 + oc;
    float v0 = w[(o * 64 + ic    ) * 9 + tap];
    float v1 = w[(o * 64 + ic + 1) * 9 + tap];
    split2(v0, v1, g_wi2h_h[idx], g_wi2h_l[idx]);
}

__global__ void wprep_f1_k(const float* __restrict__ wi, const float* __restrict__ wh)
{
    int idx = blockIdx.x * 256 + threadIdx.x;
    if (idx >= 51200) return;
    int oc = idx & 31;
    int kp = (idx >> 5) & 7;
    int q  = idx >> 8;
    int tap = q % 25;
    int qc  = q / 25;
    int chunk = qc & 3, src = qc >> 2;
    int ic = chunk * 16 + 2 * kp;
    const float* w = src ? wh : wi;
    float v0 = w[(oc * 64 + ic    ) * 25 + tap];
    float v1 = w[(oc * 64 + ic + 1) * 25 + tap];
    split2(v0, v1, g_wf1_h[idx], g_wf1_l[idx]);
}

// flow: pairs (ic, ic+8) to match g_f1bf packing
__global__ void wprep_fl_k(const float* __restrict__ w)
{
    int idx = blockIdx.x * 256 + threadIdx.x;
    if (idx >= 12800) return;
    int oc = idx & 31;
    int kp = (idx >> 5) & 7;
    int q  = idx >> 8;
    int tap = q % 25;
    int chunk = q / 25;
    int ic0 = chunk * 16 + kp;
    float v0 = 0.f, v1 = 0.f;
    if (oc < 26) {
        v0 = w[(oc * 32 + ic0    ) * 25 + tap];
        v1 = w[(oc * 32 + ic0 + 8) * 25 + tap];
    }
    split2(v0, v1, g_wfl_h[idx], g_wfl_l[idx]);
}

// ret: [mb2][l13][chunk4][kp8][m96]; pairs (k, k+1)
__global__ void wprep_ret_k(const float* __restrict__ w)
{
    int idx = blockIdx.x * 256 + threadIdx.x;
    if (idx >= 79872) return;
    int m  = idx % 96;
    int kp = (idx / 96) & 7;
    int chunk = (idx / 768) & 3;
    int l  = (idx / 3072) % 13;
    int mb = idx / 39936;
    int k  = l * 64 + chunk * 16 + kp * 2;
    float v0 = w[(mb * 96 + m) * 832 + k];
    float v1 = w[(mb * 96 + m) * 832 + k + 1];
    split2(v0, v1, g_wret_h[idx], g_wret_l[idx]);
}

// ---------------------------------------------------------------------------
// Stem: conv 3x3 stride 2 pad 1 -> bf16-split
// ---------------------------------------------------------------------------
__global__ __launch_bounds__(256) void stem_k(const float* __restrict__ x,
                                              const float* __restrict__ w,
                                              const float* __restrict__ bias)
{
    __shared__ __align__(16) float sw[54][8];

    int tid = threadIdx.x;
    int oc0 = blockIdx.y * 8;
    int b   = blockIdx.z;

    for (int i = tid; i < 432; i += 256) {
        int oc = i & 7, tap = i >> 3;
        sw[tap][oc] = w[(oc0 + oc) * 54 + tap];
    }
    __syncthreads();

    int pix = blockIdx.x * 256 + tid;
    int oy = pix >> 7, ox = pix & 127;

    float acc[8];
    #pragma unroll
    for (int j = 0; j < 8; j++) acc[j] = bias[oc0 + j];

    #pragma unroll
    for (int ic = 0; ic < 6; ic++) {
        const float* xb = x + (b * 6 + ic) * 65536;
        float in[9];
        #pragma unroll
        for (int ky = 0; ky < 3; ky++) {
            int iy = 2 * oy - 1 + ky;
            #pragma unroll
            for (int kx = 0; kx < 3; kx++) {
                int ix = 2 * ox - 1 + kx;
                bool ok = (iy >= 0) & (iy <= 255) & (ix >= 0) & (ix <= 255);
                in[ky * 3 + kx] = ok ? __ldg(&xb[iy * 256 + ix]) : 0.f;
            }
        }
        #pragma unroll
        for (int k = 0; k < 9; k++) {
            int tap = ic * 9 + k;
            float a[8];
            *(float4*)&a[0] = *(const float4*)&sw[tap][0];
            *(float4*)&a[4] = *(const float4*)&sw[tap][4];
            #pragma unroll
            for (int j = 0; j < 8; j++) acc[j] += in[k] * a[j];
        }
    }
    #pragma unroll
    for (int j = 0; j < 8; j++) acc[j] = leaky_f(acc[j]);

    int pbase = ((b * 384 + oc0) >> 1) * NPIX + pix;
    #pragma unroll
    for (int j = 0; j < 4; j++) {
        uint32_t h, l;
        split2(acc[2 * j], acc[2 * j + 1], h, l);
        g_ysbf_h[pbase + j * NPIX] = h;
        g_ysbf_l[pbase + j * NPIX] = l;
    }
}

// ---------------------------------------------------------------------------
// i2h: conv3x3 64->192, ALL 6 timesteps batched. grid (64, 3, 12): z=t*2+b.
// ---------------------------------------------------------------------------
#define I2H_SMEM_BYTES ((2 * 5184 + 2 * 4416) * 4)
__global__ __launch_bounds__(256) void i2h_k(const float* __restrict__ bias)
{
    extern __shared__ uint32_t sm_u[];
    uint32_t* s_wh = sm_u;
    uint32_t* s_wl = s_wh + 5184;
    uint32_t* s_xh = s_wl + 5184;
    uint32_t* s_xl = s_xh + 4416;

    int tid = threadIdx.x;
    int lane = tid & 31;
    int g  = lane >> 2;
    int t4 = lane & 3;
    int wid = tid >> 5;
    int wm = wid >> 2;
    int wn = wid & 3;
    int ry = wn >> 1;
    int xoff = (wn & 1) * 64;

    int y0 = blockIdx.x * 2;
    int ocg = blockIdx.y;
    int m0 = ocg * 64;
    int z  = blockIdx.z;
    int b = z & 1, t = z >> 1;
    const uint32_t* inh = g_ysbf_h + (b * 192 + t * 32) * NPIX;
    const uint32_t* inl = g_ysbf_l + (b * 192 + t * 32) * NPIX;

    float acc[2][8][4];
    #pragma unroll
    for (int mt = 0; mt < 2; mt++)
        #pragma unroll
        for (int nt = 0; nt < 8; nt++)
            #pragma unroll
            for (int i = 0; i < 4; i++) acc[mt][nt][i] = 0.f;

    for (int chunk = 0; chunk < 4; chunk++) {
        __syncthreads();
        int wbase = (ocg * 4 + chunk) * 4608;
        for (int i = tid; i < 4608; i += 256) {
            int smi = (i >> 6) * 72 + (i & 63);
            s_wh[smi] = g_wi2h_h[wbase + i];
            s_wl[smi] = g_wi2h_l[wbase + i];
        }
        int pbase = chunk * 8;
        for (int i = tid; i < 4160; i += 256) {
            int col = i % 130, r = i / 130;
            int row = r & 3, kp = r >> 2;
            int gy = y0 - 1 + row, gx = col - 1;
            uint32_t vh = 0, vl = 0;
            if (gy >= 0 && gy < 128 && gx >= 0 && gx < 128) {
                int off = (pbase + kp) * NPIX + gy * 128 + gx;
                vh = inh[off]; vl = inl[off];
            }
            int si = kp * 552 + row * 136 + col;
            s_xh[si] = vh; s_xl[si] = vl;
        }
        __syncthreads();

        #pragma unroll
        for (int ky = 0; ky < 3; ky++) {
            #pragma unroll
            for (int kx = 0; kx < 3; kx++) {
                int tap = ky * 3 + kx;
                uint32_t ah[2][4], al[2][4];
                #pragma unroll
                for (int mt = 0; mt < 2; mt++) {
                    int mm = wm * 32 + mt * 16 + g;
                    int r0 = (tap * 8 + t4) * 72, r1 = (tap * 8 + t4 + 4) * 72;
                    ah[mt][0] = s_wh[r0 + mm];     ah[mt][1] = s_wh[r0 + mm + 8];
                    ah[mt][2] = s_wh[r1 + mm];     ah[mt][3] = s_wh[r1 + mm + 8];
                    al[mt][0] = s_wl[r0 + mm];     al[mt][1] = s_wl[r0 + mm + 8];
                    al[mt][2] = s_wl[r1 + mm];     al[mt][3] = s_wl[r1 + mm + 8];
                }
                int base = (ry + ky) * 136 + xoff + kx;
                #pragma unroll
                for (int nt = 0; nt < 8; nt++) {
                    int cc = base + nt * 8 + g;
                    uint32_t bh0 = s_xh[t4 * 552 + cc];
                    uint32_t bh1 = s_xh[(t4 + 4) * 552 + cc];
                    uint32_t bl0 = s_xl[t4 * 552 + cc];
                    uint32_t bl1 = s_xl[(t4 + 4) * 552 + cc];
                    #pragma unroll
                    for (int mt = 0; mt < 2; mt++) {
                        float* c = acc[mt][nt];
                        MMA_BF16(c[0], c[1], c[2], c[3],
                                 al[mt][0], al[mt][1], al[mt][2], al[mt][3], bh0, bh1);
                        MMA_BF16(c[0], c[1], c[2], c[3],
                                 ah[mt][0], ah[mt][1], ah[mt][2], ah[mt][3], bl0, bl1);
                        MMA_BF16(c[0], c[1], c[2], c[3],
                                 ah[mt][0], ah[mt][1], ah[mt][2], ah[mt][3], bh0, bh1);
                    }
                }
            }
        }
    }

    int pix0 = (y0 + ry) * 128 + xoff;
    float* ob = g_i2h + (size_t)z * 192 * NPIX;
    #pragma unroll
    for (int mt = 0; mt < 2; mt++) {
        int m = m0 + wm * 32 + mt * 16 + g;
        float bb0 = bias[m], bb1 = bias[m + 8];
        float* C0 = &ob[(size_t)m * NPIX];
        float* C1 = &ob[(size_t)(m + 8) * NPIX];
        #pragma unroll
        for (int nt = 0; nt < 8; nt++) {
            int px = pix0 + nt * 8 + t4 * 2;
            *(float2*)&C0[px] = make_float2(acc[mt][nt][0] + bb0, acc[mt][nt][1] + bb0);
            *(float2*)&C1[px] = make_float2(acc[mt][nt][2] + bb1, acc[mt][nt][3] + bb1);
        }
    }
}

// ---------------------------------------------------------------------------
// Shared conv5x5 64->32 core (bf16-split TC).
// ---------------------------------------------------------------------------
#define C5_SMEM_BYTES ((2 * 8000 + 2 * 8768) * 4)

#define CONV5_CORE(INH, INL, WH, WL, WOFF)                                     \
    for (int chunk = 0; chunk < 4; chunk++) {                                  \
        __syncthreads();                                                       \
        int wbase = (WOFF) + chunk * 6400;                                     \
        for (int i = tid; i < 6400; i += 256) {                                \
            int smi = (i >> 5) * 40 + (i & 31);                                \
            s_wh[smi] = WH[wbase + i];                                         \
            s_wl[smi] = WL[wbase + i];                                         \
        }                                                                      \
        int pbase = chunk * 8;                                                 \
        for (int i = tid; i < 8448; i += 256) {                                \
            int col = i % 132, r = i / 132;                                    \
            int row = r & 7, kp = r >> 3;                                      \
            int gy = y0 - 2 + row, gx = col - 2;                               \
            uint32_t vh = 0, vl = 0;                                           \
            if (gy >= 0 && gy < 128 && gx >= 0 && gx < 128) {                  \
                int off = (pbase + kp) * NPIX + gy * 128 + gx;                 \
                vh = INH[off]; vl = INL[off];                                  \
            }                                                                  \
            int si = kp * 1096 + row * 136 + col;                              \
            s_xh[si] = vh; s_xl[si] = vl;                                      \
        }                                                                      \
        __syncthreads();                                                       \
        _Pragma("unroll 1")                                                    \
        for (int ky = 0; ky < 5; ky++) {                                       \
            _Pragma("unroll")                                                  \
            for (int kx = 0; kx < 5; kx++) {                                   \
                int tap = ky * 5 + kx;                                         \
                uint32_t ah[2][4], al[2][4];                                   \
                _Pragma("unroll")                                              \
                for (int mt = 0; mt < 2; mt++) {                               \
                    int mm = mt * 16 + g;                                      \
                    int r0 = (tap * 8 + t4) * 40, r1 = (tap * 8 + t4 + 4) * 40;\
                    ah[mt][0] = s_wh[r0 + mm];     ah[mt][1] = s_wh[r0 + mm + 8];\
                    ah[mt][2] = s_wh[r1 + mm];     ah[mt][3] = s_wh[r1 + mm + 8];\
                    al[mt][0] = s_wl[r0 + mm];     al[mt][1] = s_wl[r0 + mm + 8];\
                    al[mt][2] = s_wl[r1 + mm];     al[mt][3] = s_wl[r1 + mm + 8];\
                }                                                              \
                int base = (rw + ky) * 136 + xoff + kx;                        \
                _Pragma("unroll")                                              \
                for (int nt = 0; nt < 8; nt++) {                               \
                    int cc = base + nt * 8 + g;                                \
                    uint32_t bh0 = s_xh[t4 * 1096 + cc];                       \
                    uint32_t bh1 = s_xh[(t4 + 4) * 1096 + cc];                 \
                    uint32_t bl0 = s_xl[t4 * 1096 + cc];                       \
                    uint32_t bl1 = s_xl[(t4 + 4) * 1096 + cc];                 \
                    _Pragma("unroll")                                          \
                    for (int mt = 0; mt < 2; mt++) {                           \
                        float* c = acc[mt][nt];                                \
                        MMA_BF16(c[0], c[1], c[2], c[3],                       \
                                 al[mt][0], al[mt][1], al[mt][2], al[mt][3], bh0, bh1);\
                        MMA_BF16(c[0], c[1], c[2], c[3],                       \
                                 ah[mt][0], ah[mt][1], ah[mt][2], ah[mt][3], bl0, bl1);\
                        MMA_BF16(c[0], c[1], c[2], c[3],                       \
                                 ah[mt][0], ah[mt][1], ah[mt][2], ah[mt][3], bh0, bh1);\
                    }                                                          \
                }                                                              \
            }                                                                  \
        }                                                                      \
    }

// f1 input half, ALL 6 timesteps. grid (32, 6, 2): y=t. Writes partials.
__global__ __launch_bounds__(256) void f1i_k()
{
    extern __shared__ uint32_t sm_u[];
    uint32_t* s_wh = sm_u;
    uint32_t* s_wl = s_wh + 8000;
    uint32_t* s_xh = s_wl + 8000;
    uint32_t* s_xl = s_xh + 8768;

    int tid = threadIdx.x;
    int lane = tid & 31;
    int g  = lane >> 2;
    int t4 = lane & 3;
    int wid = tid >> 5;
    int rw = wid >> 1;
    int xoff = (wid & 1) * 64;

    int y0 = blockIdx.x * 4;
    int t  = blockIdx.y;
    int b  = blockIdx.z;
    const uint32_t* inh = g_ysbf_h + (b * 192 + t * 32) * NPIX;
    const uint32_t* inl = g_ysbf_l + (b * 192 + t * 32) * NPIX;

    float acc[2][8][4];
    #pragma unroll
    for (int mt = 0; mt < 2; mt++)
        #pragma unroll
        for (int nt = 0; nt < 8; nt++)
            #pragma unroll
            for (int i = 0; i < 4; i++) acc[mt][nt][i] = 0.f;

    CONV5_CORE(inh, inl, g_wf1_h, g_wf1_l, 0)

    float* op = g_f1p0 + (size_t)(t * 2 + b) * 32 * NPIX;
    int pix0 = (y0 + rw) * 128 + xoff;
    #pragma unroll
    for (int mt = 0; mt < 2; mt++) {
        int m = mt * 16 + g;
        float* C0 = &op[(size_t)m * NPIX];
        float* C1 = &op[(size_t)(m + 8) * NPIX];
        #pragma unroll
        for (int nt = 0; nt < 8; nt++) {
            int px = pix0 + nt * 8 + t4 * 2;
            *(float2*)&C0[px] = make_float2(acc[mt][nt][0], acc[mt][nt][1]);
            *(float2*)&C1[px] = make_float2(acc[mt][nt][2], acc[mt][nt][3]);
        }
    }
}

// f1 hidden half + fused combine (t>=1). grid (32, 1, 2).
__global__ __launch_bounds__(256) void f1h_k(int t, const float* __restrict__ bi,
                                             const float* __restrict__ bh)
{
    extern __shared__ uint32_t sm_u[];
    uint32_t* s_wh = sm_u;
    uint32_t* s_wl = s_wh + 8000;
    uint32_t* s_xh = s_wl + 8000;
    uint32_t* s_xl = s_xh + 8768;

    int tid = threadIdx.x;
    int lane = tid & 31;
    int g  = lane >> 2;
    int t4 = lane & 3;
    int wid = tid >> 5;
    int rw = wid >> 1;
    int xoff = (wid & 1) * 64;

    int y0 = blockIdx.x * 4;
    int b  = blockIdx.z;
    const uint32_t* inh = g_hbf_h + b * 32 * NPIX;
    const uint32_t* inl = g_hbf_l + b * 32 * NPIX;

    float acc[2][8][4];
    #pragma unroll
    for (int mt = 0; mt < 2; mt++)
        #pragma unroll
        for (int nt = 0; nt < 8; nt++)
            #pragma unroll
            for (int i = 0; i < 4; i++) acc[mt][nt][i] = 0.f;

    CONV5_CORE(inh, inl, g_wf1_h, g_wf1_l, 25600)

    const float* pp = g_f1p0 + (size_t)(t * 2 + b) * 32 * NPIX;
    int pix0 = (y0 + rw) * 128 + xoff;
    #pragma unroll
    for (int mt = 0; mt < 2; mt++) {
        int m = mt * 16 + g;
        float b0 = bi[m] + bh[m];
        float b8 = bi[m + 8] + bh[m + 8];
        uint32_t* Oh = &g_f1bf_h[(b * 16 + mt * 8 + g) * NPIX];
        uint32_t* Ol = &g_f1bf_l[(b * 16 + mt * 8 + g) * NPIX];
        #pragma unroll
        for (int nt = 0; nt < 8; nt++) {
            int px = pix0 + nt * 8 + t4 * 2;
            float2 p0 = *(const float2*)&pp[(size_t)m * NPIX + px];
            float2 p8 = *(const float2*)&pp[(size_t)(m + 8) * NPIX + px];
            float v0 = leaky_f(acc[mt][nt][0] + p0.x + b0);
            float v1 = leaky_f(acc[mt][nt][1] + p0.y + b0);
            float v8 = leaky_f(acc[mt][nt][2] + p8.x + b8);
            float v9 = leaky_f(acc[mt][nt][3] + p8.y + b8);
            uint32_t h0, l0, h1, l1;
            split2(v0, v8, h0, l0);
            split2(v1, v9, h1, l1);
            *(uint2*)&Oh[px] = make_uint2(h0, h1);
            *(uint2*)&Ol[px] = make_uint2(l0, l1);
        }
    }
}

// t=0 combine: f1 = leaky(input partial + biases) -> g_f1bf (c, c+8) pairs.
__global__ void f1c0_k(const float* __restrict__ bi, const float* __restrict__ bh)
{
    int idx = blockIdx.x * 256 + threadIdx.x;
    int pix = idx & (NPIX - 1);
    int j   = (idx >> 14) & 15;
    int b   = idx >> 18;
    int c0  = (j >> 3) * 16 + (j & 7);
    int c1  = c0 + 8;
    const float* pp = g_f1p0 + (size_t)b * 32 * NPIX;    // t = 0
    float v0 = leaky_f(pp[(size_t)c0 * NPIX + pix] + bi[c0] + bh[c0]);
    float v1 = leaky_f(pp[(size_t)c1 * NPIX + pix] + bi[c1] + bh[c1]);
    uint32_t h, l;
    split2(v0, v1, h, l);
    g_f1bf_h[idx] = h; g_f1bf_l[idx] = l;
}

// ---------------------------------------------------------------------------
// flow: conv5x5 32 -> 26 (padded 32), bf16-split TC, writes g_fl + bias.
// ---------------------------------------------------------------------------
__global__ __launch_bounds__(256) void flow_k(const float* __restrict__ bias)
{
    extern __shared__ uint32_t sm_u[];
    uint32_t* s_wh = sm_u;
    uint32_t* s_wl = s_wh + 8000;
    uint32_t* s_xh = s_wl + 8000;
    uint32_t* s_xl = s_xh + 8768;

    int tid = threadIdx.x;
    int lane = tid & 31;
    int g  = lane >> 2;
    int t4 = lane & 3;
    int wid = tid >> 5;
    int rw = wid >> 1;
    int xoff = (wid & 1) * 64;

    int y0 = blockIdx.x * 4;
    int b  = blockIdx.z;
    const uint32_t* inh = g_f1bf_h + b * 16 * NPIX;
    const uint32_t* inl = g_f1bf_l + b * 16 * NPIX;

    float acc[2][8][4];
    #pragma unroll
    for (int mt = 0; mt < 2; mt++)
        #pragma unroll
        for (int nt = 0; nt < 8; nt++)
            #pragma unroll
            for (int i = 0; i < 4; i++) acc[mt][nt][i] = 0.f;

    for (int chunk = 0; chunk < 2; chunk++) {
        __syncthreads();
        int wbase = chunk * 6400;
        for (int i = tid; i < 6400; i += 256) {
            int smi = (i >> 5) * 40 + (i & 31);
            s_wh[smi] = g_wfl_h[wbase + i];
            s_wl[smi] = g_wfl_l[wbase + i];
        }
        int pbase = chunk * 8;
        for (int i = tid; i < 8448; i += 256) {
            int col = i % 132, r = i / 132;
            int row = r & 7, kp = r >> 3;
            int gy = y0 - 2 + row, gx = col - 2;
            uint32_t vh = 0, vl = 0;
            if (gy >= 0 && gy < 128 && gx >= 0 && gx < 128) {
                int off = (pbase + kp) * NPIX + gy * 128 + gx;
                vh = inh[off]; vl = inl[off];
            }
            int si = kp * 1096 + row * 136 + col;
            s_xh[si] = vh; s_xl[si] = vl;
        }
        __syncthreads();

        #pragma unroll 1
        for (int ky = 0; ky < 5; ky++) {
            #pragma unroll
            for (int kx = 0; kx < 5; kx++) {
                int tap = ky * 5 + kx;
                uint32_t ah[2][4], al[2][4];
                #pragma unroll
                for (int mt = 0; mt < 2; mt++) {
                    int mm = mt * 16 + g;
                    int r0 = (tap * 8 + t4) * 40, r1 = (tap * 8 + t4 + 4) * 40;
                    ah[mt][0] = s_wh[r0 + mm];     ah[mt][1] = s_wh[r0 + mm + 8];
                    ah[mt][2] = s_wh[r1 + mm];     ah[mt][3] = s_wh[r1 + mm + 8];
                    al[mt][0] = s_wl[r0 + mm];     al[mt][1] = s_wl[r0 + mm + 8];
                    al[mt][2] = s_wl[r1 + mm];     al[mt][3] = s_wl[r1 + mm + 8];
                }
                int base = (rw + ky) * 136 + xoff + kx;
                #pragma unroll
                for (int nt = 0; nt < 8; nt++) {
                    int cc = base + nt * 8 + g;
                    uint32_t bh0 = s_xh[t4 * 1096 + cc];
                    uint32_t bh1 = s_xh[(t4 + 4) * 1096 + cc];
                    uint32_t bl0 = s_xl[t4 * 1096 + cc];
                    uint32_t bl1 = s_xl[(t4 + 4) * 1096 + cc];
                    #pragma unroll
                    for (int mt = 0; mt < 2; mt++) {
                        float* c = acc[mt][nt];
                        MMA_BF16(c[0], c[1], c[2], c[3],
                                 al[mt][0], al[mt][1], al[mt][2], al[mt][3], bh0, bh1);
                        MMA_BF16(c[0], c[1], c[2], c[3],
                                 ah[mt][0], ah[mt][1], ah[mt][2], ah[mt][3], bl0, bl1);
                        MMA_BF16(c[0], c[1], c[2], c[3],
                                 ah[mt][0], ah[mt][1], ah[mt][2], ah[mt][3], bh0, bh1);
                    }
                }
            }
        }
    }

    int pix0 = (y0 + rw) * 128 + xoff;
    #pragma unroll
    for (int mt = 0; mt < 2; mt++) {
        int m = mt * 16 + g;
        #pragma unroll
        for (int nt = 0; nt < 8; nt++) {
            int px = pix0 + nt * 8 + t4 * 2;
            if (m < 26) {
                float bb = bias[m];
                *(float2*)&g_fl[(b * 26 + m) * NPIX + px] =
                    make_float2(acc[mt][nt][0] + bb, acc[mt][nt][1] + bb);
            }
            if (m + 8 < 26) {
                float bb = bias[m + 8];
                *(float2*)&g_fl[(b * 26 + m + 8) * NPIX + px] =
                    make_float2(acc[mt][nt][2] + bb, acc[mt][nt][3] + bb);
            }
        }
    }
}

// ---------------------------------------------------------------------------
// wretg: fused warp + ret + GRU (t>=1). BM=192, grid (128, 1, 2).
// All 192 output channels of a 128-px column live in one block, so the GRU
// runs in the epilogue from an smem C-tile; out[b,t] + bf16-split h written
// directly. g_h2h round-trip eliminated; gather done once (was twice).
// ---------------------------------------------------------------------------
#define WRET_SC_BYTES (192 * 132 * 4)
__global__ __launch_bounds__(256, 1) void wretg_k(int t, const float* __restrict__ bias,
                                                  const float* __restrict__ bi2h_unused,
                                                  float* __restrict__ outp)
{
    __shared__ int      s_ci[4][128];
    __shared__ float    s_cw[4][128];
    __shared__ uint32_t s_wh[8 * 200], s_wl[8 * 200];
    __shared__ uint32_t s_bh[8 * 136], s_bl[8 * 136];
    extern __shared__ float s_c[];          // [192][132]

    int tid = threadIdx.x;
    int lane = tid & 31;
    int g  = lane >> 2;
    int t4 = lane & 3;
    int wid = tid >> 5;
    int wm = wid >> 2;                       // 0..1 -> 96-row half
    int wn = wid & 3;
    int mb = wm * 96;
    int nb = wn * 32;

    int b  = blockIdx.z;
    int n0 = blockIdx.x * 128;

    float acc[6][4][4];
    #pragma unroll
    for (int mt = 0; mt < 6; mt++)
        #pragma unroll
        for (int nt = 0; nt < 4; nt++)
            #pragma unroll
            for (int i = 0; i < 4; i++) acc[mt][nt][i] = 0.f;

    const float* hprev = outp + ((b * 6 + (t - 1)) * 64) * NPIX;

    for (int l = 0; l < 13; l++) {
        __syncthreads();
        if (tid < 128) {
            int pg = n0 + tid;
            float u = g_fl[(b * 26 + 2 * l    ) * NPIX + pg];
            float v = g_fl[(b * 26 + 2 * l + 1) * NPIX + pg];
            float sx = (float)(pg & 127) - u;
            float sy = (float)(pg >> 7)  - v;
            float fx = floorf(sx), fy = floorf(sy);
            float wx1 = sx - fx, wx0 = 1.f - wx1;
            float wy1 = sy - fy, wy0 = 1.f - wy1;
            int x0 = (int)fx, y0 = (int)fy;
            int x1 = x0 + 1,  y1 = y0 + 1;
            bool vx0 = (x0 >= 0) & (x0 <= 127);
            bool vx1 = (x1 >= 0) & (x1 <= 127);
            bool vy0 = (y0 >= 0) & (y0 <= 127);
            bool vy1 = (y1 >= 0) & (y1 <= 127);
            int cx0 = min(max(x0, 0), 127), cx1 = min(max(x1, 0), 127);
            int cy0 = min(max(y0, 0), 127), cy1 = min(max(y1, 0), 127);
            s_ci[0][tid] = cy0 * 128 + cx0;
            s_ci[1][tid] = cy0 * 128 + cx1;
            s_ci[2][tid] = cy1 * 128 + cx0;
            s_ci[3][tid] = cy1 * 128 + cx1;
            s_cw[0][tid] = (vx0 && vy0) ? wx0 * wy0 : 0.f;
            s_cw[1][tid] = (vx1 && vy0) ? wx1 * wy0 : 0.f;
            s_cw[2][tid] = (vx0 && vy1) ? wx0 * wy1 : 0.f;
            s_cw[3][tid] = (vx1 && vy1) ? wx1 * wy1 : 0.f;
        }

        for (int chunk = 0; chunk < 4; chunk++) {
            __syncthreads();
            // A chunk: 8 kp x 192 m (both wprep m-halves)
            #pragma unroll
            for (int r = 0; r < 6; r++) {
                int i = tid + r * 256;          // 1536 loads
                int kp = i / 192, m = i % 192;
                int mh = m / 96, ml = m % 96;
                int src = mh * 39936 + (l * 4 + chunk) * 768 + kp * 96 + ml;
                int smi = kp * 200 + m;
                s_wh[smi] = g_wret_h[src];
                s_wl[smi] = g_wret_l[src];
            }
            // B chunk: gather + split, 8 kp x 128 px (once per block now)
            #pragma unroll
            for (int r = 0; r < 4; r++) {
                int j = tid + r * 256;
                int kp = j >> 7, px = j & 127;
                int i00 = s_ci[0][px], i10 = s_ci[1][px];
                int i01 = s_ci[2][px], i11 = s_ci[3][px];
                float w00 = s_cw[0][px], w10 = s_cw[1][px];
                float w01 = s_cw[2][px], w11 = s_cw[3][px];
                const float* h0 = hprev + (chunk * 16 + kp * 2) * NPIX;
                const float* h1 = h0 + NPIX;
                float v0 = w00 * __ldg(&h0[i00]) + w10 * __ldg(&h0[i10])
                         + w01 * __ldg(&h0[i01]) + w11 * __ldg(&h0[i11]);
                float v1 = w00 * __ldg(&h1[i00]) + w10 * __ldg(&h1[i10])
                         + w01 * __ldg(&h1[i01]) + w11 * __ldg(&h1[i11]);
                uint32_t hh, ll;
                split2(v0, v1, hh, ll);
                s_bh[kp * 136 + px] = hh;
                s_bl[kp * 136 + px] = ll;
            }
            __syncthreads();

            uint32_t bh[4][2], bl[4][2];
            #pragma unroll
            for (int nt = 0; nt < 4; nt++) {
                int nn = nb + nt * 8 + g;
                bh[nt][0] = s_bh[t4 * 136 + nn];
                bh[nt][1] = s_bh[(t4 + 4) * 136 + nn];
                bl[nt][0] = s_bl[t4 * 136 + nn];
                bl[nt][1] = s_bl[(t4 + 4) * 136 + nn];
            }
            #pragma unroll
            for (int mt = 0; mt < 6; mt++) {
                int mm = mb + mt * 16 + g;
                int r0 = t4 * 200, r1 = (t4 + 4) * 200;
                uint32_t a0h = s_wh[r0 + mm],     a1h = s_wh[r0 + mm + 8];
                uint32_t a2h = s_wh[r1 + mm],     a3h = s_wh[r1 + mm + 8];
                uint32_t a0l = s_wl[r0 + mm],     a1l = s_wl[r0 + mm + 8];
                uint32_t a2l = s_wl[r1 + mm],     a3l = s_wl[r1 + mm + 8];
                #pragma unroll
                for (int nt = 0; nt < 4; nt++) {
                    float* c = acc[mt][nt];
                    MMA_BF16(c[0], c[1], c[2], c[3],
                             a0l, a1l, a2l, a3l, bh[nt][0], bh[nt][1]);
                    MMA_BF16(c[0], c[1], c[2], c[3],
                             a0h, a1h, a2h, a3h, bl[nt][0], bl[nt][1]);
                    MMA_BF16(c[0], c[1], c[2], c[3],
                             a0h, a1h, a2h, a3h, bh[nt][0], bh[nt][1]);
                }
            }
        }
    }

    // ---- stage C + bias into smem ----
    __syncthreads();
    #pragma unroll
    for (int mt = 0; mt < 6; mt++) {
        int m = mb + mt * 16 + g;
        float bb0 = bias[m], bb1 = bias[m + 8];
        #pragma unroll
        for (int nt = 0; nt < 4; nt++) {
            int col = nb + nt * 8 + t4 * 2;
            s_c[m * 132 + col]           = acc[mt][nt][0] + bb0;
            s_c[m * 132 + col + 1]       = acc[mt][nt][1] + bb0;
            s_c[(m + 8) * 132 + col]     = acc[mt][nt][2] + bb1;
            s_c[(m + 8) * 132 + col + 1] = acc[mt][nt][3] + bb1;
        }
    }
    __syncthreads();

    // ---- fused GRU: 32 channel-pairs x 128 px = 4096 items, 16/thread ----
    size_t ibase = (size_t)(t * 2 + b) * 192 * NPIX;
    const float* hp_prev = outp + ((b * 6 + t - 1) * 64) * NPIX;
    float* hout = outp + ((b * 6 + t) * 64) * NPIX;
    #pragma unroll 1
    for (int r = 0; r < 16; r++) {
        int item = r * 256 + tid;
        int c2 = item >> 7, px = item & 127;
        int pg = n0 + px;
        int c = 2 * c2;
        float h01[2];
        #pragma unroll
        for (int j = 0; j < 2; j++) {
            int cj = c + j;
            float ir = g_i2h[ibase + (size_t)(cj      ) * NPIX + pg];
            float iu = g_i2h[ibase + (size_t)(cj +  64) * NPIX + pg];
            float im = g_i2h[ibase + (size_t)(cj + 128) * NPIX + pg];
            float hr = s_c[(cj      ) * 132 + px];
            float hu = s_c[(cj +  64) * 132 + px];
            float hm = s_c[(cj + 128) * 132 + px];
            float rg = 1.f / (1.f + expf(-(ir + hr)));
            float z  = 1.f / (1.f + expf(-(iu + hu)));
            float mm = leaky_f(im + rg * hm);
            float hp = hp_prev[(size_t)cj * NPIX + pg];
            float h  = z * hp + (1.f - z) * mm;
            hout[(size_t)cj * NPIX + pg] = h;
            h01[j] = h;
        }
        uint32_t hw, lw;
        split2(h01[0], h01[1], hw, lw);
        int p = (b * 32 + c2) * NPIX + pg;
        g_hbf_h[p] = hw; g_hbf_l[p] = lw;
    }
}

// ---------------------------------------------------------------------------
// GRU for t=0 only: h2h = b_ret broadcast, hprev = 0.
// grid (64, 32, 2), block 256.
// ---------------------------------------------------------------------------
__global__ void gru0_k(const float* __restrict__ bret, float* __restrict__ outp)
{
    int pix = blockIdx.x * 256 + threadIdx.x;
    int c2  = blockIdx.y;
    int b   = blockIdx.z;
    int c   = 2 * c2;
    size_t ibase = (size_t)b * 192 * NPIX;    // t = 0

    float h01[2];
    #pragma unroll
    for (int j = 0; j < 2; j++) {
        int cj = c + j;
        float ir = g_i2h[ibase + (size_t)(cj      ) * NPIX + pix];
        float iu = g_i2h[ibase + (size_t)(cj +  64) * NPIX + pix];
        float im = g_i2h[ibase + (size_t)(cj + 128) * NPIX + pix];
        float hr = bret[cj], hu = bret[cj + 64], hm = bret[cj + 128];

        float r = 1.f / (1.f + expf(-(ir + hr)));
        float z = 1.f / (1.f + expf(-(iu + hu)));
        float m = leaky_f(im + r * hm);

        float h = (1.f - z) * m;
        outp[((b * 6) * 64 + cj) * NPIX + pix] = h;
        h01[j] = h;
    }
    uint32_t hw, lw;
    split2(h01[0], h01[1], hw, lw);
    int p = (b * 32 + c2) * NPIX + pix;
    g_hbf_h[p] = hw; g_hbf_l[p] = lw;
}

// ---------------------------------------------------------------------------
// Launch
// ---------------------------------------------------------------------------
extern "C" void kernel_launch(void* const* d_in, const int* in_sizes, int n_in,
                              void* d_out, int out_size)
{
    const float* x      = (const float*)d_in[0];
    const float* w_stem = (const float*)d_in[1];
    const float* b_stem = (const float*)d_in[2];
    const float* w_i2h  = (const float*)d_in[3];
    const float* b_i2h  = (const float*)d_in[4];
    const float* w_i2f  = (const float*)d_in[5];
    const float* b_i2f  = (const float*)d_in[6];
    const float* w_h2f  = (const float*)d_in[7];
    const float* b_h2f  = (const float*)d_in[8];
    const float* w_flow = (const float*)d_in[9];
    const float* b_flow = (const float*)d_in[10];
    const float* w_ret  = (const float*)d_in[11];
    const float* b_ret  = (const float*)d_in[12];
    float* outp = (float*)d_out;

    cudaFuncSetAttribute(i2h_k,   cudaFuncAttributeMaxDynamicSharedMemorySize, I2H_SMEM_BYTES);
    cudaFuncSetAttribute(f1i_k,   cudaFuncAttributeMaxDynamicSharedMemorySize, C5_SMEM_BYTES);
    cudaFuncSetAttribute(f1h_k,   cudaFuncAttributeMaxDynamicSharedMemorySize, C5_SMEM_BYTES);
    cudaFuncSetAttribute(flow_k,  cudaFuncAttributeMaxDynamicSharedMemorySize, C5_SMEM_BYTES);
    cudaFuncSetAttribute(wretg_k, cudaFuncAttributeMaxDynamicSharedMemorySize, WRET_SC_BYTES);

    wprep_i2h_k<<<(55296 + 255) / 256, 256>>>(w_i2h);
    wprep_f1_k <<<(51200 + 255) / 256, 256>>>(w_i2f, w_h2f);
    wprep_fl_k <<<(12800 + 255) / 256, 256>>>(w_flow);
    wprep_ret_k<<<(79872 + 255) / 256, 256>>>(w_ret);

    stem_k<<<dim3(64, 48, 2), 256>>>(x, w_stem, b_stem);

    // t-independent work: all 6 timesteps batched
    i2h_k<<<dim3(64, 3, 12), 256, I2H_SMEM_BYTES>>>(b_i2h);
    f1i_k<<<dim3(32, 6, 2),  256, C5_SMEM_BYTES>>>();

    for (int t = 0; t < 6; t++) {
        if (t == 0) {
            f1c0_k<<<(2 * 16 * NPIX) / 256, 256>>>(b_i2f, b_h2f);
            flow_k<<<dim3(32, 1, 2), 256, C5_SMEM_BYTES>>>(b_flow);
            gru0_k<<<dim3(64, 32, 2), 256>>>(b_ret, outp);
        } else {
            f1h_k <<<dim3(32, 1, 2), 256, C5_SMEM_BYTES>>>(t, b_i2f, b_h2f);
            flow_k<<<dim3(32, 1, 2), 256, C5_SMEM_BYTES>>>(b_flow);
            wretg_k<<<dim3(128, 1, 2), 256, WRET_SC_BYTES>>>(t, b_ret, nullptr, outp);
        }
    }
}

// round 12
// speedup vs baseline: 1.0476x; 1.0476x over previous
#include <cuda_runtime.h>
#include <cuda_bf16.h>
#include <math.h>
#include <stdint.h>

#define NPIX 16384            // 128*128

// ---------------------------------------------------------------------------
// Scratch (static device globals)
// ---------------------------------------------------------------------------
__device__ float g_i2h[2 * 192 * NPIX];     // i2h conv out (per step)   25 MB
__device__ float g_h2h[2 * 192 * NPIX];     // ret conv out              25 MB
__device__ float g_f1p[2][2 * 32 * NPIX];   // f1 partial sums (2 src)  8.4 MB
__device__ float g_fl [2 *  26 * NPIX];     // flows                    3.4 MB

// bf16-split packed operands (channel pairs per 32-bit word)
__device__ uint32_t g_ysbf_h[2 * 192 * NPIX], g_ysbf_l[2 * 192 * NPIX]; // stem out (c,c+1)
__device__ uint32_t g_hbf_h [2 *  32 * NPIX], g_hbf_l [2 *  32 * NPIX]; // hprev (c,c+1)

// pre-converted weights: layouts match smem consumption order
__device__ uint32_t g_wi2h_h[3 * 4 * 9 * 8 * 64],  g_wi2h_l[3 * 4 * 9 * 8 * 64];
__device__ uint32_t g_wf1_h [2 * 4 * 25 * 8 * 32], g_wf1_l [2 * 4 * 25 * 8 * 32];
__device__ uint32_t g_wfl_h [2 * 25 * 8 * 32],     g_wfl_l [2 * 25 * 8 * 32];
__device__ uint32_t g_wret_h[2 * 13 * 4 * 8 * 96], g_wret_l[2 * 13 * 4 * 8 * 96];

__device__ __forceinline__ float leaky_f(float x) { return x >= 0.f ? x : 0.2f * x; }

// split two floats into packed bf16 hi-pair and lo-pair (v = hi + lo)
__device__ __forceinline__ void split2(float v0, float v1, uint32_t& h, uint32_t& l) {
    __nv_bfloat162 hb = __floats2bfloat162_rn(v0, v1);
    float h0 = __low2float(hb), h1 = __high2float(hb);
    __nv_bfloat162 lb = __floats2bfloat162_rn(v0 - h0, v1 - h1);
    h = *reinterpret_cast<uint32_t*>(&hb);
    l = *reinterpret_cast<uint32_t*>(&lb);
}

#define MMA_BF16(c0,c1,c2,c3, a0,a1,a2,a3, b0,b1)                              \
    asm volatile("mma.sync.aligned.m16n8k16.row.col.f32.bf16.bf16.f32 "        \
        "{%0,%1,%2,%3}, {%4,%5,%6,%7}, {%8,%9}, {%0,%1,%2,%3};"                \
        : "+f"(c0), "+f"(c1), "+f"(c2), "+f"(c3)                               \
        : "r"(a0), "r"(a1), "r"(a2), "r"(a3), "r"(b0), "r"(b1))

// ---------------------------------------------------------------------------
// Weight prep — all four conversions in ONE kernel (run once per launch)
// ---------------------------------------------------------------------------
__global__ void wprep_all_k(const float* __restrict__ wi2h,
                            const float* __restrict__ wi2f,
                            const float* __restrict__ wh2f,
                            const float* __restrict__ wfl,
                            const float* __restrict__ wret)
{
    int idx = blockIdx.x * 256 + threadIdx.x;

    if (idx < 55296) {
        // i2h: [ocg3][chunk4][tap9][kp8][oc64]; pairs (ic, ic+1)
        int oc = idx & 63;
        int kp = (idx >> 6) & 7;
        int q  = idx >> 9;
        int tap = q % 9;
        int qc  = q / 9;
        int chunk = qc & 3, ocg = qc >> 2;
        int ic = chunk * 16 + 2 * kp;
        int o  = ocg * 64 + oc;
        float v0 = wi2h[(o * 64 + ic    ) * 9 + tap];
        float v1 = wi2h[(o * 64 + ic + 1) * 9 + tap];
        split2(v0, v1, g_wi2h_h[idx], g_wi2h_l[idx]);
        return;
    }
    idx -= 55296;
    if (idx < 51200) {
        // f1: [src2][chunk4][tap25][kp8][oc32]; pairs (ic, ic+1)
        int oc = idx & 31;
        int kp = (idx >> 5) & 7;
        int q  = idx >> 8;
        int tap = q % 25;
        int qc  = q / 25;
        int chunk = qc & 3, src = qc >> 2;
        int ic = chunk * 16 + 2 * kp;
        const float* w = src ? wh2f : wi2f;
        float v0 = w[(oc * 64 + ic    ) * 25 + tap];
        float v1 = w[(oc * 64 + ic + 1) * 25 + tap];
        split2(v0, v1, g_wf1_h[idx], g_wf1_l[idx]);
        return;
    }
    idx -= 51200;
    if (idx < 12800) {
        // flow: [chunk2][tap25][kp8][oc32] (oc >= 26 zero); pairs (ic, ic+1)
        int oc = idx & 31;
        int kp = (idx >> 5) & 7;
        int q  = idx >> 8;
        int tap = q % 25;
        int chunk = q / 25;
        int ic = chunk * 16 + 2 * kp;
        float v0 = 0.f, v1 = 0.f;
        if (oc < 26) {
            v0 = wfl[(oc * 32 + ic    ) * 25 + tap];
            v1 = wfl[(oc * 32 + ic + 1) * 25 + tap];
        }
        split2(v0, v1, g_wfl_h[idx], g_wfl_l[idx]);
        return;
    }
    idx -= 12800;
    if (idx < 79872) {
        // ret: [mb2][l13][chunk4][kp8][m96]; pairs (k, k+1)
        int m  = idx % 96;
        int kp = (idx / 96) & 7;
        int chunk = (idx / 768) & 3;
        int l  = (idx / 3072) % 13;
        int mb = idx / 39936;
        int k  = l * 64 + chunk * 16 + kp * 2;
        float v0 = wret[(mb * 96 + m) * 832 + k];
        float v1 = wret[(mb * 96 + m) * 832 + k + 1];
        split2(v0, v1, g_wret_h[idx], g_wret_l[idx]);
    }
}

// ---------------------------------------------------------------------------
// Stem: conv 3x3 stride 2 pad 1 -> bf16-split
// ---------------------------------------------------------------------------
__global__ __launch_bounds__(256) void stem_k(const float* __restrict__ x,
                                              const float* __restrict__ w,
                                              const float* __restrict__ bias)
{
    __shared__ __align__(16) float sw[54][8];

    int tid = threadIdx.x;
    int oc0 = blockIdx.y * 8;
    int b   = blockIdx.z;

    for (int i = tid; i < 432; i += 256) {
        int oc = i & 7, tap = i >> 3;
        sw[tap][oc] = w[(oc0 + oc) * 54 + tap];
    }
    __syncthreads();

    int pix = blockIdx.x * 256 + tid;
    int oy = pix >> 7, ox = pix & 127;

    float acc[8];
    #pragma unroll
    for (int j = 0; j < 8; j++) acc[j] = bias[oc0 + j];

    #pragma unroll
    for (int ic = 0; ic < 6; ic++) {
        const float* xb = x + (b * 6 + ic) * 65536;
        float in[9];
        #pragma unroll
        for (int ky = 0; ky < 3; ky++) {
            int iy = 2 * oy - 1 + ky;
            #pragma unroll
            for (int kx = 0; kx < 3; kx++) {
                int ix = 2 * ox - 1 + kx;
                bool ok = (iy >= 0) & (iy <= 255) & (ix >= 0) & (ix <= 255);
                in[ky * 3 + kx] = ok ? __ldg(&xb[iy * 256 + ix]) : 0.f;
            }
        }
        #pragma unroll
        for (int k = 0; k < 9; k++) {
            int tap = ic * 9 + k;
            float a[8];
            *(float4*)&a[0] = *(const float4*)&sw[tap][0];
            *(float4*)&a[4] = *(const float4*)&sw[tap][4];
            #pragma unroll
            for (int j = 0; j < 8; j++) acc[j] += in[k] * a[j];
        }
    }
    #pragma unroll
    for (int j = 0; j < 8; j++) acc[j] = leaky_f(acc[j]);

    int pbase = ((b * 384 + oc0) >> 1) * NPIX + pix;
    #pragma unroll
    for (int j = 0; j < 4; j++) {
        uint32_t h, l;
        split2(acc[2 * j], acc[2 * j + 1], h, l);
        g_ysbf_h[pbase + j * NPIX] = h;
        g_ysbf_l[pbase + j * NPIX] = l;
    }
}

// ---------------------------------------------------------------------------
// i2h: conv3x3 64->192, per step. grid (64, 3, 2).
// ---------------------------------------------------------------------------
#define I2H_SMEM_BYTES ((2 * 5184 + 2 * 4416) * 4)
__global__ __launch_bounds__(256) void i2h_k(int t, const float* __restrict__ bias)
{
    extern __shared__ uint32_t sm_u[];
    uint32_t* s_wh = sm_u;
    uint32_t* s_wl = s_wh + 5184;
    uint32_t* s_xh = s_wl + 5184;
    uint32_t* s_xl = s_xh + 4416;

    int tid = threadIdx.x;
    int lane = tid & 31;
    int g  = lane >> 2;
    int t4 = lane & 3;
    int wid = tid >> 5;
    int wm = wid >> 2;
    int wn = wid & 3;
    int ry = wn >> 1;
    int xoff = (wn & 1) * 64;

    int y0 = blockIdx.x * 2;
    int ocg = blockIdx.y;
    int m0 = ocg * 64;
    int b  = blockIdx.z;
    const uint32_t* inh = g_ysbf_h + (b * 192 + t * 32) * NPIX;
    const uint32_t* inl = g_ysbf_l + (b * 192 + t * 32) * NPIX;

    float acc[2][8][4];
    #pragma unroll
    for (int mt = 0; mt < 2; mt++)
        #pragma unroll
        for (int nt = 0; nt < 8; nt++)
            #pragma unroll
            for (int i = 0; i < 4; i++) acc[mt][nt][i] = 0.f;

    for (int chunk = 0; chunk < 4; chunk++) {
        __syncthreads();
        int wbase = (ocg * 4 + chunk) * 4608;
        for (int i = tid; i < 4608; i += 256) {
            int smi = (i >> 6) * 72 + (i & 63);
            s_wh[smi] = g_wi2h_h[wbase + i];
            s_wl[smi] = g_wi2h_l[wbase + i];
        }
        int pbase = chunk * 8;
        for (int i = tid; i < 4160; i += 256) {
            int col = i % 130, r = i / 130;
            int row = r & 3, kp = r >> 2;
            int gy = y0 - 1 + row, gx = col - 1;
            uint32_t vh = 0, vl = 0;
            if (gy >= 0 && gy < 128 && gx >= 0 && gx < 128) {
                int off = (pbase + kp) * NPIX + gy * 128 + gx;
                vh = inh[off]; vl = inl[off];
            }
            int si = kp * 552 + row * 136 + col;
            s_xh[si] = vh; s_xl[si] = vl;
        }
        __syncthreads();

        #pragma unroll
        for (int ky = 0; ky < 3; ky++) {
            #pragma unroll
            for (int kx = 0; kx < 3; kx++) {
                int tap = ky * 3 + kx;
                uint32_t ah[2][4], al[2][4];
                #pragma unroll
                for (int mt = 0; mt < 2; mt++) {
                    int mm = wm * 32 + mt * 16 + g;
                    int r0 = (tap * 8 + t4) * 72, r1 = (tap * 8 + t4 + 4) * 72;
                    ah[mt][0] = s_wh[r0 + mm];     ah[mt][1] = s_wh[r0 + mm + 8];
                    ah[mt][2] = s_wh[r1 + mm];     ah[mt][3] = s_wh[r1 + mm + 8];
                    al[mt][0] = s_wl[r0 + mm];     al[mt][1] = s_wl[r0 + mm + 8];
                    al[mt][2] = s_wl[r1 + mm];     al[mt][3] = s_wl[r1 + mm + 8];
                }
                int base = (ry + ky) * 136 + xoff + kx;
                #pragma unroll
                for (int nt = 0; nt < 8; nt++) {
                    int cc = base + nt * 8 + g;
                    uint32_t bh0 = s_xh[t4 * 552 + cc];
                    uint32_t bh1 = s_xh[(t4 + 4) * 552 + cc];
                    uint32_t bl0 = s_xl[t4 * 552 + cc];
                    uint32_t bl1 = s_xl[(t4 + 4) * 552 + cc];
                    #pragma unroll
                    for (int mt = 0; mt < 2; mt++) {
                        float* c = acc[mt][nt];
                        MMA_BF16(c[0], c[1], c[2], c[3],
                                 al[mt][0], al[mt][1], al[mt][2], al[mt][3], bh0, bh1);
                        MMA_BF16(c[0], c[1], c[2], c[3],
                                 ah[mt][0], ah[mt][1], ah[mt][2], ah[mt][3], bl0, bl1);
                        MMA_BF16(c[0], c[1], c[2], c[3],
                                 ah[mt][0], ah[mt][1], ah[mt][2], ah[mt][3], bh0, bh1);
                    }
                }
            }
        }
    }

    int pix0 = (y0 + ry) * 128 + xoff;
    #pragma unroll
    for (int mt = 0; mt < 2; mt++) {
        int m = m0 + wm * 32 + mt * 16 + g;
        float bb0 = bias[m], bb1 = bias[m + 8];
        float* C0 = &g_i2h[(b * 192 + m    ) * NPIX];
        float* C1 = &g_i2h[(b * 192 + m + 8) * NPIX];
        #pragma unroll
        for (int nt = 0; nt < 8; nt++) {
            int px = pix0 + nt * 8 + t4 * 2;
            *(float2*)&C0[px] = make_float2(acc[mt][nt][0] + bb0, acc[mt][nt][1] + bb0);
            *(float2*)&C1[px] = make_float2(acc[mt][nt][2] + bb1, acc[mt][nt][3] + bb1);
        }
    }
}

// ---------------------------------------------------------------------------
// f1: conv5x5 of one source (64 ic -> 32 oc), bf16-split TC, partial sums.
// grid (32, 2 src, 2 b).
// ---------------------------------------------------------------------------
#define C5_SMEM_BYTES ((2 * 8000 + 2 * 8768) * 4)
__global__ __launch_bounds__(256) void f1_k(int t, int first)
{
    int src = blockIdx.y;
    if (first && src) return;

    extern __shared__ uint32_t sm_u[];
    uint32_t* s_wh = sm_u;
    uint32_t* s_wl = s_wh + 8000;
    uint32_t* s_xh = s_wl + 8000;
    uint32_t* s_xl = s_xh + 8768;

    int tid = threadIdx.x;
    int lane = tid & 31;
    int g  = lane >> 2;
    int t4 = lane & 3;
    int wid = tid >> 5;
    int rw = wid >> 1;
    int xoff = (wid & 1) * 64;

    int y0 = blockIdx.x * 4;
    int b  = blockIdx.z;
    const uint32_t* inh = src ? (g_hbf_h + b * 32 * NPIX) : (g_ysbf_h + (b * 192 + t * 32) * NPIX);
    const uint32_t* inl = src ? (g_hbf_l + b * 32 * NPIX) : (g_ysbf_l + (b * 192 + t * 32) * NPIX);

    float acc[2][8][4];
    #pragma unroll
    for (int mt = 0; mt < 2; mt++)
        #pragma unroll
        for (int nt = 0; nt < 8; nt++)
            #pragma unroll
            for (int i = 0; i < 4; i++) acc[mt][nt][i] = 0.f;

    for (int chunk = 0; chunk < 4; chunk++) {
        __syncthreads();
        int wbase = (src * 4 + chunk) * 6400;
        for (int i = tid; i < 6400; i += 256) {
            int smi = (i >> 5) * 40 + (i & 31);
            s_wh[smi] = g_wf1_h[wbase + i];
            s_wl[smi] = g_wf1_l[wbase + i];
        }
        int pbase = chunk * 8;
        for (int i = tid; i < 8448; i += 256) {
            int col = i % 132, r = i / 132;
            int row = r & 7, kp = r >> 3;
            int gy = y0 - 2 + row, gx = col - 2;
            uint32_t vh = 0, vl = 0;
            if (gy >= 0 && gy < 128 && gx >= 0 && gx < 128) {
                int off = (pbase + kp) * NPIX + gy * 128 + gx;
                vh = inh[off]; vl = inl[off];
            }
            int si = kp * 1096 + row * 136 + col;
            s_xh[si] = vh; s_xl[si] = vl;
        }
        __syncthreads();

        #pragma unroll 1
        for (int ky = 0; ky < 5; ky++) {
            #pragma unroll
            for (int kx = 0; kx < 5; kx++) {
                int tap = ky * 5 + kx;
                uint32_t ah[2][4], al[2][4];
                #pragma unroll
                for (int mt = 0; mt < 2; mt++) {
                    int mm = mt * 16 + g;
                    int r0 = (tap * 8 + t4) * 40, r1 = (tap * 8 + t4 + 4) * 40;
                    ah[mt][0] = s_wh[r0 + mm];     ah[mt][1] = s_wh[r0 + mm + 8];
                    ah[mt][2] = s_wh[r1 + mm];     ah[mt][3] = s_wh[r1 + mm + 8];
                    al[mt][0] = s_wl[r0 + mm];     al[mt][1] = s_wl[r0 + mm + 8];
                    al[mt][2] = s_wl[r1 + mm];     al[mt][3] = s_wl[r1 + mm + 8];
                }
                int base = (rw + ky) * 136 + xoff + kx;
                #pragma unroll
                for (int nt = 0; nt < 8; nt++) {
                    int cc = base + nt * 8 + g;
                    uint32_t bh0 = s_xh[t4 * 1096 + cc];
                    uint32_t bh1 = s_xh[(t4 + 4) * 1096 + cc];
                    uint32_t bl0 = s_xl[t4 * 1096 + cc];
                    uint32_t bl1 = s_xl[(t4 + 4) * 1096 + cc];
                    #pragma unroll
                    for (int mt = 0; mt < 2; mt++) {
                        float* c = acc[mt][nt];
                        MMA_BF16(c[0], c[1], c[2], c[3],
                                 al[mt][0], al[mt][1], al[mt][2], al[mt][3], bh0, bh1);
                        MMA_BF16(c[0], c[1], c[2], c[3],
                                 ah[mt][0], ah[mt][1], ah[mt][2], ah[mt][3], bl0, bl1);
                        MMA_BF16(c[0], c[1], c[2], c[3],
                                 ah[mt][0], ah[mt][1], ah[mt][2], ah[mt][3], bh0, bh1);
                    }
                }
            }
        }
    }

    float* op = g_f1p[src];
    int pix0 = (y0 + rw) * 128 + xoff;
    #pragma unroll
    for (int mt = 0; mt < 2; mt++) {
        int m = mt * 16 + g;
        float* C0 = &op[(b * 32 + m    ) * NPIX];
        float* C1 = &op[(b * 32 + m + 8) * NPIX];
        #pragma unroll
        for (int nt = 0; nt < 8; nt++) {
            int px = pix0 + nt * 8 + t4 * 2;
            *(float2*)&C0[px] = make_float2(acc[mt][nt][0], acc[mt][nt][1]);
            *(float2*)&C1[px] = make_float2(acc[mt][nt][2], acc[mt][nt][3]);
        }
    }
}

// ---------------------------------------------------------------------------
// flow: conv5x5 32 -> 26 (padded 32), bf16-split TC, writes g_fl + bias.
// Input loader FUSES the f1 combine: reads fp32 partials of both sources,
// adds biases, leaky, bf16-splits inline (same ops f1comb did; g_f1bf gone).
// ---------------------------------------------------------------------------
__global__ __launch_bounds__(256) void flow_k(const float* __restrict__ bias,
                                              const float* __restrict__ bi,
                                              const float* __restrict__ bh,
                                              int first)
{
    extern __shared__ uint32_t sm_u[];
    uint32_t* s_wh = sm_u;
    uint32_t* s_wl = s_wh + 8000;
    uint32_t* s_xh = s_wl + 8000;
    uint32_t* s_xl = s_xh + 8768;
    __shared__ float s_cb[32];             // combined f1 bias

    int tid = threadIdx.x;
    int lane = tid & 31;
    int g  = lane >> 2;
    int t4 = lane & 3;
    int wid = tid >> 5;
    int rw = wid >> 1;
    int xoff = (wid & 1) * 64;

    int y0 = blockIdx.x * 4;
    int b  = blockIdx.z;
    if (tid < 32) s_cb[tid] = bi[tid] + bh[tid];

    const float* p0 = g_f1p[0] + b * 32 * NPIX;
    const float* p1 = g_f1p[1] + b * 32 * NPIX;

    float acc[2][8][4];
    #pragma unroll
    for (int mt = 0; mt < 2; mt++)
        #pragma unroll
        for (int nt = 0; nt < 8; nt++)
            #pragma unroll
            for (int i = 0; i < 4; i++) acc[mt][nt][i] = 0.f;

    for (int chunk = 0; chunk < 2; chunk++) {
        __syncthreads();
        int wbase = chunk * 6400;
        for (int i = tid; i < 6400; i += 256) {
            int smi = (i >> 5) * 40 + (i & 31);
            s_wh[smi] = g_wfl_h[wbase + i];
            s_wl[smi] = g_wfl_l[wbase + i];
        }
        int pbase = chunk * 8;
        for (int i = tid; i < 8448; i += 256) {
            int col = i % 132, r = i / 132;
            int row = r & 7, kp = r >> 3;
            int gy = y0 - 2 + row, gx = col - 2;
            uint32_t vh = 0, vl = 0;
            if (gy >= 0 && gy < 128 && gx >= 0 && gx < 128) {
                int c0 = 2 * (pbase + kp);              // channels (c0, c0+1)
                int off = (size_t)0 + gy * 128 + gx;
                const float* q0 = p0 + c0 * NPIX;
                float v0 = q0[off], v1 = q0[NPIX + off];
                if (!first) {
                    const float* q1 = p1 + c0 * NPIX;
                    v0 += q1[off]; v1 += q1[NPIX + off];
                }
                v0 = leaky_f(v0 + s_cb[c0]);
                v1 = leaky_f(v1 + s_cb[c0 + 1]);
                split2(v0, v1, vh, vl);
            }
            int si = kp * 1096 + row * 136 + col;
            s_xh[si] = vh; s_xl[si] = vl;
        }
        __syncthreads();

        #pragma unroll 1
        for (int ky = 0; ky < 5; ky++) {
            #pragma unroll
            for (int kx = 0; kx < 5; kx++) {
                int tap = ky * 5 + kx;
                uint32_t ah[2][4], al[2][4];
                #pragma unroll
                for (int mt = 0; mt < 2; mt++) {
                    int mm = mt * 16 + g;
                    int r0 = (tap * 8 + t4) * 40, r1 = (tap * 8 + t4 + 4) * 40;
                    ah[mt][0] = s_wh[r0 + mm];     ah[mt][1] = s_wh[r0 + mm + 8];
                    ah[mt][2] = s_wh[r1 + mm];     ah[mt][3] = s_wh[r1 + mm + 8];
                    al[mt][0] = s_wl[r0 + mm];     al[mt][1] = s_wl[r0 + mm + 8];
                    al[mt][2] = s_wl[r1 + mm];     al[mt][3] = s_wl[r1 + mm + 8];
                }
                int base = (rw + ky) * 136 + xoff + kx;
                #pragma unroll
                for (int nt = 0; nt < 8; nt++) {
                    int cc = base + nt * 8 + g;
                    uint32_t bh0 = s_xh[t4 * 1096 + cc];
                    uint32_t bh1 = s_xh[(t4 + 4) * 1096 + cc];
                    uint32_t bl0 = s_xl[t4 * 1096 + cc];
                    uint32_t bl1 = s_xl[(t4 + 4) * 1096 + cc];
                    #pragma unroll
                    for (int mt = 0; mt < 2; mt++) {
                        float* c = acc[mt][nt];
                        MMA_BF16(c[0], c[1], c[2], c[3],
                                 al[mt][0], al[mt][1], al[mt][2], al[mt][3], bh0, bh1);
                        MMA_BF16(c[0], c[1], c[2], c[3],
                                 ah[mt][0], ah[mt][1], ah[mt][2], ah[mt][3], bl0, bl1);
                        MMA_BF16(c[0], c[1], c[2], c[3],
                                 ah[mt][0], ah[mt][1], ah[mt][2], ah[mt][3], bh0, bh1);
                    }
                }
            }
        }
    }

    int pix0 = (y0 + rw) * 128 + xoff;
    #pragma unroll
    for (int mt = 0; mt < 2; mt++) {
        int m = mt * 16 + g;
        #pragma unroll
        for (int nt = 0; nt < 8; nt++) {
            int px = pix0 + nt * 8 + t4 * 2;
            if (m < 26) {
                float bb = bias[m];
                *(float2*)&g_fl[(b * 26 + m) * NPIX + px] =
                    make_float2(acc[mt][nt][0] + bb, acc[mt][nt][1] + bb);
            }
            if (m + 8 < 26) {
                float bb = bias[m + 8];
                *(float2*)&g_fl[(b * 26 + m + 8) * NPIX + px] =
                    make_float2(acc[mt][nt][2] + bb, acc[mt][nt][3] + bb);
            }
        }
    }
}

// ---------------------------------------------------------------------------
// wret: fused warp + ret (t>=1 only). grid (128, 2, 2).  [round-9 config]
// ---------------------------------------------------------------------------
__global__ __launch_bounds__(256, 2) void wret_k(int t, const float* __restrict__ bias,
                                                 const float* __restrict__ outp)
{
    __shared__ int      s_ci[4][128];
    __shared__ float    s_cw[4][128];
    __shared__ uint32_t s_wh[8 * 104], s_wl[8 * 104];
    __shared__ uint32_t s_bh[8 * 136], s_bl[8 * 136];

    int tid = threadIdx.x;
    int lane = tid & 31;
    int g  = lane >> 2;
    int t4 = lane & 3;
    int wid = tid >> 5;
    int wm = wid >> 2;
    int wn = wid & 3;
    int mb = wm * 48;
    int nb = wn * 32;

    int b  = blockIdx.z;
    int n0 = blockIdx.x * 128;
    int mblk = blockIdx.y;
    int m0 = mblk * 96;

    float acc[3][4][4];
    #pragma unroll
    for (int mt = 0; mt < 3; mt++)
        #pragma unroll
        for (int nt = 0; nt < 4; nt++)
            #pragma unroll
            for (int i = 0; i < 4; i++) acc[mt][nt][i] = 0.f;

    const float* hprev = outp + ((b * 6 + (t - 1)) * 64) * NPIX;

    for (int l = 0; l < 13; l++) {
        __syncthreads();
        if (tid < 128) {
            int pg = n0 + tid;
            float u = g_fl[(b * 26 + 2 * l    ) * NPIX + pg];
            float v = g_fl[(b * 26 + 2 * l + 1) * NPIX + pg];
            float sx = (float)(pg & 127) - u;
            float sy = (float)(pg >> 7)  - v;
            float fx = floorf(sx), fy = floorf(sy);
            float wx1 = sx - fx, wx0 = 1.f - wx1;
            float wy1 = sy - fy, wy0 = 1.f - wy1;
            int x0 = (int)fx, y0 = (int)fy;
            int x1 = x0 + 1,  y1 = y0 + 1;
            bool vx0 = (x0 >= 0) & (x0 <= 127);
            bool vx1 = (x1 >= 0) & (x1 <= 127);
            bool vy0 = (y0 >= 0) & (y0 <= 127);
            bool vy1 = (y1 >= 0) & (y1 <= 127);
            int cx0 = min(max(x0, 0), 127), cx1 = min(max(x1, 0), 127);
            int cy0 = min(max(y0, 0), 127), cy1 = min(max(y1, 0), 127);
            s_ci[0][tid] = cy0 * 128 + cx0;
            s_ci[1][tid] = cy0 * 128 + cx1;
            s_ci[2][tid] = cy1 * 128 + cx0;
            s_ci[3][tid] = cy1 * 128 + cx1;
            s_cw[0][tid] = (vx0 && vy0) ? wx0 * wy0 : 0.f;
            s_cw[1][tid] = (vx1 && vy0) ? wx1 * wy0 : 0.f;
            s_cw[2][tid] = (vx0 && vy1) ? wx0 * wy1 : 0.f;
            s_cw[3][tid] = (vx1 && vy1) ? wx1 * wy1 : 0.f;
        }

        for (int chunk = 0; chunk < 4; chunk++) {
            __syncthreads();
            int wbase = ((mblk * 13 + l) * 4 + chunk) * 768;
            #pragma unroll
            for (int r = 0; r < 3; r++) {
                int i = tid + r * 256;
                int smi = (i / 96) * 104 + (i % 96);
                s_wh[smi] = g_wret_h[wbase + i];
                s_wl[smi] = g_wret_l[wbase + i];
            }
            #pragma unroll
            for (int r = 0; r < 4; r++) {
                int j = tid + r * 256;
                int kp = j >> 7, px = j & 127;
                int i00 = s_ci[0][px], i10 = s_ci[1][px];
                int i01 = s_ci[2][px], i11 = s_ci[3][px];
                float w00 = s_cw[0][px], w10 = s_cw[1][px];
                float w01 = s_cw[2][px], w11 = s_cw[3][px];
                const float* h0 = hprev + (chunk * 16 + kp * 2) * NPIX;
                const float* h1 = h0 + NPIX;
                float v0 = w00 * __ldg(&h0[i00]) + w10 * __ldg(&h0[i10])
                         + w01 * __ldg(&h0[i01]) + w11 * __ldg(&h0[i11]);
                float v1 = w00 * __ldg(&h1[i00]) + w10 * __ldg(&h1[i10])
                         + w01 * __ldg(&h1[i01]) + w11 * __ldg(&h1[i11]);
                uint32_t hh, ll;
                split2(v0, v1, hh, ll);
                s_bh[kp * 136 + px] = hh;
                s_bl[kp * 136 + px] = ll;
            }
            __syncthreads();

            uint32_t ah[3][4], al[3][4], bh[4][2], bl[4][2];
            #pragma unroll
            for (int mt = 0; mt < 3; mt++) {
                int mm = mb + mt * 16 + g;
                int r0 = t4 * 104, r1 = (t4 + 4) * 104;
                ah[mt][0] = s_wh[r0 + mm];     ah[mt][1] = s_wh[r0 + mm + 8];
                ah[mt][2] = s_wh[r1 + mm];     ah[mt][3] = s_wh[r1 + mm + 8];
                al[mt][0] = s_wl[r0 + mm];     al[mt][1] = s_wl[r0 + mm + 8];
                al[mt][2] = s_wl[r1 + mm];     al[mt][3] = s_wl[r1 + mm + 8];
            }
            #pragma unroll
            for (int nt = 0; nt < 4; nt++) {
                int nn = nb + nt * 8 + g;
                bh[nt][0] = s_bh[t4 * 136 + nn];
                bh[nt][1] = s_bh[(t4 + 4) * 136 + nn];
                bl[nt][0] = s_bl[t4 * 136 + nn];
                bl[nt][1] = s_bl[(t4 + 4) * 136 + nn];
            }
            #pragma unroll
            for (int mt = 0; mt < 3; mt++)
                #pragma unroll
                for (int nt = 0; nt < 4; nt++) {
                    float* c = acc[mt][nt];
                    MMA_BF16(c[0], c[1], c[2], c[3],
                             al[mt][0], al[mt][1], al[mt][2], al[mt][3],
                             bh[nt][0], bh[nt][1]);
                    MMA_BF16(c[0], c[1], c[2], c[3],
                             ah[mt][0], ah[mt][1], ah[mt][2], ah[mt][3],
                             bl[nt][0], bl[nt][1]);
                    MMA_BF16(c[0], c[1], c[2], c[3],
                             ah[mt][0], ah[mt][1], ah[mt][2], ah[mt][3],
                             bh[nt][0], bh[nt][1]);
                }
        }
    }

    float* C = g_h2h + b * 192 * NPIX;
    #pragma unroll
    for (int mt = 0; mt < 3; mt++) {
        int m = m0 + mb + mt * 16 + g;
        float bb0 = bias[m], bb1 = bias[m + 8];
        #pragma unroll
        for (int nt = 0; nt < 4; nt++) {
            int col = n0 + nb + nt * 8 + t4 * 2;
            float2 o0 = make_float2(acc[mt][nt][0] + bb0, acc[mt][nt][1] + bb0);
            float2 o1 = make_float2(acc[mt][nt][2] + bb1, acc[mt][nt][3] + bb1);
            *(float2*)&C[m * NPIX + col]       = o0;
            *(float2*)&C[(m + 8) * NPIX + col] = o1;
        }
    }
}

// ---------------------------------------------------------------------------
// GRU update: out[b,t] fp32 + bf16-split hidden copy. t=0: h2h = b_ret.
// grid (64, 32, 2), block 256.
// ---------------------------------------------------------------------------
__global__ void gru_k(int t, int first, const float* __restrict__ bret,
                      float* __restrict__ outp)
{
    int pix = blockIdx.x * 256 + threadIdx.x;
    int c2  = blockIdx.y;
    int b   = blockIdx.z;
    int c   = 2 * c2;
    int base = b * 192 * NPIX;

    float h01[2];
    #pragma unroll
    for (int j = 0; j < 2; j++) {
        int cj = c + j;
        float ir = g_i2h[base + (cj      ) * NPIX + pix];
        float iu = g_i2h[base + (cj +  64) * NPIX + pix];
        float im = g_i2h[base + (cj + 128) * NPIX + pix];
        float hr, hu, hm;
        if (first) {
            hr = bret[cj]; hu = bret[cj + 64]; hm = bret[cj + 128];
        } else {
            hr = g_h2h[base + (cj      ) * NPIX + pix];
            hu = g_h2h[base + (cj +  64) * NPIX + pix];
            hm = g_h2h[base + (cj + 128) * NPIX + pix];
        }

        float r = 1.f / (1.f + expf(-(ir + hr)));
        float z = 1.f / (1.f + expf(-(iu + hu)));
        float m = leaky_f(im + r * hm);

        float hp = first ? 0.f : outp[((b * 6 + t - 1) * 64 + cj) * NPIX + pix];
        float h  = z * hp + (1.f - z) * m;
        outp[((b * 6 + t) * 64 + cj) * NPIX + pix] = h;
        h01[j] = h;
    }
    uint32_t hw, lw;
    split2(h01[0], h01[1], hw, lw);
    int p = (b * 32 + c2) * NPIX + pix;
    g_hbf_h[p] = hw; g_hbf_l[p] = lw;
}

// ---------------------------------------------------------------------------
// Launch
// ---------------------------------------------------------------------------
extern "C" void kernel_launch(void* const* d_in, const int* in_sizes, int n_in,
                              void* d_out, int out_size)
{
    const float* x      = (const float*)d_in[0];
    const float* w_stem = (const float*)d_in[1];
    const float* b_stem = (const float*)d_in[2];
    const float* w_i2h  = (const float*)d_in[3];
    const float* b_i2h  = (const float*)d_in[4];
    const float* w_i2f  = (const float*)d_in[5];
    const float* b_i2f  = (const float*)d_in[6];
    const float* w_h2f  = (const float*)d_in[7];
    const float* b_h2f  = (const float*)d_in[8];
    const float* w_flow = (const float*)d_in[9];
    const float* b_flow = (const float*)d_in[10];
    const float* w_ret  = (const float*)d_in[11];
    const float* b_ret  = (const float*)d_in[12];
    float* outp = (float*)d_out;

    cudaFuncSetAttribute(i2h_k,  cudaFuncAttributeMaxDynamicSharedMemorySize, I2H_SMEM_BYTES);
    cudaFuncSetAttribute(f1_k,   cudaFuncAttributeMaxDynamicSharedMemorySize, C5_SMEM_BYTES);
    cudaFuncSetAttribute(flow_k, cudaFuncAttributeMaxDynamicSharedMemorySize, C5_SMEM_BYTES);

    wprep_all_k<<<(199168 + 255) / 256, 256>>>(w_i2h, w_i2f, w_h2f, w_flow, w_ret);

    stem_k<<<dim3(64, 48, 2), 256>>>(x, w_stem, b_stem);

    for (int t = 0; t < 6; t++) {
        int first = (t == 0) ? 1 : 0;
        i2h_k <<<dim3(64, 3, 2), 256, I2H_SMEM_BYTES>>>(t, b_i2h);
        f1_k  <<<dim3(32, 2, 2), 256, C5_SMEM_BYTES>>>(t, first);
        flow_k<<<dim3(32, 1, 2), 256, C5_SMEM_BYTES>>>(b_flow, b_i2f, b_h2f, first);
        if (!first)
            wret_k<<<dim3(128, 2, 2), 256>>>(t, b_ret, outp);
        gru_k <<<dim3(64, 32, 2), 256>>>(t, first, b_ret, outp);
    }
}

// round 13
// speedup vs baseline: 1.0875x; 1.0381x over previous
#include <cuda_runtime.h>
#include <cuda_bf16.h>
#include <math.h>
#include <stdint.h>

#define NPIX 16384            // 128*128

// ---------------------------------------------------------------------------
// Scratch (static device globals)
// ---------------------------------------------------------------------------
__device__ float g_i2h[2 * 192 * NPIX];     // i2h conv out (per step)   25 MB
__device__ float g_h2h[2 * 192 * NPIX];     // ret conv out              25 MB
__device__ float g_f1p[2][2 * 32 * NPIX];   // f1 partial sums (2 src)  8.4 MB
__device__ float g_fl [2 *  26 * NPIX];     // flows                    3.4 MB

// bf16-split packed operands (channel pairs per 32-bit word)
__device__ uint32_t g_ysbf_h[2 * 192 * NPIX], g_ysbf_l[2 * 192 * NPIX]; // stem out (c,c+1)
__device__ uint32_t g_hbf_h [2 *  32 * NPIX], g_hbf_l [2 *  32 * NPIX]; // hprev (c,c+1)

// pre-converted weights: layouts match smem consumption order
__device__ uint32_t g_wi2h_h[3 * 4 * 9 * 8 * 64],  g_wi2h_l[3 * 4 * 9 * 8 * 64];
__device__ uint32_t g_wf1_h [2 * 4 * 25 * 8 * 32], g_wf1_l [2 * 4 * 25 * 8 * 32];
__device__ uint32_t g_wfl_h [2 * 25 * 8 * 32],     g_wfl_l [2 * 25 * 8 * 32];
__device__ uint32_t g_wret_h[2 * 13 * 4 * 8 * 96], g_wret_l[2 * 13 * 4 * 8 * 96];

__device__ __forceinline__ float leaky_f(float x) { return x >= 0.f ? x : 0.2f * x; }

// split two floats into packed bf16 hi-pair and lo-pair (v = hi + lo)
__device__ __forceinline__ void split2(float v0, float v1, uint32_t& h, uint32_t& l) {
    __nv_bfloat162 hb = __floats2bfloat162_rn(v0, v1);
    float h0 = __low2float(hb), h1 = __high2float(hb);
    __nv_bfloat162 lb = __floats2bfloat162_rn(v0 - h0, v1 - h1);
    h = *reinterpret_cast<uint32_t*>(&hb);
    l = *reinterpret_cast<uint32_t*>(&lb);
}

#define MMA_BF16(c0,c1,c2,c3, a0,a1,a2,a3, b0,b1)                              \
    asm volatile("mma.sync.aligned.m16n8k16.row.col.f32.bf16.bf16.f32 "        \
        "{%0,%1,%2,%3}, {%4,%5,%6,%7}, {%8,%9}, {%0,%1,%2,%3};"                \
        : "+f"(c0), "+f"(c1), "+f"(c2), "+f"(c3)                               \
        : "r"(a0), "r"(a1), "r"(a2), "r"(a3), "r"(b0), "r"(b1))

// ---------------------------------------------------------------------------
// Weight prep — all four conversions in ONE kernel (run once per launch)
// ---------------------------------------------------------------------------
__global__ void wprep_all_k(const float* __restrict__ wi2h,
                            const float* __restrict__ wi2f,
                            const float* __restrict__ wh2f,
                            const float* __restrict__ wfl,
                            const float* __restrict__ wret)
{
    int idx = blockIdx.x * 256 + threadIdx.x;

    if (idx < 55296) {
        // i2h: [ocg3][chunk4][tap9][kp8][oc64]; pairs (ic, ic+1)
        int oc = idx & 63;
        int kp = (idx >> 6) & 7;
        int q  = idx >> 9;
        int tap = q % 9;
        int qc  = q / 9;
        int chunk = qc & 3, ocg = qc >> 2;
        int ic = chunk * 16 + 2 * kp;
        int o  = ocg * 64 + oc;
        float v0 = wi2h[(o * 64 + ic    ) * 9 + tap];
        float v1 = wi2h[(o * 64 + ic + 1) * 9 + tap];
        split2(v0, v1, g_wi2h_h[idx], g_wi2h_l[idx]);
        return;
    }
    idx -= 55296;
    if (idx < 51200) {
        // f1: [src2][chunk4][tap25][kp8][oc32]; pairs (ic, ic+1)
        int oc = idx & 31;
        int kp = (idx >> 5) & 7;
        int q  = idx >> 8;
        int tap = q % 25;
        int qc  = q / 25;
        int chunk = qc & 3, src = qc >> 2;
        int ic = chunk * 16 + 2 * kp;
        const float* w = src ? wh2f : wi2f;
        float v0 = w[(oc * 64 + ic    ) * 25 + tap];
        float v1 = w[(oc * 64 + ic + 1) * 25 + tap];
        split2(v0, v1, g_wf1_h[idx], g_wf1_l[idx]);
        return;
    }
    idx -= 51200;
    if (idx < 12800) {
        // flow: [chunk2][tap25][kp8][oc32] (oc >= 26 zero); pairs (ic, ic+1)
        int oc = idx & 31;
        int kp = (idx >> 5) & 7;
        int q  = idx >> 8;
        int tap = q % 25;
        int chunk = q / 25;
        int ic = chunk * 16 + 2 * kp;
        float v0 = 0.f, v1 = 0.f;
        if (oc < 26) {
            v0 = wfl[(oc * 32 + ic    ) * 25 + tap];
            v1 = wfl[(oc * 32 + ic + 1) * 25 + tap];
        }
        split2(v0, v1, g_wfl_h[idx], g_wfl_l[idx]);
        return;
    }
    idx -= 12800;
    if (idx < 79872) {
        // ret: [mb2][l13][chunk4][kp8][m96]; pairs (k, k+1)
        int m  = idx % 96;
        int kp = (idx / 96) & 7;
        int chunk = (idx / 768) & 3;
        int l  = (idx / 3072) % 13;
        int mb = idx / 39936;
        int k  = l * 64 + chunk * 16 + kp * 2;
        float v0 = wret[(mb * 96 + m) * 832 + k];
        float v1 = wret[(mb * 96 + m) * 832 + k + 1];
        split2(v0, v1, g_wret_h[idx], g_wret_l[idx]);
    }
}

// ---------------------------------------------------------------------------
// Stem: conv 3x3 stride 2 pad 1 -> bf16-split
// ---------------------------------------------------------------------------
__global__ __launch_bounds__(256) void stem_k(const float* __restrict__ x,
                                              const float* __restrict__ w,
                                              const float* __restrict__ bias)
{
    __shared__ __align__(16) float sw[54][8];

    int tid = threadIdx.x;
    int oc0 = blockIdx.y * 8;
    int b   = blockIdx.z;

    for (int i = tid; i < 432; i += 256) {
        int oc = i & 7, tap = i >> 3;
        sw[tap][oc] = w[(oc0 + oc) * 54 + tap];
    }
    __syncthreads();

    int pix = blockIdx.x * 256 + tid;
    int oy = pix >> 7, ox = pix & 127;

    float acc[8];
    #pragma unroll
    for (int j = 0; j < 8; j++) acc[j] = bias[oc0 + j];

    #pragma unroll
    for (int ic = 0; ic < 6; ic++) {
        const float* xb = x + (b * 6 + ic) * 65536;
        float in[9];
        #pragma unroll
        for (int ky = 0; ky < 3; ky++) {
            int iy = 2 * oy - 1 + ky;
            #pragma unroll
            for (int kx = 0; kx < 3; kx++) {
                int ix = 2 * ox - 1 + kx;
                bool ok = (iy >= 0) & (iy <= 255) & (ix >= 0) & (ix <= 255);
                in[ky * 3 + kx] = ok ? __ldg(&xb[iy * 256 + ix]) : 0.f;
            }
        }
        #pragma unroll
        for (int k = 0; k < 9; k++) {
            int tap = ic * 9 + k;
            float a[8];
            *(float4*)&a[0] = *(const float4*)&sw[tap][0];
            *(float4*)&a[4] = *(const float4*)&sw[tap][4];
            #pragma unroll
            for (int j = 0; j < 8; j++) acc[j] += in[k] * a[j];
        }
    }
    #pragma unroll
    for (int j = 0; j < 8; j++) acc[j] = leaky_f(acc[j]);

    int pbase = ((b * 384 + oc0) >> 1) * NPIX + pix;
    #pragma unroll
    for (int j = 0; j < 4; j++) {
        uint32_t h, l;
        split2(acc[2 * j], acc[2 * j + 1], h, l);
        g_ysbf_h[pbase + j * NPIX] = h;
        g_ysbf_l[pbase + j * NPIX] = l;
    }
}

// ---------------------------------------------------------------------------
// i2h: conv3x3 64->192, per step. grid (64, 3, 2).  [unchanged]
// ---------------------------------------------------------------------------
#define I2H_SMEM_BYTES ((2 * 5184 + 2 * 4416) * 4)
__global__ __launch_bounds__(256) void i2h_k(int t, const float* __restrict__ bias)
{
    extern __shared__ uint32_t sm_u[];
    uint32_t* s_wh = sm_u;
    uint32_t* s_wl = s_wh + 5184;
    uint32_t* s_xh = s_wl + 5184;
    uint32_t* s_xl = s_xh + 4416;

    int tid = threadIdx.x;
    int lane = tid & 31;
    int g  = lane >> 2;
    int t4 = lane & 3;
    int wid = tid >> 5;
    int wm = wid >> 2;
    int wn = wid & 3;
    int ry = wn >> 1;
    int xoff = (wn & 1) * 64;

    int y0 = blockIdx.x * 2;
    int ocg = blockIdx.y;
    int m0 = ocg * 64;
    int b  = blockIdx.z;
    const uint32_t* inh = g_ysbf_h + (b * 192 + t * 32) * NPIX;
    const uint32_t* inl = g_ysbf_l + (b * 192 + t * 32) * NPIX;

    float acc[2][8][4];
    #pragma unroll
    for (int mt = 0; mt < 2; mt++)
        #pragma unroll
        for (int nt = 0; nt < 8; nt++)
            #pragma unroll
            for (int i = 0; i < 4; i++) acc[mt][nt][i] = 0.f;

    for (int chunk = 0; chunk < 4; chunk++) {
        __syncthreads();
        int wbase = (ocg * 4 + chunk) * 4608;
        for (int i = tid; i < 4608; i += 256) {
            int smi = (i >> 6) * 72 + (i & 63);
            s_wh[smi] = g_wi2h_h[wbase + i];
            s_wl[smi] = g_wi2h_l[wbase + i];
        }
        int pbase = chunk * 8;
        for (int i = tid; i < 4160; i += 256) {
            int col = i % 130, r = i / 130;
            int row = r & 3, kp = r >> 2;
            int gy = y0 - 1 + row, gx = col - 1;
            uint32_t vh = 0, vl = 0;
            if (gy >= 0 && gy < 128 && gx >= 0 && gx < 128) {
                int off = (pbase + kp) * NPIX + gy * 128 + gx;
                vh = inh[off]; vl = inl[off];
            }
            int si = kp * 552 + row * 136 + col;
            s_xh[si] = vh; s_xl[si] = vl;
        }
        __syncthreads();

        #pragma unroll
        for (int ky = 0; ky < 3; ky++) {
            #pragma unroll
            for (int kx = 0; kx < 3; kx++) {
                int tap = ky * 3 + kx;
                uint32_t ah[2][4], al[2][4];
                #pragma unroll
                for (int mt = 0; mt < 2; mt++) {
                    int mm = wm * 32 + mt * 16 + g;
                    int r0 = (tap * 8 + t4) * 72, r1 = (tap * 8 + t4 + 4) * 72;
                    ah[mt][0] = s_wh[r0 + mm];     ah[mt][1] = s_wh[r0 + mm + 8];
                    ah[mt][2] = s_wh[r1 + mm];     ah[mt][3] = s_wh[r1 + mm + 8];
                    al[mt][0] = s_wl[r0 + mm];     al[mt][1] = s_wl[r0 + mm + 8];
                    al[mt][2] = s_wl[r1 + mm];     al[mt][3] = s_wl[r1 + mm + 8];
                }
                int base = (ry + ky) * 136 + xoff + kx;
                #pragma unroll
                for (int nt = 0; nt < 8; nt++) {
                    int cc = base + nt * 8 + g;
                    uint32_t bh0 = s_xh[t4 * 552 + cc];
                    uint32_t bh1 = s_xh[(t4 + 4) * 552 + cc];
                    uint32_t bl0 = s_xl[t4 * 552 + cc];
                    uint32_t bl1 = s_xl[(t4 + 4) * 552 + cc];
                    #pragma unroll
                    for (int mt = 0; mt < 2; mt++) {
                        float* c = acc[mt][nt];
                        MMA_BF16(c[0], c[1], c[2], c[3],
                                 al[mt][0], al[mt][1], al[mt][2], al[mt][3], bh0, bh1);
                        MMA_BF16(c[0], c[1], c[2], c[3],
                                 ah[mt][0], ah[mt][1], ah[mt][2], ah[mt][3], bl0, bl1);
                        MMA_BF16(c[0], c[1], c[2], c[3],
                                 ah[mt][0], ah[mt][1], ah[mt][2], ah[mt][3], bh0, bh1);
                    }
                }
            }
        }
    }

    int pix0 = (y0 + ry) * 128 + xoff;
    #pragma unroll
    for (int mt = 0; mt < 2; mt++) {
        int m = m0 + wm * 32 + mt * 16 + g;
        float bb0 = bias[m], bb1 = bias[m + 8];
        float* C0 = &g_i2h[(b * 192 + m    ) * NPIX];
        float* C1 = &g_i2h[(b * 192 + m + 8) * NPIX];
        #pragma unroll
        for (int nt = 0; nt < 8; nt++) {
            int px = pix0 + nt * 8 + t4 * 2;
            *(float2*)&C0[px] = make_float2(acc[mt][nt][0] + bb0, acc[mt][nt][1] + bb0);
            *(float2*)&C1[px] = make_float2(acc[mt][nt][2] + bb1, acc[mt][nt][3] + bb1);
        }
    }
}

// ---------------------------------------------------------------------------
// f1: conv5x5 of one source (64 ic -> 32 oc). 2-row tiles, ky-staged weights,
// 2 blocks/SM. grid (64, 2 src, 2 b), block 256, smem 64.5 KB.
// Warp = 32 oc x 32 px. Input smem: kp stride 808 (=8 mod 32), row stride 132.
// ---------------------------------------------------------------------------
#define C5_SMEM_BYTES ((2 * 1600 + 2 * 6464) * 4)
__global__ __launch_bounds__(256, 2) void f1_k(int t, int first)
{
    int src = blockIdx.y;
    if (first && src) return;

    extern __shared__ uint32_t sm_u[];
    uint32_t* s_wh = sm_u;             // [5 kx][8 kp][40]
    uint32_t* s_wl = s_wh + 1600;
    uint32_t* s_xh = s_wl + 1600;      // [8 kp][6 rows x 132], kp stride 808
    uint32_t* s_xl = s_xh + 6464;

    int tid = threadIdx.x;
    int lane = tid & 31;
    int g  = lane >> 2;
    int t4 = lane & 3;
    int wid = tid >> 5;
    int rw = wid >> 2;                 // output row within tile (0..1)
    int xoff = (wid & 3) * 32;         // 0,32,64,96

    int y0 = blockIdx.x * 2;
    int b  = blockIdx.z;
    const uint32_t* inh = src ? (g_hbf_h + b * 32 * NPIX) : (g_ysbf_h + (b * 192 + t * 32) * NPIX);
    const uint32_t* inl = src ? (g_hbf_l + b * 32 * NPIX) : (g_ysbf_l + (b * 192 + t * 32) * NPIX);

    float acc[2][4][4];
    #pragma unroll
    for (int mt = 0; mt < 2; mt++)
        #pragma unroll
        for (int nt = 0; nt < 4; nt++)
            #pragma unroll
            for (int i = 0; i < 4; i++) acc[mt][nt][i] = 0.f;

    for (int chunk = 0; chunk < 4; chunk++) {
        __syncthreads();               // prior compute done: input+weights reusable
        int pbase = chunk * 8;
        for (int i = tid; i < 6336; i += 256) {      // 8 kp x 6 rows x 132
            int col = i % 132, r = i / 132;
            int row = r % 6, kp = r / 6;
            int gy = y0 - 2 + row, gx = col - 2;
            uint32_t vh = 0, vl = 0;
            if (gy >= 0 && gy < 128 && gx >= 0 && gx < 128) {
                int off = (pbase + kp) * NPIX + gy * 128 + gx;
                vh = inh[off]; vl = inl[off];
            }
            int si = kp * 808 + row * 132 + col;
            s_xh[si] = vh; s_xl[si] = vl;
        }
        #pragma unroll 1
        for (int ky = 0; ky < 5; ky++) {
            if (ky) __syncthreads();   // prior ky compute done: weight buf reusable
            int wbase = ((src * 4 + chunk) * 25 + ky * 5) * 256;
            {
                int i = tid;           // 1280 elems, exactly 5 iters
                #pragma unroll
                for (int r = 0; r < 5; r++) {
                    int smi = (i >> 5) * 40 + (i & 31);
                    s_wh[smi] = g_wf1_h[wbase + i];
                    s_wl[smi] = g_wf1_l[wbase + i];
                    i += 256;
                }
            }
            __syncthreads();           // weights (and, at ky=0, input) ready

            #pragma unroll
            for (int kx = 0; kx < 5; kx++) {
                uint32_t ah[2][4], al[2][4];
                #pragma unroll
                for (int mt = 0; mt < 2; mt++) {
                    int mm = mt * 16 + g;
                    int r0 = (kx * 8 + t4) * 40, r1 = (kx * 8 + t4 + 4) * 40;
                    ah[mt][0] = s_wh[r0 + mm];     ah[mt][1] = s_wh[r0 + mm + 8];
                    ah[mt][2] = s_wh[r1 + mm];     ah[mt][3] = s_wh[r1 + mm + 8];
                    al[mt][0] = s_wl[r0 + mm];     al[mt][1] = s_wl[r0 + mm + 8];
                    al[mt][2] = s_wl[r1 + mm];     al[mt][3] = s_wl[r1 + mm + 8];
                }
                int base = (rw + ky) * 132 + xoff + kx;
                #pragma unroll
                for (int nt = 0; nt < 4; nt++) {
                    int cc = base + nt * 8 + g;
                    uint32_t bh0 = s_xh[t4 * 808 + cc];
                    uint32_t bh1 = s_xh[(t4 + 4) * 808 + cc];
                    uint32_t bl0 = s_xl[t4 * 808 + cc];
                    uint32_t bl1 = s_xl[(t4 + 4) * 808 + cc];
                    #pragma unroll
                    for (int mt = 0; mt < 2; mt++) {
                        float* c = acc[mt][nt];
                        MMA_BF16(c[0], c[1], c[2], c[3],
                                 al[mt][0], al[mt][1], al[mt][2], al[mt][3], bh0, bh1);
                        MMA_BF16(c[0], c[1], c[2], c[3],
                                 ah[mt][0], ah[mt][1], ah[mt][2], ah[mt][3], bl0, bl1);
                        MMA_BF16(c[0], c[1], c[2], c[3],
                                 ah[mt][0], ah[mt][1], ah[mt][2], ah[mt][3], bh0, bh1);
                    }
                }
            }
        }
    }

    float* op = g_f1p[src];
    int pix0 = (y0 + rw) * 128 + xoff;
    #pragma unroll
    for (int mt = 0; mt < 2; mt++) {
        int m = mt * 16 + g;
        float* C0 = &op[(b * 32 + m    ) * NPIX];
        float* C1 = &op[(b * 32 + m + 8) * NPIX];
        #pragma unroll
        for (int nt = 0; nt < 4; nt++) {
            int px = pix0 + nt * 8 + t4 * 2;
            *(float2*)&C0[px] = make_float2(acc[mt][nt][0], acc[mt][nt][1]);
            *(float2*)&C1[px] = make_float2(acc[mt][nt][2], acc[mt][nt][3]);
        }
    }
}

// ---------------------------------------------------------------------------
// flow: conv5x5 32 -> 26 (padded 32). Same 2-row tiling as f1; input loader
// fuses the f1 combine (partial sums + biases + leaky + bf16 split).
// grid (64, 1, 2), smem 64.5 KB, 2 blocks/SM.
// ---------------------------------------------------------------------------
__global__ __launch_bounds__(256, 2) void flow_k(const float* __restrict__ bias,
                                                 const float* __restrict__ bi,
                                                 const float* __restrict__ bh,
                                                 int first)
{
    extern __shared__ uint32_t sm_u[];
    uint32_t* s_wh = sm_u;
    uint32_t* s_wl = s_wh + 1600;
    uint32_t* s_xh = s_wl + 1600;
    uint32_t* s_xl = s_xh + 6464;
    __shared__ float s_cb[32];

    int tid = threadIdx.x;
    int lane = tid & 31;
    int g  = lane >> 2;
    int t4 = lane & 3;
    int wid = tid >> 5;
    int rw = wid >> 2;
    int xoff = (wid & 3) * 32;

    int y0 = blockIdx.x * 2;
    int b  = blockIdx.z;
    if (tid < 32) s_cb[tid] = bi[tid] + bh[tid];

    const float* p0 = g_f1p[0] + b * 32 * NPIX;
    const float* p1 = g_f1p[1] + b * 32 * NPIX;

    float acc[2][4][4];
    #pragma unroll
    for (int mt = 0; mt < 2; mt++)
        #pragma unroll
        for (int nt = 0; nt < 4; nt++)
            #pragma unroll
            for (int i = 0; i < 4; i++) acc[mt][nt][i] = 0.f;

    for (int chunk = 0; chunk < 2; chunk++) {
        __syncthreads();
        int pbase = chunk * 8;
        for (int i = tid; i < 6336; i += 256) {
            int col = i % 132, r = i / 132;
            int row = r % 6, kp = r / 6;
            int gy = y0 - 2 + row, gx = col - 2;
            uint32_t vh = 0, vl = 0;
            if (gy >= 0 && gy < 128 && gx >= 0 && gx < 128) {
                int c0 = 2 * (pbase + kp);
                int off = gy * 128 + gx;
                const float* q0 = p0 + c0 * NPIX;
                float v0 = q0[off], v1 = q0[NPIX + off];
                if (!first) {
                    const float* q1 = p1 + c0 * NPIX;
                    v0 += q1[off]; v1 += q1[NPIX + off];
                }
                v0 = leaky_f(v0 + s_cb[c0]);
                v1 = leaky_f(v1 + s_cb[c0 + 1]);
                split2(v0, v1, vh, vl);
            }
            int si = kp * 808 + row * 132 + col;
            s_xh[si] = vh; s_xl[si] = vl;
        }
        #pragma unroll 1
        for (int ky = 0; ky < 5; ky++) {
            if (ky) __syncthreads();
            int wbase = (chunk * 25 + ky * 5) * 256;
            {
                int i = tid;
                #pragma unroll
                for (int r = 0; r < 5; r++) {
                    int smi = (i >> 5) * 40 + (i & 31);
                    s_wh[smi] = g_wfl_h[wbase + i];
                    s_wl[smi] = g_wfl_l[wbase + i];
                    i += 256;
                }
            }
            __syncthreads();

            #pragma unroll
            for (int kx = 0; kx < 5; kx++) {
                uint32_t ah[2][4], al[2][4];
                #pragma unroll
                for (int mt = 0; mt < 2; mt++) {
                    int mm = mt * 16 + g;
                    int r0 = (kx * 8 + t4) * 40, r1 = (kx * 8 + t4 + 4) * 40;
                    ah[mt][0] = s_wh[r0 + mm];     ah[mt][1] = s_wh[r0 + mm + 8];
                    ah[mt][2] = s_wh[r1 + mm];     ah[mt][3] = s_wh[r1 + mm + 8];
                    al[mt][0] = s_wl[r0 + mm];     al[mt][1] = s_wl[r0 + mm + 8];
                    al[mt][2] = s_wl[r1 + mm];     al[mt][3] = s_wl[r1 + mm + 8];
                }
                int base = (rw + ky) * 132 + xoff + kx;
                #pragma unroll
                for (int nt = 0; nt < 4; nt++) {
                    int cc = base + nt * 8 + g;
                    uint32_t bh0 = s_xh[t4 * 808 + cc];
                    uint32_t bh1 = s_xh[(t4 + 4) * 808 + cc];
                    uint32_t bl0 = s_xl[t4 * 808 + cc];
                    uint32_t bl1 = s_xl[(t4 + 4) * 808 + cc];
                    #pragma unroll
                    for (int mt = 0; mt < 2; mt++) {
                        float* c = acc[mt][nt];
                        MMA_BF16(c[0], c[1], c[2], c[3],
                                 al[mt][0], al[mt][1], al[mt][2], al[mt][3], bh0, bh1);
                        MMA_BF16(c[0], c[1], c[2], c[3],
                                 ah[mt][0], ah[mt][1], ah[mt][2], ah[mt][3], bl0, bl1);
                        MMA_BF16(c[0], c[1], c[2], c[3],
                                 ah[mt][0], ah[mt][1], ah[mt][2], ah[mt][3], bh0, bh1);
                    }
                }
            }
        }
    }

    int pix0 = (y0 + rw) * 128 + xoff;
    #pragma unroll
    for (int mt = 0; mt < 2; mt++) {
        int m = mt * 16 + g;
        #pragma unroll
        for (int nt = 0; nt < 4; nt++) {
            int px = pix0 + nt * 8 + t4 * 2;
            if (m < 26) {
                float bb = bias[m];
                *(float2*)&g_fl[(b * 26 + m) * NPIX + px] =
                    make_float2(acc[mt][nt][0] + bb, acc[mt][nt][1] + bb);
            }
            if (m + 8 < 26) {
                float bb = bias[m + 8];
                *(float2*)&g_fl[(b * 26 + m + 8) * NPIX + px] =
                    make_float2(acc[mt][nt][2] + bb, acc[mt][nt][3] + bb);
            }
        }
    }
}

// ---------------------------------------------------------------------------
// wret: fused warp + ret (t>=1 only). grid (128, 2, 2).  [round-9 config]
// ---------------------------------------------------------------------------
__global__ __launch_bounds__(256, 2) void wret_k(int t, const float* __restrict__ bias,
                                                 const float* __restrict__ outp)
{
    __shared__ int      s_ci[4][128];
    __shared__ float    s_cw[4][128];
    __shared__ uint32_t s_wh[8 * 104], s_wl[8 * 104];
    __shared__ uint32_t s_bh[8 * 136], s_bl[8 * 136];

    int tid = threadIdx.x;
    int lane = tid & 31;
    int g  = lane >> 2;
    int t4 = lane & 3;
    int wid = tid >> 5;
    int wm = wid >> 2;
    int wn = wid & 3;
    int mb = wm * 48;
    int nb = wn * 32;

    int b  = blockIdx.z;
    int n0 = blockIdx.x * 128;
    int mblk = blockIdx.y;
    int m0 = mblk * 96;

    float acc[3][4][4];
    #pragma unroll
    for (int mt = 0; mt < 3; mt++)
        #pragma unroll
        for (int nt = 0; nt < 4; nt++)
            #pragma unroll
            for (int i = 0; i < 4; i++) acc[mt][nt][i] = 0.f;

    const float* hprev = outp + ((b * 6 + (t - 1)) * 64) * NPIX;

    for (int l = 0; l < 13; l++) {
        __syncthreads();
        if (tid < 128) {
            int pg = n0 + tid;
            float u = g_fl[(b * 26 + 2 * l    ) * NPIX + pg];
            float v = g_fl[(b * 26 + 2 * l + 1) * NPIX + pg];
            float sx = (float)(pg & 127) - u;
            float sy = (float)(pg >> 7)  - v;
            float fx = floorf(sx), fy = floorf(sy);
            float wx1 = sx - fx, wx0 = 1.f - wx1;
            float wy1 = sy - fy, wy0 = 1.f - wy1;
            int x0 = (int)fx, y0 = (int)fy;
            int x1 = x0 + 1,  y1 = y0 + 1;
            bool vx0 = (x0 >= 0) & (x0 <= 127);
            bool vx1 = (x1 >= 0) & (x1 <= 127);
            bool vy0 = (y0 >= 0) & (y0 <= 127);
            bool vy1 = (y1 >= 0) & (y1 <= 127);
            int cx0 = min(max(x0, 0), 127), cx1 = min(max(x1, 0), 127);
            int cy0 = min(max(y0, 0), 127), cy1 = min(max(y1, 0), 127);
            s_ci[0][tid] = cy0 * 128 + cx0;
            s_ci[1][tid] = cy0 * 128 + cx1;
            s_ci[2][tid] = cy1 * 128 + cx0;
            s_ci[3][tid] = cy1 * 128 + cx1;
            s_cw[0][tid] = (vx0 && vy0) ? wx0 * wy0 : 0.f;
            s_cw[1][tid] = (vx1 && vy0) ? wx1 * wy0 : 0.f;
            s_cw[2][tid] = (vx0 && vy1) ? wx0 * wy1 : 0.f;
            s_cw[3][tid] = (vx1 && vy1) ? wx1 * wy1 : 0.f;
        }

        for (int chunk = 0; chunk < 4; chunk++) {
            __syncthreads();
            int wbase = ((mblk * 13 + l) * 4 + chunk) * 768;
            #pragma unroll
            for (int r = 0; r < 3; r++) {
                int i = tid + r * 256;
                int smi = (i / 96) * 104 + (i % 96);
                s_wh[smi] = g_wret_h[wbase + i];
                s_wl[smi] = g_wret_l[wbase + i];
            }
            #pragma unroll
            for (int r = 0; r < 4; r++) {
                int j = tid + r * 256;
                int kp = j >> 7, px = j & 127;
                int i00 = s_ci[0][px], i10 = s_ci[1][px];
                int i01 = s_ci[2][px], i11 = s_ci[3][px];
                float w00 = s_cw[0][px], w10 = s_cw[1][px];
                float w01 = s_cw[2][px], w11 = s_cw[3][px];
                const float* h0 = hprev + (chunk * 16 + kp * 2) * NPIX;
                const float* h1 = h0 + NPIX;
                float v0 = w00 * __ldg(&h0[i00]) + w10 * __ldg(&h0[i10])
                         + w01 * __ldg(&h0[i01]) + w11 * __ldg(&h0[i11]);
                float v1 = w00 * __ldg(&h1[i00]) + w10 * __ldg(&h1[i10])
                         + w01 * __ldg(&h1[i01]) + w11 * __ldg(&h1[i11]);
                uint32_t hh, ll;
                split2(v0, v1, hh, ll);
                s_bh[kp * 136 + px] = hh;
                s_bl[kp * 136 + px] = ll;
            }
            __syncthreads();

            uint32_t ah[3][4], al[3][4], bh[4][2], bl[4][2];
            #pragma unroll
            for (int mt = 0; mt < 3; mt++) {
                int mm = mb + mt * 16 + g;
                int r0 = t4 * 104, r1 = (t4 + 4) * 104;
                ah[mt][0] = s_wh[r0 + mm];     ah[mt][1] = s_wh[r0 + mm + 8];
                ah[mt][2] = s_wh[r1 + mm];     ah[mt][3] = s_wh[r1 + mm + 8];
                al[mt][0] = s_wl[r0 + mm];     al[mt][1] = s_wl[r0 + mm + 8];
                al[mt][2] = s_wl[r1 + mm];     al[mt][3] = s_wl[r1 + mm + 8];
            }
            #pragma unroll
            for (int nt = 0; nt < 4; nt++) {
                int nn = nb + nt * 8 + g;
                bh[nt][0] = s_bh[t4 * 136 + nn];
                bh[nt][1] = s_bh[(t4 + 4) * 136 + nn];
                bl[nt][0] = s_bl[t4 * 136 + nn];
                bl[nt][1] = s_bl[(t4 + 4) * 136 + nn];
            }
            #pragma unroll
            for (int mt = 0; mt < 3; mt++)
                #pragma unroll
                for (int nt = 0; nt < 4; nt++) {
                    float* c = acc[mt][nt];
                    MMA_BF16(c[0], c[1], c[2], c[3],
                             al[mt][0], al[mt][1], al[mt][2], al[mt][3],
                             bh[nt][0], bh[nt][1]);
                    MMA_BF16(c[0], c[1], c[2], c[3],
                             ah[mt][0], ah[mt][1], ah[mt][2], ah[mt][3],
                             bl[nt][0], bl[nt][1]);
                    MMA_BF16(c[0], c[1], c[2], c[3],
                             ah[mt][0], ah[mt][1], ah[mt][2], ah[mt][3],
                             bh[nt][0], bh[nt][1]);
                }
        }
    }

    float* C = g_h2h + b * 192 * NPIX;
    #pragma unroll
    for (int mt = 0; mt < 3; mt++) {
        int m = m0 + mb + mt * 16 + g;
        float bb0 = bias[m], bb1 = bias[m + 8];
        #pragma unroll
        for (int nt = 0; nt < 4; nt++) {
            int col = n0 + nb + nt * 8 + t4 * 2;
            float2 o0 = make_float2(acc[mt][nt][0] + bb0, acc[mt][nt][1] + bb0);
            float2 o1 = make_float2(acc[mt][nt][2] + bb1, acc[mt][nt][3] + bb1);
            *(float2*)&C[m * NPIX + col]       = o0;
            *(float2*)&C[(m + 8) * NPIX + col] = o1;
        }
    }
}

// ---------------------------------------------------------------------------
// GRU update: out[b,t] fp32 + bf16-split hidden copy. t=0: h2h = b_ret.
// grid (64, 32, 2), block 256.
// ---------------------------------------------------------------------------
__global__ void gru_k(int t, int first, const float* __restrict__ bret,
                      float* __restrict__ outp)
{
    int pix = blockIdx.x * 256 + threadIdx.x;
    int c2  = blockIdx.y;
    int b   = blockIdx.z;
    int c   = 2 * c2;
    int base = b * 192 * NPIX;

    float h01[2];
    #pragma unroll
    for (int j = 0; j < 2; j++) {
        int cj = c + j;
        float ir = g_i2h[base + (cj      ) * NPIX + pix];
        float iu = g_i2h[base + (cj +  64) * NPIX + pix];
        float im = g_i2h[base + (cj + 128) * NPIX + pix];
        float hr, hu, hm;
        if (first) {
            hr = bret[cj]; hu = bret[cj + 64]; hm = bret[cj + 128];
        } else {
            hr = g_h2h[base + (cj      ) * NPIX + pix];
            hu = g_h2h[base + (cj +  64) * NPIX + pix];
            hm = g_h2h[base + (cj + 128) * NPIX + pix];
        }

        float r = 1.f / (1.f + expf(-(ir + hr)));
        float z = 1.f / (1.f + expf(-(iu + hu)));
        float m = leaky_f(im + r * hm);

        float hp = first ? 0.f : outp[((b * 6 + t - 1) * 64 + cj) * NPIX + pix];
        float h  = z * hp + (1.f - z) * m;
        outp[((b * 6 + t) * 64 + cj) * NPIX + pix] = h;
        h01[j] = h;
    }
    uint32_t hw, lw;
    split2(h01[0], h01[1], hw, lw);
    int p = (b * 32 + c2) * NPIX + pix;
    g_hbf_h[p] = hw; g_hbf_l[p] = lw;
}

// ---------------------------------------------------------------------------
// Launch
// ---------------------------------------------------------------------------
extern "C" void kernel_launch(void* const* d_in, const int* in_sizes, int n_in,
                              void* d_out, int out_size)
{
    const float* x      = (const float*)d_in[0];
    const float* w_stem = (const float*)d_in[1];
    const float* b_stem = (const float*)d_in[2];
    const float* w_i2h  = (const float*)d_in[3];
    const float* b_i2h  = (const float*)d_in[4];
    const float* w_i2f  = (const float*)d_in[5];
    const float* b_i2f  = (const float*)d_in[6];
    const float* w_h2f  = (const float*)d_in[7];
    const float* b_h2f  = (const float*)d_in[8];
    const float* w_flow = (const float*)d_in[9];
    const float* b_flow = (const float*)d_in[10];
    const float* w_ret  = (const float*)d_in[11];
    const float* b_ret  = (const float*)d_in[12];
    float* outp = (float*)d_out;

    cudaFuncSetAttribute(i2h_k,  cudaFuncAttributeMaxDynamicSharedMemorySize, I2H_SMEM_BYTES);
    cudaFuncSetAttribute(f1_k,   cudaFuncAttributeMaxDynamicSharedMemorySize, C5_SMEM_BYTES);
    cudaFuncSetAttribute(flow_k, cudaFuncAttributeMaxDynamicSharedMemorySize, C5_SMEM_BYTES);

    wprep_all_k<<<(199168 + 255) / 256, 256>>>(w_i2h, w_i2f, w_h2f, w_flow, w_ret);

    stem_k<<<dim3(64, 48, 2), 256>>>(x, w_stem, b_stem);

    for (int t = 0; t < 6; t++) {
        int first = (t == 0) ? 1 : 0;
        i2h_k <<<dim3(64, 3, 2), 256, I2H_SMEM_BYTES>>>(t, b_i2h);
        f1_k  <<<dim3(64, 2, 2), 256, C5_SMEM_BYTES>>>(t, first);
        flow_k<<<dim3(64, 1, 2), 256, C5_SMEM_BYTES>>>(b_flow, b_i2f, b_h2f, first);
        if (!first)
            wret_k<<<dim3(128, 2, 2), 256>>>(t, b_ret, outp);
        gru_k <<<dim3(64, 32, 2), 256>>>(t, first, b_ret, outp);
    }
}

// round 14
// speedup vs baseline: 1.2579x; 1.1567x over previous
#include <cuda_runtime.h>
#include <cuda_bf16.h>
#include <math.h>
#include <stdint.h>

#define NPIX 16384            // 128*128

// ---------------------------------------------------------------------------
// Scratch (static device globals)
// ---------------------------------------------------------------------------
__device__ float g_i2h[2 * 192 * NPIX];     // i2h conv out (per step)   25 MB
__device__ float g_h2h[2 * 192 * NPIX];     // ret conv out              25 MB
__device__ float g_f1p[2][2 * 32 * NPIX];   // f1 partial sums (2 src)  8.4 MB
__device__ float g_fl [2 *  26 * NPIX];     // flows                    3.4 MB

// bf16-split packed operands (channel pairs per 32-bit word)
__device__ uint32_t g_ysbf_h[2 * 192 * NPIX], g_ysbf_l[2 * 192 * NPIX]; // stem out (c,c+1)
__device__ uint32_t g_hbf_h [2 *  32 * NPIX], g_hbf_l [2 *  32 * NPIX]; // hprev (c,c+1)

// pre-converted weights: layouts match smem consumption order
__device__ uint32_t g_wi2h_h[3 * 4 * 9 * 8 * 64],  g_wi2h_l[3 * 4 * 9 * 8 * 64];
__device__ uint32_t g_wf1_h [2 * 4 * 25 * 8 * 32], g_wf1_l [2 * 4 * 25 * 8 * 32];
__device__ uint32_t g_wfl_h [2 * 25 * 8 * 32],     g_wfl_l [2 * 25 * 8 * 32];
__device__ uint32_t g_wret_h[2 * 13 * 4 * 8 * 96], g_wret_l[2 * 13 * 4 * 8 * 96];

__device__ __forceinline__ float leaky_f(float x) { return x >= 0.f ? x : 0.2f * x; }

// split two floats into packed bf16 hi-pair and lo-pair (v = hi + lo)
__device__ __forceinline__ void split2(float v0, float v1, uint32_t& h, uint32_t& l) {
    __nv_bfloat162 hb = __floats2bfloat162_rn(v0, v1);
    float h0 = __low2float(hb), h1 = __high2float(hb);
    __nv_bfloat162 lb = __floats2bfloat162_rn(v0 - h0, v1 - h1);
    h = *reinterpret_cast<uint32_t*>(&hb);
    l = *reinterpret_cast<uint32_t*>(&lb);
}

#define MMA_BF16(c0,c1,c2,c3, a0,a1,a2,a3, b0,b1)                              \
    asm volatile("mma.sync.aligned.m16n8k16.row.col.f32.bf16.bf16.f32 "        \
        "{%0,%1,%2,%3}, {%4,%5,%6,%7}, {%8,%9}, {%0,%1,%2,%3};"                \
        : "+f"(c0), "+f"(c1), "+f"(c2), "+f"(c3)                               \
        : "r"(a0), "r"(a1), "r"(a2), "r"(a3), "r"(b0), "r"(b1))

// ---------------------------------------------------------------------------
// Weight prep — all four conversions in ONE kernel (run once per launch)
// ---------------------------------------------------------------------------
__global__ void wprep_all_k(const float* __restrict__ wi2h,
                            const float* __restrict__ wi2f,
                            const float* __restrict__ wh2f,
                            const float* __restrict__ wfl,
                            const float* __restrict__ wret)
{
    int idx = blockIdx.x * 256 + threadIdx.x;

    if (idx < 55296) {
        int oc = idx & 63;
        int kp = (idx >> 6) & 7;
        int q  = idx >> 9;
        int tap = q % 9;
        int qc  = q / 9;
        int chunk = qc & 3, ocg = qc >> 2;
        int ic = chunk * 16 + 2 * kp;
        int o  = ocg * 64 + oc;
        float v0 = wi2h[(o * 64 + ic    ) * 9 + tap];
        float v1 = wi2h[(o * 64 + ic + 1) * 9 + tap];
        split2(v0, v1, g_wi2h_h[idx], g_wi2h_l[idx]);
        return;
    }
    idx -= 55296;
    if (idx < 51200) {
        int oc = idx & 31;
        int kp = (idx >> 5) & 7;
        int q  = idx >> 8;
        int tap = q % 25;
        int qc  = q / 25;
        int chunk = qc & 3, src = qc >> 2;
        int ic = chunk * 16 + 2 * kp;
        const float* w = src ? wh2f : wi2f;
        float v0 = w[(oc * 64 + ic    ) * 25 + tap];
        float v1 = w[(oc * 64 + ic + 1) * 25 + tap];
        split2(v0, v1, g_wf1_h[idx], g_wf1_l[idx]);
        return;
    }
    idx -= 51200;
    if (idx < 12800) {
        int oc = idx & 31;
        int kp = (idx >> 5) & 7;
        int q  = idx >> 8;
        int tap = q % 25;
        int chunk = q / 25;
        int ic = chunk * 16 + 2 * kp;
        float v0 = 0.f, v1 = 0.f;
        if (oc < 26) {
            v0 = wfl[(oc * 32 + ic    ) * 25 + tap];
            v1 = wfl[(oc * 32 + ic + 1) * 25 + tap];
        }
        split2(v0, v1, g_wfl_h[idx], g_wfl_l[idx]);
        return;
    }
    idx -= 12800;
    if (idx < 79872) {
        int m  = idx % 96;
        int kp = (idx / 96) & 7;
        int chunk = (idx / 768) & 3;
        int l  = (idx / 3072) % 13;
        int mb = idx / 39936;
        int k  = l * 64 + chunk * 16 + kp * 2;
        float v0 = wret[(mb * 96 + m) * 832 + k];
        float v1 = wret[(mb * 96 + m) * 832 + k + 1];
        split2(v0, v1, g_wret_h[idx], g_wret_l[idx]);
    }
}

// ---------------------------------------------------------------------------
// Stem: conv 3x3 stride 2 pad 1 -> bf16-split
// ---------------------------------------------------------------------------
__global__ __launch_bounds__(256) void stem_k(const float* __restrict__ x,
                                              const float* __restrict__ w,
                                              const float* __restrict__ bias)
{
    __shared__ __align__(16) float sw[54][8];

    int tid = threadIdx.x;
    int oc0 = blockIdx.y * 8;
    int b   = blockIdx.z;

    for (int i = tid; i < 432; i += 256) {
        int oc = i & 7, tap = i >> 3;
        sw[tap][oc] = w[(oc0 + oc) * 54 + tap];
    }
    __syncthreads();

    int pix = blockIdx.x * 256 + tid;
    int oy = pix >> 7, ox = pix & 127;

    float acc[8];
    #pragma unroll
    for (int j = 0; j < 8; j++) acc[j] = bias[oc0 + j];

    #pragma unroll
    for (int ic = 0; ic < 6; ic++) {
        const float* xb = x + (b * 6 + ic) * 65536;
        float in[9];
        #pragma unroll
        for (int ky = 0; ky < 3; ky++) {
            int iy = 2 * oy - 1 + ky;
            #pragma unroll
            for (int kx = 0; kx < 3; kx++) {
                int ix = 2 * ox - 1 + kx;
                bool ok = (iy >= 0) & (iy <= 255) & (ix >= 0) & (ix <= 255);
                in[ky * 3 + kx] = ok ? __ldg(&xb[iy * 256 + ix]) : 0.f;
            }
        }
        #pragma unroll
        for (int k = 0; k < 9; k++) {
            int tap = ic * 9 + k;
            float a[8];
            *(float4*)&a[0] = *(const float4*)&sw[tap][0];
            *(float4*)&a[4] = *(const float4*)&sw[tap][4];
            #pragma unroll
            for (int j = 0; j < 8; j++) acc[j] += in[k] * a[j];
        }
    }
    #pragma unroll
    for (int j = 0; j < 8; j++) acc[j] = leaky_f(acc[j]);

    int pbase = ((b * 384 + oc0) >> 1) * NPIX + pix;
    #pragma unroll
    for (int j = 0; j < 4; j++) {
        uint32_t h, l;
        split2(acc[2 * j], acc[2 * j + 1], h, l);
        g_ysbf_h[pbase + j * NPIX] = h;
        g_ysbf_l[pbase + j * NPIX] = l;
    }
}

// ---------------------------------------------------------------------------
// i2h role body (conv3x3 64->192): 192 blocks per b. bid = xt*3... see fat_k.
// ---------------------------------------------------------------------------
__device__ __forceinline__ void i2h_body(uint32_t* sm_u, int xt, int ocg, int b,
                                         int t, const float* __restrict__ bias)
{
    uint32_t* s_wh = sm_u;
    uint32_t* s_wl = s_wh + 5184;
    uint32_t* s_xh = s_wl + 5184;
    uint32_t* s_xl = s_xh + 4416;

    int tid = threadIdx.x;
    int lane = tid & 31;
    int g  = lane >> 2;
    int t4 = lane & 3;
    int wid = tid >> 5;
    int wm = wid >> 2;
    int wn = wid & 3;
    int ry = wn >> 1;
    int xoff = (wn & 1) * 64;

    int y0 = xt * 2;
    int m0 = ocg * 64;
    const uint32_t* inh = g_ysbf_h + (b * 192 + t * 32) * NPIX;
    const uint32_t* inl = g_ysbf_l + (b * 192 + t * 32) * NPIX;

    float acc[2][8][4];
    #pragma unroll
    for (int mt = 0; mt < 2; mt++)
        #pragma unroll
        for (int nt = 0; nt < 8; nt++)
            #pragma unroll
            for (int i = 0; i < 4; i++) acc[mt][nt][i] = 0.f;

    for (int chunk = 0; chunk < 4; chunk++) {
        __syncthreads();
        int wbase = (ocg * 4 + chunk) * 4608;
        for (int i = tid; i < 4608; i += 256) {
            int smi = (i >> 6) * 72 + (i & 63);
            s_wh[smi] = g_wi2h_h[wbase + i];
            s_wl[smi] = g_wi2h_l[wbase + i];
        }
        int pbase = chunk * 8;
        for (int i = tid; i < 4160; i += 256) {
            int col = i % 130, r = i / 130;
            int row = r & 3, kp = r >> 2;
            int gy = y0 - 1 + row, gx = col - 1;
            uint32_t vh = 0, vl = 0;
            if (gy >= 0 && gy < 128 && gx >= 0 && gx < 128) {
                int off = (pbase + kp) * NPIX + gy * 128 + gx;
                vh = inh[off]; vl = inl[off];
            }
            int si = kp * 552 + row * 136 + col;
            s_xh[si] = vh; s_xl[si] = vl;
        }
        __syncthreads();

        #pragma unroll
        for (int ky = 0; ky < 3; ky++) {
            #pragma unroll
            for (int kx = 0; kx < 3; kx++) {
                int tap = ky * 3 + kx;
                uint32_t ah[2][4], al[2][4];
                #pragma unroll
                for (int mt = 0; mt < 2; mt++) {
                    int mm = wm * 32 + mt * 16 + g;
                    int r0 = (tap * 8 + t4) * 72, r1 = (tap * 8 + t4 + 4) * 72;
                    ah[mt][0] = s_wh[r0 + mm];     ah[mt][1] = s_wh[r0 + mm + 8];
                    ah[mt][2] = s_wh[r1 + mm];     ah[mt][3] = s_wh[r1 + mm + 8];
                    al[mt][0] = s_wl[r0 + mm];     al[mt][1] = s_wl[r0 + mm + 8];
                    al[mt][2] = s_wl[r1 + mm];     al[mt][3] = s_wl[r1 + mm + 8];
                }
                int base = (ry + ky) * 136 + xoff + kx;
                #pragma unroll
                for (int nt = 0; nt < 8; nt++) {
                    int cc = base + nt * 8 + g;
                    uint32_t bh0 = s_xh[t4 * 552 + cc];
                    uint32_t bh1 = s_xh[(t4 + 4) * 552 + cc];
                    uint32_t bl0 = s_xl[t4 * 552 + cc];
                    uint32_t bl1 = s_xl[(t4 + 4) * 552 + cc];
                    #pragma unroll
                    for (int mt = 0; mt < 2; mt++) {
                        float* c = acc[mt][nt];
                        MMA_BF16(c[0], c[1], c[2], c[3],
                                 al[mt][0], al[mt][1], al[mt][2], al[mt][3], bh0, bh1);
                        MMA_BF16(c[0], c[1], c[2], c[3],
                                 ah[mt][0], ah[mt][1], ah[mt][2], ah[mt][3], bl0, bl1);
                        MMA_BF16(c[0], c[1], c[2], c[3],
                                 ah[mt][0], ah[mt][1], ah[mt][2], ah[mt][3], bh0, bh1);
                    }
                }
            }
        }
    }

    int pix0 = (y0 + ry) * 128 + xoff;
    #pragma unroll
    for (int mt = 0; mt < 2; mt++) {
        int m = m0 + wm * 32 + mt * 16 + g;
        float bb0 = bias[m], bb1 = bias[m + 8];
        float* C0 = &g_i2h[(b * 192 + m    ) * NPIX];
        float* C1 = &g_i2h[(b * 192 + m + 8) * NPIX];
        #pragma unroll
        for (int nt = 0; nt < 8; nt++) {
            int px = pix0 + nt * 8 + t4 * 2;
            *(float2*)&C0[px] = make_float2(acc[mt][nt][0] + bb0, acc[mt][nt][1] + bb0);
            *(float2*)&C1[px] = make_float2(acc[mt][nt][2] + bb1, acc[mt][nt][3] + bb1);
        }
    }
}

// ---------------------------------------------------------------------------
// f1 role body (conv5x5 64->32, one source): 128 blocks per b.
// ---------------------------------------------------------------------------
__device__ __forceinline__ void f1_body(uint32_t* sm_u, int xt, int src, int b, int t)
{
    uint32_t* s_wh = sm_u;             // [5 kx][8 kp][40]
    uint32_t* s_wl = s_wh + 1600;
    uint32_t* s_xh = s_wl + 1600;      // [8 kp][6 rows x 132], kp stride 808
    uint32_t* s_xl = s_xh + 6464;

    int tid = threadIdx.x;
    int lane = tid & 31;
    int g  = lane >> 2;
    int t4 = lane & 3;
    int wid = tid >> 5;
    int rw = wid >> 2;
    int xoff = (wid & 3) * 32;

    int y0 = xt * 2;
    const uint32_t* inh = src ? (g_hbf_h + b * 32 * NPIX) : (g_ysbf_h + (b * 192 + t * 32) * NPIX);
    const uint32_t* inl = src ? (g_hbf_l + b * 32 * NPIX) : (g_ysbf_l + (b * 192 + t * 32) * NPIX);

    float acc[2][4][4];
    #pragma unroll
    for (int mt = 0; mt < 2; mt++)
        #pragma unroll
        for (int nt = 0; nt < 4; nt++)
            #pragma unroll
            for (int i = 0; i < 4; i++) acc[mt][nt][i] = 0.f;

    for (int chunk = 0; chunk < 4; chunk++) {
        __syncthreads();
        int pbase = chunk * 8;
        for (int i = tid; i < 6336; i += 256) {
            int col = i % 132, r = i / 132;
            int row = r % 6, kp = r / 6;
            int gy = y0 - 2 + row, gx = col - 2;
            uint32_t vh = 0, vl = 0;
            if (gy >= 0 && gy < 128 && gx >= 0 && gx < 128) {
                int off = (pbase + kp) * NPIX + gy * 128 + gx;
                vh = inh[off]; vl = inl[off];
            }
            int si = kp * 808 + row * 132 + col;
            s_xh[si] = vh; s_xl[si] = vl;
        }
        #pragma unroll 1
        for (int ky = 0; ky < 5; ky++) {
            if (ky) __syncthreads();
            int wbase = ((src * 4 + chunk) * 25 + ky * 5) * 256;
            {
                int i = tid;
                #pragma unroll
                for (int r = 0; r < 5; r++) {
                    int smi = (i >> 5) * 40 + (i & 31);
                    s_wh[smi] = g_wf1_h[wbase + i];
                    s_wl[smi] = g_wf1_l[wbase + i];
                    i += 256;
                }
            }
            __syncthreads();

            #pragma unroll
            for (int kx = 0; kx < 5; kx++) {
                uint32_t ah[2][4], al[2][4];
                #pragma unroll
                for (int mt = 0; mt < 2; mt++) {
                    int mm = mt * 16 + g;
                    int r0 = (kx * 8 + t4) * 40, r1 = (kx * 8 + t4 + 4) * 40;
                    ah[mt][0] = s_wh[r0 + mm];     ah[mt][1] = s_wh[r0 + mm + 8];
                    ah[mt][2] = s_wh[r1 + mm];     ah[mt][3] = s_wh[r1 + mm + 8];
                    al[mt][0] = s_wl[r0 + mm];     al[mt][1] = s_wl[r0 + mm + 8];
                    al[mt][2] = s_wl[r1 + mm];     al[mt][3] = s_wl[r1 + mm + 8];
                }
                int base = (rw + ky) * 132 + xoff + kx;
                #pragma unroll
                for (int nt = 0; nt < 4; nt++) {
                    int cc = base + nt * 8 + g;
                    uint32_t bh0 = s_xh[t4 * 808 + cc];
                    uint32_t bh1 = s_xh[(t4 + 4) * 808 + cc];
                    uint32_t bl0 = s_xl[t4 * 808 + cc];
                    uint32_t bl1 = s_xl[(t4 + 4) * 808 + cc];
                    #pragma unroll
                    for (int mt = 0; mt < 2; mt++) {
                        float* c = acc[mt][nt];
                        MMA_BF16(c[0], c[1], c[2], c[3],
                                 al[mt][0], al[mt][1], al[mt][2], al[mt][3], bh0, bh1);
                        MMA_BF16(c[0], c[1], c[2], c[3],
                                 ah[mt][0], ah[mt][1], ah[mt][2], ah[mt][3], bl0, bl1);
                        MMA_BF16(c[0], c[1], c[2], c[3],
                                 ah[mt][0], ah[mt][1], ah[mt][2], ah[mt][3], bh0, bh1);
                    }
                }
            }
        }
    }

    float* op = g_f1p[src];
    int pix0 = (y0 + rw) * 128 + xoff;
    #pragma unroll
    for (int mt = 0; mt < 2; mt++) {
        int m = mt * 16 + g;
        float* C0 = &op[(b * 32 + m    ) * NPIX];
        float* C1 = &op[(b * 32 + m + 8) * NPIX];
        #pragma unroll
        for (int nt = 0; nt < 4; nt++) {
            int px = pix0 + nt * 8 + t4 * 2;
            *(float2*)&C0[px] = make_float2(acc[mt][nt][0], acc[mt][nt][1]);
            *(float2*)&C1[px] = make_float2(acc[mt][nt][2], acc[mt][nt][3]);
        }
    }
}

// ---------------------------------------------------------------------------
// fat kernel: i2h (blocks 0..191) + f1 (blocks 192..319) per batch.
// grid (320, 1, 2), dynamic smem 76.8 KB, 2 blocks/SM.
// ---------------------------------------------------------------------------
#define FAT_SMEM_BYTES ((2 * 5184 + 2 * 4416) * 4)
__global__ __launch_bounds__(256, 2) void fat_k(int t, int first,
                                                const float* __restrict__ bias_i2h)
{
    extern __shared__ uint32_t sm_u[];
    int bid = blockIdx.x;
    int b   = blockIdx.z;

    if (bid < 192) {
        i2h_body(sm_u, bid & 63, bid >> 6, b, t, bias_i2h);
    } else {
        int r = bid - 192;
        int src = r >> 6;
        if (first && src) return;
        f1_body(sm_u, r & 63, src, b, t);
    }
}

// ---------------------------------------------------------------------------
// flow: conv5x5 32 -> 26 (padded 32); loader fuses f1 combine.
// grid (64, 1, 2), smem 64.5 KB, 2 blocks/SM.
// ---------------------------------------------------------------------------
#define C5_SMEM_BYTES ((2 * 1600 + 2 * 6464) * 4)
__global__ __launch_bounds__(256, 2) void flow_k(const float* __restrict__ bias,
                                                 const float* __restrict__ bi,
                                                 const float* __restrict__ bh,
                                                 int first)
{
    extern __shared__ uint32_t sm_u[];
    uint32_t* s_wh = sm_u;
    uint32_t* s_wl = s_wh + 1600;
    uint32_t* s_xh = s_wl + 1600;
    uint32_t* s_xl = s_xh + 6464;
    __shared__ float s_cb[32];

    int tid = threadIdx.x;
    int lane = tid & 31;
    int g  = lane >> 2;
    int t4 = lane & 3;
    int wid = tid >> 5;
    int rw = wid >> 2;
    int xoff = (wid & 3) * 32;

    int y0 = blockIdx.x * 2;
    int b  = blockIdx.z;
    if (tid < 32) s_cb[tid] = bi[tid] + bh[tid];

    const float* p0 = g_f1p[0] + b * 32 * NPIX;
    const float* p1 = g_f1p[1] + b * 32 * NPIX;

    float acc[2][4][4];
    #pragma unroll
    for (int mt = 0; mt < 2; mt++)
        #pragma unroll
        for (int nt = 0; nt < 4; nt++)
            #pragma unroll
            for (int i = 0; i < 4; i++) acc[mt][nt][i] = 0.f;

    for (int chunk = 0; chunk < 2; chunk++) {
        __syncthreads();
        int pbase = chunk * 8;
        for (int i = tid; i < 6336; i += 256) {
            int col = i % 132, r = i / 132;
            int row = r % 6, kp = r / 6;
            int gy = y0 - 2 + row, gx = col - 2;
            uint32_t vh = 0, vl = 0;
            if (gy >= 0 && gy < 128 && gx >= 0 && gx < 128) {
                int c0 = 2 * (pbase + kp);
                int off = gy * 128 + gx;
                const float* q0 = p0 + c0 * NPIX;
                float v0 = q0[off], v1 = q0[NPIX + off];
                if (!first) {
                    const float* q1 = p1 + c0 * NPIX;
                    v0 += q1[off]; v1 += q1[NPIX + off];
                }
                v0 = leaky_f(v0 + s_cb[c0]);
                v1 = leaky_f(v1 + s_cb[c0 + 1]);
                split2(v0, v1, vh, vl);
            }
            int si = kp * 808 + row * 132 + col;
            s_xh[si] = vh; s_xl[si] = vl;
        }
        #pragma unroll 1
        for (int ky = 0; ky < 5; ky++) {
            if (ky) __syncthreads();
            int wbase = (chunk * 25 + ky * 5) * 256;
            {
                int i = tid;
                #pragma unroll
                for (int r = 0; r < 5; r++) {
                    int smi = (i >> 5) * 40 + (i & 31);
                    s_wh[smi] = g_wfl_h[wbase + i];
                    s_wl[smi] = g_wfl_l[wbase + i];
                    i += 256;
                }
            }
            __syncthreads();

            #pragma unroll
            for (int kx = 0; kx < 5; kx++) {
                uint32_t ah[2][4], al[2][4];
                #pragma unroll
                for (int mt = 0; mt < 2; mt++) {
                    int mm = mt * 16 + g;
                    int r0 = (kx * 8 + t4) * 40, r1 = (kx * 8 + t4 + 4) * 40;
                    ah[mt][0] = s_wh[r0 + mm];     ah[mt][1] = s_wh[r0 + mm + 8];
                    ah[mt][2] = s_wh[r1 + mm];     ah[mt][3] = s_wh[r1 + mm + 8];
                    al[mt][0] = s_wl[r0 + mm];     al[mt][1] = s_wl[r0 + mm + 8];
                    al[mt][2] = s_wl[r1 + mm];     al[mt][3] = s_wl[r1 + mm + 8];
                }
                int base = (rw + ky) * 132 + xoff + kx;
                #pragma unroll
                for (int nt = 0; nt < 4; nt++) {
                    int cc = base + nt * 8 + g;
                    uint32_t bh0 = s_xh[t4 * 808 + cc];
                    uint32_t bh1 = s_xh[(t4 + 4) * 808 + cc];
                    uint32_t bl0 = s_xl[t4 * 808 + cc];
                    uint32_t bl1 = s_xl[(t4 + 4) * 808 + cc];
                    #pragma unroll
                    for (int mt = 0; mt < 2; mt++) {
                        float* c = acc[mt][nt];
                        MMA_BF16(c[0], c[1], c[2], c[3],
                                 al[mt][0], al[mt][1], al[mt][2], al[mt][3], bh0, bh1);
                        MMA_BF16(c[0], c[1], c[2], c[3],
                                 ah[mt][0], ah[mt][1], ah[mt][2], ah[mt][3], bl0, bl1);
                        MMA_BF16(c[0], c[1], c[2], c[3],
                                 ah[mt][0], ah[mt][1], ah[mt][2], ah[mt][3], bh0, bh1);
                    }
                }
            }
        }
    }

    int pix0 = (y0 + rw) * 128 + xoff;
    #pragma unroll
    for (int mt = 0; mt < 2; mt++) {
        int m = mt * 16 + g;
        #pragma unroll
        for (int nt = 0; nt < 4; nt++) {
            int px = pix0 + nt * 8 + t4 * 2;
            if (m < 26) {
                float bb = bias[m];
                *(float2*)&g_fl[(b * 26 + m) * NPIX + px] =
                    make_float2(acc[mt][nt][0] + bb, acc[mt][nt][1] + bb);
            }
            if (m + 8 < 26) {
                float bb = bias[m + 8];
                *(float2*)&g_fl[(b * 26 + m + 8) * NPIX + px] =
                    make_float2(acc[mt][nt][2] + bb, acc[mt][nt][3] + bb);
            }
        }
    }
}

// ---------------------------------------------------------------------------
// wret: fused warp + ret (t>=1 only). grid (128, 2, 2).  [round-9 config]
// ---------------------------------------------------------------------------
__global__ __launch_bounds__(256, 2) void wret_k(int t, const float* __restrict__ bias,
                                                 const float* __restrict__ outp)
{
    __shared__ int      s_ci[4][128];
    __shared__ float    s_cw[4][128];
    __shared__ uint32_t s_wh[8 * 104], s_wl[8 * 104];
    __shared__ uint32_t s_bh[8 * 136], s_bl[8 * 136];

    int tid = threadIdx.x;
    int lane = tid & 31;
    int g  = lane >> 2;
    int t4 = lane & 3;
    int wid = tid >> 5;
    int wm = wid >> 2;
    int wn = wid & 3;
    int mb = wm * 48;
    int nb = wn * 32;

    int b  = blockIdx.z;
    int n0 = blockIdx.x * 128;
    int mblk = blockIdx.y;
    int m0 = mblk * 96;

    float acc[3][4][4];
    #pragma unroll
    for (int mt = 0; mt < 3; mt++)
        #pragma unroll
        for (int nt = 0; nt < 4; nt++)
            #pragma unroll
            for (int i = 0; i < 4; i++) acc[mt][nt][i] = 0.f;

    const float* hprev = outp + ((b * 6 + (t - 1)) * 64) * NPIX;

    for (int l = 0; l < 13; l++) {
        __syncthreads();
        if (tid < 128) {
            int pg = n0 + tid;
            float u = g_fl[(b * 26 + 2 * l    ) * NPIX + pg];
            float v = g_fl[(b * 26 + 2 * l + 1) * NPIX + pg];
            float sx = (float)(pg & 127) - u;
            float sy = (float)(pg >> 7)  - v;
            float fx = floorf(sx), fy = floorf(sy);
            float wx1 = sx - fx, wx0 = 1.f - wx1;
            float wy1 = sy - fy, wy0 = 1.f - wy1;
            int x0 = (int)fx, y0 = (int)fy;
            int x1 = x0 + 1,  y1 = y0 + 1;
            bool vx0 = (x0 >= 0) & (x0 <= 127);
            bool vx1 = (x1 >= 0) & (x1 <= 127);
            bool vy0 = (y0 >= 0) & (y0 <= 127);
            bool vy1 = (y1 >= 0) & (y1 <= 127);
            int cx0 = min(max(x0, 0), 127), cx1 = min(max(x1, 0), 127);
            int cy0 = min(max(y0, 0), 127), cy1 = min(max(y1, 0), 127);
            s_ci[0][tid] = cy0 * 128 + cx0;
            s_ci[1][tid] = cy0 * 128 + cx1;
            s_ci[2][tid] = cy1 * 128 + cx0;
            s_ci[3][tid] = cy1 * 128 + cx1;
            s_cw[0][tid] = (vx0 && vy0) ? wx0 * wy0 : 0.f;
            s_cw[1][tid] = (vx1 && vy0) ? wx1 * wy0 : 0.f;
            s_cw[2][tid] = (vx0 && vy1) ? wx0 * wy1 : 0.f;
            s_cw[3][tid] = (vx1 && vy1) ? wx1 * wy1 : 0.f;
        }

        for (int chunk = 0; chunk < 4; chunk++) {
            __syncthreads();
            int wbase = ((mblk * 13 + l) * 4 + chunk) * 768;
            #pragma unroll
            for (int r = 0; r < 3; r++) {
                int i = tid + r * 256;
                int smi = (i / 96) * 104 + (i % 96);
                s_wh[smi] = g_wret_h[wbase + i];
                s_wl[smi] = g_wret_l[wbase + i];
            }
            #pragma unroll
            for (int r = 0; r < 4; r++) {
                int j = tid + r * 256;
                int kp = j >> 7, px = j & 127;
                int i00 = s_ci[0][px], i10 = s_ci[1][px];
                int i01 = s_ci[2][px], i11 = s_ci[3][px];
                float w00 = s_cw[0][px], w10 = s_cw[1][px];
                float w01 = s_cw[2][px], w11 = s_cw[3][px];
                const float* h0 = hprev + (chunk * 16 + kp * 2) * NPIX;
                const float* h1 = h0 + NPIX;
                float v0 = w00 * __ldg(&h0[i00]) + w10 * __ldg(&h0[i10])
                         + w01 * __ldg(&h0[i01]) + w11 * __ldg(&h0[i11]);
                float v1 = w00 * __ldg(&h1[i00]) + w10 * __ldg(&h1[i10])
                         + w01 * __ldg(&h1[i01]) + w11 * __ldg(&h1[i11]);
                uint32_t hh, ll;
                split2(v0, v1, hh, ll);
                s_bh[kp * 136 + px] = hh;
                s_bl[kp * 136 + px] = ll;
            }
            __syncthreads();

            uint32_t ah[3][4], al[3][4], bh[4][2], bl[4][2];
            #pragma unroll
            for (int mt = 0; mt < 3; mt++) {
                int mm = mb + mt * 16 + g;
                int r0 = t4 * 104, r1 = (t4 + 4) * 104;
                ah[mt][0] = s_wh[r0 + mm];     ah[mt][1] = s_wh[r0 + mm + 8];
                ah[mt][2] = s_wh[r1 + mm];     ah[mt][3] = s_wh[r1 + mm + 8];
                al[mt][0] = s_wl[r0 + mm];     al[mt][1] = s_wl[r0 + mm + 8];
                al[mt][2] = s_wl[r1 + mm];     al[mt][3] = s_wl[r1 + mm + 8];
            }
            #pragma unroll
            for (int nt = 0; nt < 4; nt++) {
                int nn = nb + nt * 8 + g;
                bh[nt][0] = s_bh[t4 * 136 + nn];
                bh[nt][1] = s_bh[(t4 + 4) * 136 + nn];
                bl[nt][0] = s_bl[t4 * 136 + nn];
                bl[nt][1] = s_bl[(t4 + 4) * 136 + nn];
            }
            #pragma unroll
            for (int mt = 0; mt < 3; mt++)
                #pragma unroll
                for (int nt = 0; nt < 4; nt++) {
                    float* c = acc[mt][nt];
                    MMA_BF16(c[0], c[1], c[2], c[3],
                             al[mt][0], al[mt][1], al[mt][2], al[mt][3],
                             bh[nt][0], bh[nt][1]);
                    MMA_BF16(c[0], c[1], c[2], c[3],
                             ah[mt][0], ah[mt][1], ah[mt][2], ah[mt][3],
                             bl[nt][0], bl[nt][1]);
                    MMA_BF16(c[0], c[1], c[2], c[3],
                             ah[mt][0], ah[mt][1], ah[mt][2], ah[mt][3],
                             bh[nt][0], bh[nt][1]);
                }
        }
    }

    float* C = g_h2h + b * 192 * NPIX;
    #pragma unroll
    for (int mt = 0; mt < 3; mt++) {
        int m = m0 + mb + mt * 16 + g;
        float bb0 = bias[m], bb1 = bias[m + 8];
        #pragma unroll
        for (int nt = 0; nt < 4; nt++) {
            int col = n0 + nb + nt * 8 + t4 * 2;
            float2 o0 = make_float2(acc[mt][nt][0] + bb0, acc[mt][nt][1] + bb0);
            float2 o1 = make_float2(acc[mt][nt][2] + bb1, acc[mt][nt][3] + bb1);
            *(float2*)&C[m * NPIX + col]       = o0;
            *(float2*)&C[(m + 8) * NPIX + col] = o1;
        }
    }
}

// ---------------------------------------------------------------------------
// GRU update: out[b,t] fp32 + bf16-split hidden copy. t=0: h2h = b_ret.
// grid (64, 32, 2), block 256.
// ---------------------------------------------------------------------------
__global__ void gru_k(int t, int first, const float* __restrict__ bret,
                      float* __restrict__ outp)
{
    int pix = blockIdx.x * 256 + threadIdx.x;
    int c2  = blockIdx.y;
    int b   = blockIdx.z;
    int c   = 2 * c2;
    int base = b * 192 * NPIX;

    float h01[2];
    #pragma unroll
    for (int j = 0; j < 2; j++) {
        int cj = c + j;
        float ir = g_i2h[base + (cj      ) * NPIX + pix];
        float iu = g_i2h[base + (cj +  64) * NPIX + pix];
        float im = g_i2h[base + (cj + 128) * NPIX + pix];
        float hr, hu, hm;
        if (first) {
            hr = bret[cj]; hu = bret[cj + 64]; hm = bret[cj + 128];
        } else {
            hr = g_h2h[base + (cj      ) * NPIX + pix];
            hu = g_h2h[base + (cj +  64) * NPIX + pix];
            hm = g_h2h[base + (cj + 128) * NPIX + pix];
        }

        float r = 1.f / (1.f + expf(-(ir + hr)));
        float z = 1.f / (1.f + expf(-(iu + hu)));
        float m = leaky_f(im + r * hm);

        float hp = first ? 0.f : outp[((b * 6 + t - 1) * 64 + cj) * NPIX + pix];
        float h  = z * hp + (1.f - z) * m;
        outp[((b * 6 + t) * 64 + cj) * NPIX + pix] = h;
        h01[j] = h;
    }
    uint32_t hw, lw;
    split2(h01[0], h01[1], hw, lw);
    int p = (b * 32 + c2) * NPIX + pix;
    g_hbf_h[p] = hw; g_hbf_l[p] = lw;
}

// ---------------------------------------------------------------------------
// Launch
// ---------------------------------------------------------------------------
extern "C" void kernel_launch(void* const* d_in, const int* in_sizes, int n_in,
                              void* d_out, int out_size)
{
    const float* x      = (const float*)d_in[0];
    const float* w_stem = (const float*)d_in[1];
    const float* b_stem = (const float*)d_in[2];
    const float* w_i2h  = (const float*)d_in[3];
    const float* b_i2h  = (const float*)d_in[4];
    const float* w_i2f  = (const float*)d_in[5];
    const float* b_i2f  = (const float*)d_in[6];
    const float* w_h2f  = (const float*)d_in[7];
    const float* b_h2f  = (const float*)d_in[8];
    const float* w_flow = (const float*)d_in[9];
    const float* b_flow = (const float*)d_in[10];
    const float* w_ret  = (const float*)d_in[11];
    const float* b_ret  = (const float*)d_in[12];
    float* outp = (float*)d_out;

    cudaFuncSetAttribute(fat_k,  cudaFuncAttributeMaxDynamicSharedMemorySize, FAT_SMEM_BYTES);
    cudaFuncSetAttribute(flow_k, cudaFuncAttributeMaxDynamicSharedMemorySize, C5_SMEM_BYTES);

    wprep_all_k<<<(199168 + 255) / 256, 256>>>(w_i2h, w_i2f, w_h2f, w_flow, w_ret);

    stem_k<<<dim3(64, 48, 2), 256>>>(x, w_stem, b_stem);

    for (int t = 0; t < 6; t++) {
        int first = (t == 0) ? 1 : 0;
        fat_k <<<dim3(320, 1, 2), 256, FAT_SMEM_BYTES>>>(t, first, b_i2h);
        flow_k<<<dim3(64, 1, 2), 256, C5_SMEM_BYTES>>>(b_flow, b_i2f, b_h2f, first);
        if (!first)
            wret_k<<<dim3(128, 2, 2), 256>>>(t, b_ret, outp);
        gru_k <<<dim3(64, 32, 2), 256>>>(t, first, b_ret, outp);
    }
}

// round 15
// speedup vs baseline: 1.2729x; 1.0119x over previous
#include <cuda_runtime.h>
#include <cuda_bf16.h>
#include <math.h>
#include <stdint.h>

#define NPIX 16384            // 128*128

// ---------------------------------------------------------------------------
// Scratch (static device globals)
// ---------------------------------------------------------------------------
__device__ float g_i2h[2 * 192 * NPIX];     // i2h conv out (per step)   25 MB
__device__ float g_h2h[2 * 192 * NPIX];     // ret conv out              25 MB
__device__ float g_f1p[2][2 * 32 * NPIX];   // f1 partial sums (2 src)  8.4 MB
__device__ float g_fl [2 *  26 * NPIX];     // flows                    3.4 MB

// bf16-split packed operands (channel pairs per 32-bit word)
__device__ uint32_t g_ysbf_h[2 * 192 * NPIX], g_ysbf_l[2 * 192 * NPIX]; // stem out (c,c+1)
__device__ uint32_t g_hbf_h [2 *  32 * NPIX], g_hbf_l [2 *  32 * NPIX]; // hprev (c,c+1)

// pre-converted weights: layouts match smem consumption order
__device__ uint32_t g_wi2h_h[3 * 4 * 9 * 8 * 64],  g_wi2h_l[3 * 4 * 9 * 8 * 64];
__device__ uint32_t g_wf1_h [2 * 4 * 25 * 8 * 32], g_wf1_l [2 * 4 * 25 * 8 * 32];
__device__ uint32_t g_wfl_h [2 * 25 * 8 * 32],     g_wfl_l [2 * 25 * 8 * 32];
__device__ uint32_t g_wret_h[2 * 13 * 4 * 8 * 96], g_wret_l[2 * 13 * 4 * 8 * 96];

__device__ __forceinline__ float leaky_f(float x) { return x >= 0.f ? x : 0.2f * x; }

// split two floats into packed bf16 hi-pair and lo-pair (v = hi + lo)
__device__ __forceinline__ void split2(float v0, float v1, uint32_t& h, uint32_t& l) {
    __nv_bfloat162 hb = __floats2bfloat162_rn(v0, v1);
    float h0 = __low2float(hb), h1 = __high2float(hb);
    __nv_bfloat162 lb = __floats2bfloat162_rn(v0 - h0, v1 - h1);
    h = *reinterpret_cast<uint32_t*>(&hb);
    l = *reinterpret_cast<uint32_t*>(&lb);
}

#define MMA_BF16(c0,c1,c2,c3, a0,a1,a2,a3, b0,b1)                              \
    asm volatile("mma.sync.aligned.m16n8k16.row.col.f32.bf16.bf16.f32 "        \
        "{%0,%1,%2,%3}, {%4,%5,%6,%7}, {%8,%9}, {%0,%1,%2,%3};"                \
        : "+f"(c0), "+f"(c1), "+f"(c2), "+f"(c3)                               \
        : "r"(a0), "r"(a1), "r"(a2), "r"(a3), "r"(b0), "r"(b1))

__device__ __forceinline__ void cpa4(uint32_t dst, const void* src, bool ok) {
    asm volatile("cp.async.ca.shared.global [%0], [%1], 4, %2;"
                 :: "r"(dst), "l"(src), "r"(ok ? 4 : 0));
}

// ---------------------------------------------------------------------------
// Weight prep — all four conversions in ONE kernel (run once per launch)
// ---------------------------------------------------------------------------
__global__ void wprep_all_k(const float* __restrict__ wi2h,
                            const float* __restrict__ wi2f,
                            const float* __restrict__ wh2f,
                            const float* __restrict__ wfl,
                            const float* __restrict__ wret)
{
    int idx = blockIdx.x * 256 + threadIdx.x;

    if (idx < 55296) {
        int oc = idx & 63;
        int kp = (idx >> 6) & 7;
        int q  = idx >> 9;
        int tap = q % 9;
        int qc  = q / 9;
        int chunk = qc & 3, ocg = qc >> 2;
        int ic = chunk * 16 + 2 * kp;
        int o  = ocg * 64 + oc;
        float v0 = wi2h[(o * 64 + ic    ) * 9 + tap];
        float v1 = wi2h[(o * 64 + ic + 1) * 9 + tap];
        split2(v0, v1, g_wi2h_h[idx], g_wi2h_l[idx]);
        return;
    }
    idx -= 55296;
    if (idx < 51200) {
        int oc = idx & 31;
        int kp = (idx >> 5) & 7;
        int q  = idx >> 8;
        int tap = q % 25;
        int qc  = q / 25;
        int chunk = qc & 3, src = qc >> 2;
        int ic = chunk * 16 + 2 * kp;
        const float* w = src ? wh2f : wi2f;
        float v0 = w[(oc * 64 + ic    ) * 25 + tap];
        float v1 = w[(oc * 64 + ic + 1) * 25 + tap];
        split2(v0, v1, g_wf1_h[idx], g_wf1_l[idx]);
        return;
    }
    idx -= 51200;
    if (idx < 12800) {
        int oc = idx & 31;
        int kp = (idx >> 5) & 7;
        int q  = idx >> 8;
        int tap = q % 25;
        int chunk = q / 25;
        int ic = chunk * 16 + 2 * kp;
        float v0 = 0.f, v1 = 0.f;
        if (oc < 26) {
            v0 = wfl[(oc * 32 + ic    ) * 25 + tap];
            v1 = wfl[(oc * 32 + ic + 1) * 25 + tap];
        }
        split2(v0, v1, g_wfl_h[idx], g_wfl_l[idx]);
        return;
    }
    idx -= 12800;
    if (idx < 79872) {
        int m  = idx % 96;
        int kp = (idx / 96) & 7;
        int chunk = (idx / 768) & 3;
        int l  = (idx / 3072) % 13;
        int mb = idx / 39936;
        int k  = l * 64 + chunk * 16 + kp * 2;
        float v0 = wret[(mb * 96 + m) * 832 + k];
        float v1 = wret[(mb * 96 + m) * 832 + k + 1];
        split2(v0, v1, g_wret_h[idx], g_wret_l[idx]);
    }
}

// ---------------------------------------------------------------------------
// Stem: conv 3x3 stride 2 pad 1 -> bf16-split
// ---------------------------------------------------------------------------
__global__ __launch_bounds__(256) void stem_k(const float* __restrict__ x,
                                              const float* __restrict__ w,
                                              const float* __restrict__ bias)
{
    __shared__ __align__(16) float sw[54][8];

    int tid = threadIdx.x;
    int oc0 = blockIdx.y * 8;
    int b   = blockIdx.z;

    for (int i = tid; i < 432; i += 256) {
        int oc = i & 7, tap = i >> 3;
        sw[tap][oc] = w[(oc0 + oc) * 54 + tap];
    }
    __syncthreads();

    int pix = blockIdx.x * 256 + tid;
    int oy = pix >> 7, ox = pix & 127;

    float acc[8];
    #pragma unroll
    for (int j = 0; j < 8; j++) acc[j] = bias[oc0 + j];

    #pragma unroll
    for (int ic = 0; ic < 6; ic++) {
        const float* xb = x + (b * 6 + ic) * 65536;
        float in[9];
        #pragma unroll
        for (int ky = 0; ky < 3; ky++) {
            int iy = 2 * oy - 1 + ky;
            #pragma unroll
            for (int kx = 0; kx < 3; kx++) {
                int ix = 2 * ox - 1 + kx;
                bool ok = (iy >= 0) & (iy <= 255) & (ix >= 0) & (ix <= 255);
                in[ky * 3 + kx] = ok ? __ldg(&xb[iy * 256 + ix]) : 0.f;
            }
        }
        #pragma unroll
        for (int k = 0; k < 9; k++) {
            int tap = ic * 9 + k;
            float a[8];
            *(float4*)&a[0] = *(const float4*)&sw[tap][0];
            *(float4*)&a[4] = *(const float4*)&sw[tap][4];
            #pragma unroll
            for (int j = 0; j < 8; j++) acc[j] += in[k] * a[j];
        }
    }
    #pragma unroll
    for (int j = 0; j < 8; j++) acc[j] = leaky_f(acc[j]);

    int pbase = ((b * 384 + oc0) >> 1) * NPIX + pix;
    #pragma unroll
    for (int j = 0; j < 4; j++) {
        uint32_t h, l;
        split2(acc[2 * j], acc[2 * j + 1], h, l);
        g_ysbf_h[pbase + j * NPIX] = h;
        g_ysbf_l[pbase + j * NPIX] = l;
    }
}

// ---------------------------------------------------------------------------
// i2h role body (conv3x3 64->192), cp.async double-buffered input pipeline.
// smem: weights 2x5184 + input 2 bufs x 2 (h,l) x 4416 = 28032 words (112.1KB)
// ---------------------------------------------------------------------------
__device__ __forceinline__ void i2h_body(uint32_t* sm_u, int xt, int ocg, int b,
                                         int t, const float* __restrict__ bias)
{
    uint32_t* s_wh = sm_u;
    uint32_t* s_wl = s_wh + 5184;
    uint32_t* s_x  = s_wl + 5184;      // [buf2][hl2][4416]

    int tid = threadIdx.x;
    int lane = tid & 31;
    int g  = lane >> 2;
    int t4 = lane & 3;
    int wid = tid >> 5;
    int wm = wid >> 2;
    int wn = wid & 3;
    int ry = wn >> 1;
    int xoff = (wn & 1) * 64;

    int y0 = xt * 2;
    int m0 = ocg * 64;
    const uint32_t* inh = g_ysbf_h + (b * 192 + t * 32) * NPIX;
    const uint32_t* inl = g_ysbf_l + (b * 192 + t * 32) * NPIX;

    float acc[2][8][4];
    #pragma unroll
    for (int mt = 0; mt < 2; mt++)
        #pragma unroll
        for (int nt = 0; nt < 8; nt++)
            #pragma unroll
            for (int i = 0; i < 4; i++) acc[mt][nt][i] = 0.f;

    // async input loader: chunk -> buffer buf
    auto load_input_async = [&](int chunk, int buf) {
        int pbase = chunk * 8;
        uint32_t* xh = s_x + (buf * 2    ) * 4416;
        uint32_t* xl = s_x + (buf * 2 + 1) * 4416;
        for (int i = tid; i < 4160; i += 256) {
            int col = i % 130, r = i / 130;
            int row = r & 3, kp = r >> 2;
            int gy = y0 - 1 + row, gx = col - 1;
            bool ok = (gy >= 0) & (gy < 128) & (gx >= 0) & (gx < 128);
            int off = (pbase + kp) * NPIX + gy * 128 + gx;
            int si = kp * 552 + row * 136 + col;
            cpa4((uint32_t)__cvta_generic_to_shared(&xh[si]), &inh[off], ok);
            cpa4((uint32_t)__cvta_generic_to_shared(&xl[si]), &inl[off], ok);
        }
        asm volatile("cp.async.commit_group;");
    };

    load_input_async(0, 0);

    for (int chunk = 0; chunk < 4; chunk++) {
        __syncthreads();               // prior compute done: weights + old buf reusable
        int wbase = (ocg * 4 + chunk) * 4608;
        for (int i = tid; i < 4608; i += 256) {
            int smi = (i >> 6) * 72 + (i & 63);
            s_wh[smi] = g_wi2h_h[wbase + i];
            s_wl[smi] = g_wi2h_l[wbase + i];
        }
        if (chunk < 3) {
            load_input_async(chunk + 1, (chunk + 1) & 1);
            asm volatile("cp.async.wait_group 1;");
        } else {
            asm volatile("cp.async.wait_group 0;");
        }
        __syncthreads();

        uint32_t* s_xh = s_x + ((chunk & 1) * 2    ) * 4416;
        uint32_t* s_xl = s_x + ((chunk & 1) * 2 + 1) * 4416;

        #pragma unroll
        for (int ky = 0; ky < 3; ky++) {
            #pragma unroll
            for (int kx = 0; kx < 3; kx++) {
                int tap = ky * 3 + kx;
                uint32_t ah[2][4], al[2][4];
                #pragma unroll
                for (int mt = 0; mt < 2; mt++) {
                    int mm = wm * 32 + mt * 16 + g;
                    int r0 = (tap * 8 + t4) * 72, r1 = (tap * 8 + t4 + 4) * 72;
                    ah[mt][0] = s_wh[r0 + mm];     ah[mt][1] = s_wh[r0 + mm + 8];
                    ah[mt][2] = s_wh[r1 + mm];     ah[mt][3] = s_wh[r1 + mm + 8];
                    al[mt][0] = s_wl[r0 + mm];     al[mt][1] = s_wl[r0 + mm + 8];
                    al[mt][2] = s_wl[r1 + mm];     al[mt][3] = s_wl[r1 + mm + 8];
                }
                int base = (ry + ky) * 136 + xoff + kx;
                #pragma unroll
                for (int nt = 0; nt < 8; nt++) {
                    int cc = base + nt * 8 + g;
                    uint32_t bh0 = s_xh[t4 * 552 + cc];
                    uint32_t bh1 = s_xh[(t4 + 4) * 552 + cc];
                    uint32_t bl0 = s_xl[t4 * 552 + cc];
                    uint32_t bl1 = s_xl[(t4 + 4) * 552 + cc];
                    #pragma unroll
                    for (int mt = 0; mt < 2; mt++) {
                        float* c = acc[mt][nt];
                        MMA_BF16(c[0], c[1], c[2], c[3],
                                 al[mt][0], al[mt][1], al[mt][2], al[mt][3], bh0, bh1);
                        MMA_BF16(c[0], c[1], c[2], c[3],
                                 ah[mt][0], ah[mt][1], ah[mt][2], ah[mt][3], bl0, bl1);
                        MMA_BF16(c[0], c[1], c[2], c[3],
                                 ah[mt][0], ah[mt][1], ah[mt][2], ah[mt][3], bh0, bh1);
                    }
                }
            }
        }
    }

    int pix0 = (y0 + ry) * 128 + xoff;
    #pragma unroll
    for (int mt = 0; mt < 2; mt++) {
        int m = m0 + wm * 32 + mt * 16 + g;
        float bb0 = bias[m], bb1 = bias[m + 8];
        float* C0 = &g_i2h[(b * 192 + m    ) * NPIX];
        float* C1 = &g_i2h[(b * 192 + m + 8) * NPIX];
        #pragma unroll
        for (int nt = 0; nt < 8; nt++) {
            int px = pix0 + nt * 8 + t4 * 2;
            *(float2*)&C0[px] = make_float2(acc[mt][nt][0] + bb0, acc[mt][nt][1] + bb0);
            *(float2*)&C1[px] = make_float2(acc[mt][nt][2] + bb1, acc[mt][nt][3] + bb1);
        }
    }
}

// ---------------------------------------------------------------------------
// f1 role body (conv5x5 64->32, one source): 128 blocks per b. [unchanged]
// ---------------------------------------------------------------------------
__device__ __forceinline__ void f1_body(uint32_t* sm_u, int xt, int src, int b, int t)
{
    uint32_t* s_wh = sm_u;             // [5 kx][8 kp][40]
    uint32_t* s_wl = s_wh + 1600;
    uint32_t* s_xh = s_wl + 1600;      // [8 kp][6 rows x 132], kp stride 808
    uint32_t* s_xl = s_xh + 6464;

    int tid = threadIdx.x;
    int lane = tid & 31;
    int g  = lane >> 2;
    int t4 = lane & 3;
    int wid = tid >> 5;
    int rw = wid >> 2;
    int xoff = (wid & 3) * 32;

    int y0 = xt * 2;
    const uint32_t* inh = src ? (g_hbf_h + b * 32 * NPIX) : (g_ysbf_h + (b * 192 + t * 32) * NPIX);
    const uint32_t* inl = src ? (g_hbf_l + b * 32 * NPIX) : (g_ysbf_l + (b * 192 + t * 32) * NPIX);

    float acc[2][4][4];
    #pragma unroll
    for (int mt = 0; mt < 2; mt++)
        #pragma unroll
        for (int nt = 0; nt < 4; nt++)
            #pragma unroll
            for (int i = 0; i < 4; i++) acc[mt][nt][i] = 0.f;

    for (int chunk = 0; chunk < 4; chunk++) {
        __syncthreads();
        int pbase = chunk * 8;
        for (int i = tid; i < 6336; i += 256) {
            int col = i % 132, r = i / 132;
            int row = r % 6, kp = r / 6;
            int gy = y0 - 2 + row, gx = col - 2;
            uint32_t vh = 0, vl = 0;
            if (gy >= 0 && gy < 128 && gx >= 0 && gx < 128) {
                int off = (pbase + kp) * NPIX + gy * 128 + gx;
                vh = inh[off]; vl = inl[off];
            }
            int si = kp * 808 + row * 132 + col;
            s_xh[si] = vh; s_xl[si] = vl;
        }
        #pragma unroll 1
        for (int ky = 0; ky < 5; ky++) {
            if (ky) __syncthreads();
            int wbase = ((src * 4 + chunk) * 25 + ky * 5) * 256;
            {
                int i = tid;
                #pragma unroll
                for (int r = 0; r < 5; r++) {
                    int smi = (i >> 5) * 40 + (i & 31);
                    s_wh[smi] = g_wf1_h[wbase + i];
                    s_wl[smi] = g_wf1_l[wbase + i];
                    i += 256;
                }
            }
            __syncthreads();

            #pragma unroll
            for (int kx = 0; kx < 5; kx++) {
                uint32_t ah[2][4], al[2][4];
                #pragma unroll
                for (int mt = 0; mt < 2; mt++) {
                    int mm = mt * 16 + g;
                    int r0 = (kx * 8 + t4) * 40, r1 = (kx * 8 + t4 + 4) * 40;
                    ah[mt][0] = s_wh[r0 + mm];     ah[mt][1] = s_wh[r0 + mm + 8];
                    ah[mt][2] = s_wh[r1 + mm];     ah[mt][3] = s_wh[r1 + mm + 8];
                    al[mt][0] = s_wl[r0 + mm];     al[mt][1] = s_wl[r0 + mm + 8];
                    al[mt][2] = s_wl[r1 + mm];     al[mt][3] = s_wl[r1 + mm + 8];
                }
                int base = (rw + ky) * 132 + xoff + kx;
                #pragma unroll
                for (int nt = 0; nt < 4; nt++) {
                    int cc = base + nt * 8 + g;
                    uint32_t bh0 = s_xh[t4 * 808 + cc];
                    uint32_t bh1 = s_xh[(t4 + 4) * 808 + cc];
                    uint32_t bl0 = s_xl[t4 * 808 + cc];
                    uint32_t bl1 = s_xl[(t4 + 4) * 808 + cc];
                    #pragma unroll
                    for (int mt = 0; mt < 2; mt++) {
                        float* c = acc[mt][nt];
                        MMA_BF16(c[0], c[1], c[2], c[3],
                                 al[mt][0], al[mt][1], al[mt][2], al[mt][3], bh0, bh1);
                        MMA_BF16(c[0], c[1], c[2], c[3],
                                 ah[mt][0], ah[mt][1], ah[mt][2], ah[mt][3], bl0, bl1);
                        MMA_BF16(c[0], c[1], c[2], c[3],
                                 ah[mt][0], ah[mt][1], ah[mt][2], ah[mt][3], bh0, bh1);
                    }
                }
            }
        }
    }

    float* op = g_f1p[src];
    int pix0 = (y0 + rw) * 128 + xoff;
    #pragma unroll
    for (int mt = 0; mt < 2; mt++) {
        int m = mt * 16 + g;
        float* C0 = &op[(b * 32 + m    ) * NPIX];
        float* C1 = &op[(b * 32 + m + 8) * NPIX];
        #pragma unroll
        for (int nt = 0; nt < 4; nt++) {
            int px = pix0 + nt * 8 + t4 * 2;
            *(float2*)&C0[px] = make_float2(acc[mt][nt][0], acc[mt][nt][1]);
            *(float2*)&C1[px] = make_float2(acc[mt][nt][2], acc[mt][nt][3]);
        }
    }
}

// ---------------------------------------------------------------------------
// fat kernel: i2h (blocks 0..191) + f1 (blocks 192..319) per batch.
// grid (320, 1, 2), dynamic smem 112.1 KB, 2 blocks/SM.
// ---------------------------------------------------------------------------
#define FAT_SMEM_BYTES ((2 * 5184 + 4 * 4416) * 4)
__global__ __launch_bounds__(256, 2) void fat_k(int t, int first,
                                                const float* __restrict__ bias_i2h)
{
    extern __shared__ uint32_t sm_u[];
    int bid = blockIdx.x;
    int b   = blockIdx.z;

    if (bid < 192) {
        i2h_body(sm_u, bid & 63, bid >> 6, b, t, bias_i2h);
    } else {
        int r = bid - 192;
        int src = r >> 6;
        if (first && src) return;
        f1_body(sm_u, r & 63, src, b, t);
    }
}

// ---------------------------------------------------------------------------
// flow: conv5x5 32 -> 26 (padded 32); loader fuses f1 combine.
// 1-ROW tiles: grid (128, 1, 2) = 256 blocks (was 128). Warp = 32oc x 16px.
// smem: weights 2x1600 + input 2 x (8 kp x 680) = 56.3 KB, 2 blocks/SM.
// ---------------------------------------------------------------------------
#define FLOW_SMEM_BYTES ((2 * 1600 + 2 * 5440) * 4)
__global__ __launch_bounds__(256, 2) void flow_k(const float* __restrict__ bias,
                                                 const float* __restrict__ bi,
                                                 const float* __restrict__ bh,
                                                 int first)
{
    extern __shared__ uint32_t sm_u[];
    uint32_t* s_wh = sm_u;
    uint32_t* s_wl = s_wh + 1600;
    uint32_t* s_xh = s_wl + 1600;      // [8 kp][5 rows x 132], kp stride 680
    uint32_t* s_xl = s_xh + 5440;
    __shared__ float s_cb[32];

    int tid = threadIdx.x;
    int lane = tid & 31;
    int g  = lane >> 2;
    int t4 = lane & 3;
    int wid = tid >> 5;
    int xoff = wid * 16;

    int y0 = blockIdx.x;               // single output row
    int b  = blockIdx.z;
    if (tid < 32) s_cb[tid] = bi[tid] + bh[tid];

    const float* p0 = g_f1p[0] + b * 32 * NPIX;
    const float* p1 = g_f1p[1] + b * 32 * NPIX;

    float acc[2][2][4];
    #pragma unroll
    for (int mt = 0; mt < 2; mt++)
        #pragma unroll
        for (int nt = 0; nt < 2; nt++)
            #pragma unroll
            for (int i = 0; i < 4; i++) acc[mt][nt][i] = 0.f;

    for (int chunk = 0; chunk < 2; chunk++) {
        __syncthreads();
        int pbase = chunk * 8;
        for (int i = tid; i < 5280; i += 256) {      // 8 kp x 5 rows x 132
            int col = i % 132, r = i / 132;
            int row = r % 5, kp = r / 5;
            int gy = y0 - 2 + row, gx = col - 2;
            uint32_t vh = 0, vl = 0;
            if (gy >= 0 && gy < 128 && gx >= 0 && gx < 128) {
                int c0 = 2 * (pbase + kp);
                int off = gy * 128 + gx;
                const float* q0 = p0 + c0 * NPIX;
                float v0 = q0[off], v1 = q0[NPIX + off];
                if (!first) {
                    const float* q1 = p1 + c0 * NPIX;
                    v0 += q1[off]; v1 += q1[NPIX + off];
                }
                v0 = leaky_f(v0 + s_cb[c0]);
                v1 = leaky_f(v1 + s_cb[c0 + 1]);
                split2(v0, v1, vh, vl);
            }
            int si = kp * 680 + row * 132 + col;
            s_xh[si] = vh; s_xl[si] = vl;
        }
        #pragma unroll 1
        for (int ky = 0; ky < 5; ky++) {
            if (ky) __syncthreads();
            int wbase = (chunk * 25 + ky * 5) * 256;
            {
                int i = tid;
                #pragma unroll
                for (int r = 0; r < 5; r++) {
                    int smi = (i >> 5) * 40 + (i & 31);
                    s_wh[smi] = g_wfl_h[wbase + i];
                    s_wl[smi] = g_wfl_l[wbase + i];
                    i += 256;
                }
            }
            __syncthreads();

            #pragma unroll
            for (int kx = 0; kx < 5; kx++) {
                uint32_t ah[2][4], al[2][4];
                #pragma unroll
                for (int mt = 0; mt < 2; mt++) {
                    int mm = mt * 16 + g;
                    int r0 = (kx * 8 + t4) * 40, r1 = (kx * 8 + t4 + 4) * 40;
                    ah[mt][0] = s_wh[r0 + mm];     ah[mt][1] = s_wh[r0 + mm + 8];
                    ah[mt][2] = s_wh[r1 + mm];     ah[mt][3] = s_wh[r1 + mm + 8];
                    al[mt][0] = s_wl[r0 + mm];     al[mt][1] = s_wl[r0 + mm + 8];
                    al[mt][2] = s_wl[r1 + mm];     al[mt][3] = s_wl[r1 + mm + 8];
                }
                int base = ky * 132 + xoff + kx;
                #pragma unroll
                for (int nt = 0; nt < 2; nt++) {
                    int cc = base + nt * 8 + g;
                    uint32_t bh0 = s_xh[t4 * 680 + cc];
                    uint32_t bh1 = s_xh[(t4 + 4) * 680 + cc];
                    uint32_t bl0 = s_xl[t4 * 680 + cc];
                    uint32_t bl1 = s_xl[(t4 + 4) * 680 + cc];
                    #pragma unroll
                    for (int mt = 0; mt < 2; mt++) {
                        float* c = acc[mt][nt];
                        MMA_BF16(c[0], c[1], c[2], c[3],
                                 al[mt][0], al[mt][1], al[mt][2], al[mt][3], bh0, bh1);
                        MMA_BF16(c[0], c[1], c[2], c[3],
                                 ah[mt][0], ah[mt][1], ah[mt][2], ah[mt][3], bl0, bl1);
                        MMA_BF16(c[0], c[1], c[2], c[3],
                                 ah[mt][0], ah[mt][1], ah[mt][2], ah[mt][3], bh0, bh1);
                    }
                }
            }
        }
    }

    int pix0 = y0 * 128 + xoff;
    #pragma unroll
    for (int mt = 0; mt < 2; mt++) {
        int m = mt * 16 + g;
        #pragma unroll
        for (int nt = 0; nt < 2; nt++) {
            int px = pix0 + nt * 8 + t4 * 2;
            if (m < 26) {
                float bb = bias[m];
                *(float2*)&g_fl[(b * 26 + m) * NPIX + px] =
                    make_float2(acc[mt][nt][0] + bb, acc[mt][nt][1] + bb);
            }
            if (m + 8 < 26) {
                float bb = bias[m + 8];
                *(float2*)&g_fl[(b * 26 + m + 8) * NPIX + px] =
                    make_float2(acc[mt][nt][2] + bb, acc[mt][nt][3] + bb);
            }
        }
    }
}

// ---------------------------------------------------------------------------
// wret: fused warp + ret (t>=1 only). grid (128, 2, 2).  [unchanged]
// ---------------------------------------------------------------------------
__global__ __launch_bounds__(256, 2) void wret_k(int t, const float* __restrict__ bias,
                                                 const float* __restrict__ outp)
{
    __shared__ int      s_ci[4][128];
    __shared__ float    s_cw[4][128];
    __shared__ uint32_t s_wh[8 * 104], s_wl[8 * 104];
    __shared__ uint32_t s_bh[8 * 136], s_bl[8 * 136];

    int tid = threadIdx.x;
    int lane = tid & 31;
    int g  = lane >> 2;
    int t4 = lane & 3;
    int wid = tid >> 5;
    int wm = wid >> 2;
    int wn = wid & 3;
    int mb = wm * 48;
    int nb = wn * 32;

    int b  = blockIdx.z;
    int n0 = blockIdx.x * 128;
    int mblk = blockIdx.y;
    int m0 = mblk * 96;

    float acc[3][4][4];
    #pragma unroll
    for (int mt = 0; mt < 3; mt++)
        #pragma unroll
        for (int nt = 0; nt < 4; nt++)
            #pragma unroll
            for (int i = 0; i < 4; i++) acc[mt][nt][i] = 0.f;

    const float* hprev = outp + ((b * 6 + (t - 1)) * 64) * NPIX;

    for (int l = 0; l < 13; l++) {
        __syncthreads();
        if (tid < 128) {
            int pg = n0 + tid;
            float u = g_fl[(b * 26 + 2 * l    ) * NPIX + pg];
            float v = g_fl[(b * 26 + 2 * l + 1) * NPIX + pg];
            float sx = (float)(pg & 127) - u;
            float sy = (float)(pg >> 7)  - v;
            float fx = floorf(sx), fy = floorf(sy);
            float wx1 = sx - fx, wx0 = 1.f - wx1;
            float wy1 = sy - fy, wy0 = 1.f - wy1;
            int x0 = (int)fx, y0 = (int)fy;
            int x1 = x0 + 1,  y1 = y0 + 1;
            bool vx0 = (x0 >= 0) & (x0 <= 127);
            bool vx1 = (x1 >= 0) & (x1 <= 127);
            bool vy0 = (y0 >= 0) & (y0 <= 127);
            bool vy1 = (y1 >= 0) & (y1 <= 127);
            int cx0 = min(max(x0, 0), 127), cx1 = min(max(x1, 0), 127);
            int cy0 = min(max(y0, 0), 127), cy1 = min(max(y1, 0), 127);
            s_ci[0][tid] = cy0 * 128 + cx0;
            s_ci[1][tid] = cy0 * 128 + cx1;
            s_ci[2][tid] = cy1 * 128 + cx0;
            s_ci[3][tid] = cy1 * 128 + cx1;
            s_cw[0][tid] = (vx0 && vy0) ? wx0 * wy0 : 0.f;
            s_cw[1][tid] = (vx1 && vy0) ? wx1 * wy0 : 0.f;
            s_cw[2][tid] = (vx0 && vy1) ? wx0 * wy1 : 0.f;
            s_cw[3][tid] = (vx1 && vy1) ? wx1 * wy1 : 0.f;
        }

        for (int chunk = 0; chunk < 4; chunk++) {
            __syncthreads();
            int wbase = ((mblk * 13 + l) * 4 + chunk) * 768;
            #pragma unroll
            for (int r = 0; r < 3; r++) {
                int i = tid + r * 256;
                int smi = (i / 96) * 104 + (i % 96);
                s_wh[smi] = g_wret_h[wbase + i];
                s_wl[smi] = g_wret_l[wbase + i];
            }
            #pragma unroll
            for (int r = 0; r < 4; r++) {
                int j = tid + r * 256;
                int kp = j >> 7, px = j & 127;
                int i00 = s_ci[0][px], i10 = s_ci[1][px];
                int i01 = s_ci[2][px], i11 = s_ci[3][px];
                float w00 = s_cw[0][px], w10 = s_cw[1][px];
                float w01 = s_cw[2][px], w11 = s_cw[3][px];
                const float* h0 = hprev + (chunk * 16 + kp * 2) * NPIX;
                const float* h1 = h0 + NPIX;
                float v0 = w00 * __ldg(&h0[i00]) + w10 * __ldg(&h0[i10])
                         + w01 * __ldg(&h0[i01]) + w11 * __ldg(&h0[i11]);
                float v1 = w00 * __ldg(&h1[i00]) + w10 * __ldg(&h1[i10])
                         + w01 * __ldg(&h1[i01]) + w11 * __ldg(&h1[i11]);
                uint32_t hh, ll;
                split2(v0, v1, hh, ll);
                s_bh[kp * 136 + px] = hh;
                s_bl[kp * 136 + px] = ll;
            }
            __syncthreads();

            uint32_t ah[3][4], al[3][4], bh[4][2], bl[4][2];
            #pragma unroll
            for (int mt = 0; mt < 3; mt++) {
                int mm = mb + mt * 16 + g;
                int r0 = t4 * 104, r1 = (t4 + 4) * 104;
                ah[mt][0] = s_wh[r0 + mm];     ah[mt][1] = s_wh[r0 + mm + 8];
                ah[mt][2] = s_wh[r1 + mm];     ah[mt][3] = s_wh[r1 + mm + 8];
                al[mt][0] = s_wl[r0 + mm];     al[mt][1] = s_wl[r0 + mm + 8];
                al[mt][2] = s_wl[r1 + mm];     al[mt][3] = s_wl[r1 + mm + 8];
            }
            #pragma unroll
            for (int nt = 0; nt < 4; nt++) {
                int nn = nb + nt * 8 + g;
                bh[nt][0] = s_bh[t4 * 136 + nn];
                bh[nt][1] = s_bh[(t4 + 4) * 136 + nn];
                bl[nt][0] = s_bl[t4 * 136 + nn];
                bl[nt][1] = s_bl[(t4 + 4) * 136 + nn];
            }
            #pragma unroll
            for (int mt = 0; mt < 3; mt++)
                #pragma unroll
                for (int nt = 0; nt < 4; nt++) {
                    float* c = acc[mt][nt];
                    MMA_BF16(c[0], c[1], c[2], c[3],
                             al[mt][0], al[mt][1], al[mt][2], al[mt][3],
                             bh[nt][0], bh[nt][1]);
                    MMA_BF16(c[0], c[1], c[2], c[3],
                             ah[mt][0], ah[mt][1], ah[mt][2], ah[mt][3],
                             bl[nt][0], bl[nt][1]);
                    MMA_BF16(c[0], c[1], c[2], c[3],
                             ah[mt][0], ah[mt][1], ah[mt][2], ah[mt][3],
                             bh[nt][0], bh[nt][1]);
                }
        }
    }

    float* C = g_h2h + b * 192 * NPIX;
    #pragma unroll
    for (int mt = 0; mt < 3; mt++) {
        int m = m0 + mb + mt * 16 + g;
        float bb0 = bias[m], bb1 = bias[m + 8];
        #pragma unroll
        for (int nt = 0; nt < 4; nt++) {
            int col = n0 + nb + nt * 8 + t4 * 2;
            float2 o0 = make_float2(acc[mt][nt][0] + bb0, acc[mt][nt][1] + bb0);
            float2 o1 = make_float2(acc[mt][nt][2] + bb1, acc[mt][nt][3] + bb1);
            *(float2*)&C[m * NPIX + col]       = o0;
            *(float2*)&C[(m + 8) * NPIX + col] = o1;
        }
    }
}

// ---------------------------------------------------------------------------
// GRU update: out[b,t] fp32 + bf16-split hidden copy. t=0: h2h = b_ret.
// ---------------------------------------------------------------------------
__global__ void gru_k(int t, int first, const float* __restrict__ bret,
                      float* __restrict__ outp)
{
    int pix = blockIdx.x * 256 + threadIdx.x;
    int c2  = blockIdx.y;
    int b   = blockIdx.z;
    int c   = 2 * c2;
    int base = b * 192 * NPIX;

    float h01[2];
    #pragma unroll
    for (int j = 0; j < 2; j++) {
        int cj = c + j;
        float ir = g_i2h[base + (cj      ) * NPIX + pix];
        float iu = g_i2h[base + (cj +  64) * NPIX + pix];
        float im = g_i2h[base + (cj + 128) * NPIX + pix];
        float hr, hu, hm;
        if (first) {
            hr = bret[cj]; hu = bret[cj + 64]; hm = bret[cj + 128];
        } else {
            hr = g_h2h[base + (cj      ) * NPIX + pix];
            hu = g_h2h[base + (cj +  64) * NPIX + pix];
            hm = g_h2h[base + (cj + 128) * NPIX + pix];
        }

        float r = 1.f / (1.f + expf(-(ir + hr)));
        float z = 1.f / (1.f + expf(-(iu + hu)));
        float m = leaky_f(im + r * hm);

        float hp = first ? 0.f : outp[((b * 6 + t - 1) * 64 + cj) * NPIX + pix];
        float h  = z * hp + (1.f - z) * m;
        outp[((b * 6 + t) * 64 + cj) * NPIX + pix] = h;
        h01[j] = h;
    }
    uint32_t hw, lw;
    split2(h01[0], h01[1], hw, lw);
    int p = (b * 32 + c2) * NPIX + pix;
    g_hbf_h[p] = hw; g_hbf_l[p] = lw;
}

// ---------------------------------------------------------------------------
// Launch
// ---------------------------------------------------------------------------
extern "C" void kernel_launch(void* const* d_in, const int* in_sizes, int n_in,
                              void* d_out, int out_size)
{
    const float* x      = (const float*)d_in[0];
    const float* w_stem = (const float*)d_in[1];
    const float* b_stem = (const float*)d_in[2];
    const float* w_i2h  = (const float*)d_in[3];
    const float* b_i2h  = (const float*)d_in[4];
    const float* w_i2f  = (const float*)d_in[5];
    const float* b_i2f  = (const float*)d_in[6];
    const float* w_h2f  = (const float*)d_in[7];
    const float* b_h2f  = (const float*)d_in[8];
    const float* w_flow = (const float*)d_in[9];
    const float* b_flow = (const float*)d_in[10];
    const float* w_ret  = (const float*)d_in[11];
    const float* b_ret  = (const float*)d_in[12];
    float* outp = (float*)d_out;

    cudaFuncSetAttribute(fat_k,  cudaFuncAttributeMaxDynamicSharedMemorySize, FAT_SMEM_BYTES);
    cudaFuncSetAttribute(flow_k, cudaFuncAttributeMaxDynamicSharedMemorySize, FLOW_SMEM_BYTES);

    wprep_all_k<<<(199168 + 255) / 256, 256>>>(w_i2h, w_i2f, w_h2f, w_flow, w_ret);

    stem_k<<<dim3(64, 48, 2), 256>>>(x, w_stem, b_stem);

    for (int t = 0; t < 6; t++) {
        int first = (t == 0) ? 1 : 0;
        fat_k <<<dim3(320, 1, 2), 256, FAT_SMEM_BYTES>>>(t, first, b_i2h);
        flow_k<<<dim3(128, 1, 2), 256, FLOW_SMEM_BYTES>>>(b_flow, b_i2f, b_h2f, first);
        if (!first)
            wret_k<<<dim3(128, 2, 2), 256>>>(t, b_ret, outp);
        gru_k <<<dim3(64, 32, 2), 256>>>(t, first, b_ret, outp);
    }
}

// round 16
// speedup vs baseline: 1.3059x; 1.0259x over previous
#include <cuda_runtime.h>
#include <cuda_bf16.h>
#include <math.h>
#include <stdint.h>

#define NPIX 16384            // 128*128

// ---------------------------------------------------------------------------
// Scratch (static device globals)
// ---------------------------------------------------------------------------
__device__ float g_i2h[2][2 * 192 * NPIX];  // i2h out, double-buffered  50 MB
__device__ float g_h2h[2 * 192 * NPIX];     // ret conv out              25 MB
__device__ float g_f1p[2][2 * 32 * NPIX];   // f1 partial sums (2 src)  8.4 MB
__device__ float g_fl [2 *  26 * NPIX];     // flows                    3.4 MB

// bf16-split packed operands (channel pairs per 32-bit word)
__device__ uint32_t g_ysbf_h[2 * 192 * NPIX], g_ysbf_l[2 * 192 * NPIX]; // stem out (c,c+1)
__device__ uint32_t g_hbf_h [2 *  32 * NPIX], g_hbf_l [2 *  32 * NPIX]; // hprev (c,c+1)

// pre-converted weights: layouts match smem consumption order
__device__ uint32_t g_wi2h_h[3 * 4 * 9 * 8 * 64],  g_wi2h_l[3 * 4 * 9 * 8 * 64];
__device__ uint32_t g_wf1_h [2 * 4 * 25 * 8 * 32], g_wf1_l [2 * 4 * 25 * 8 * 32];
__device__ uint32_t g_wfl_h [2 * 25 * 8 * 32],     g_wfl_l [2 * 25 * 8 * 32];
__device__ uint32_t g_wret_h[2 * 13 * 4 * 8 * 96], g_wret_l[2 * 13 * 4 * 8 * 96];

__device__ __forceinline__ float leaky_f(float x) { return x >= 0.f ? x : 0.2f * x; }

// split two floats into packed bf16 hi-pair and lo-pair (v = hi + lo)
__device__ __forceinline__ void split2(float v0, float v1, uint32_t& h, uint32_t& l) {
    __nv_bfloat162 hb = __floats2bfloat162_rn(v0, v1);
    float h0 = __low2float(hb), h1 = __high2float(hb);
    __nv_bfloat162 lb = __floats2bfloat162_rn(v0 - h0, v1 - h1);
    h = *reinterpret_cast<uint32_t*>(&hb);
    l = *reinterpret_cast<uint32_t*>(&lb);
}

#define MMA_BF16(c0,c1,c2,c3, a0,a1,a2,a3, b0,b1)                              \
    asm volatile("mma.sync.aligned.m16n8k16.row.col.f32.bf16.bf16.f32 "        \
        "{%0,%1,%2,%3}, {%4,%5,%6,%7}, {%8,%9}, {%0,%1,%2,%3};"                \
        : "+f"(c0), "+f"(c1), "+f"(c2), "+f"(c3)                               \
        : "r"(a0), "r"(a1), "r"(a2), "r"(a3), "r"(b0), "r"(b1))

// ---------------------------------------------------------------------------
// Weight prep — all four conversions in ONE kernel (run once per launch)
// ---------------------------------------------------------------------------
__global__ void wprep_all_k(const float* __restrict__ wi2h,
                            const float* __restrict__ wi2f,
                            const float* __restrict__ wh2f,
                            const float* __restrict__ wfl,
                            const float* __restrict__ wret)
{
    int idx = blockIdx.x * 256 + threadIdx.x;

    if (idx < 55296) {
        int oc = idx & 63;
        int kp = (idx >> 6) & 7;
        int q  = idx >> 9;
        int tap = q % 9;
        int qc  = q / 9;
        int chunk = qc & 3, ocg = qc >> 2;
        int ic = chunk * 16 + 2 * kp;
        int o  = ocg * 64 + oc;
        float v0 = wi2h[(o * 64 + ic    ) * 9 + tap];
        float v1 = wi2h[(o * 64 + ic + 1) * 9 + tap];
        split2(v0, v1, g_wi2h_h[idx], g_wi2h_l[idx]);
        return;
    }
    idx -= 55296;
    if (idx < 51200) {
        int oc = idx & 31;
        int kp = (idx >> 5) & 7;
        int q  = idx >> 8;
        int tap = q % 25;
        int qc  = q / 25;
        int chunk = qc & 3, src = qc >> 2;
        int ic = chunk * 16 + 2 * kp;
        const float* w = src ? wh2f : wi2f;
        float v0 = w[(oc * 64 + ic    ) * 25 + tap];
        float v1 = w[(oc * 64 + ic + 1) * 25 + tap];
        split2(v0, v1, g_wf1_h[idx], g_wf1_l[idx]);
        return;
    }
    idx -= 51200;
    if (idx < 12800) {
        int oc = idx & 31;
        int kp = (idx >> 5) & 7;
        int q  = idx >> 8;
        int tap = q % 25;
        int chunk = q / 25;
        int ic = chunk * 16 + 2 * kp;
        float v0 = 0.f, v1 = 0.f;
        if (oc < 26) {
            v0 = wfl[(oc * 32 + ic    ) * 25 + tap];
            v1 = wfl[(oc * 32 + ic + 1) * 25 + tap];
        }
        split2(v0, v1, g_wfl_h[idx], g_wfl_l[idx]);
        return;
    }
    idx -= 12800;
    if (idx < 79872) {
        int m  = idx % 96;
        int kp = (idx / 96) & 7;
        int chunk = (idx / 768) & 3;
        int l  = (idx / 3072) % 13;
        int mb = idx / 39936;
        int k  = l * 64 + chunk * 16 + kp * 2;
        float v0 = wret[(mb * 96 + m) * 832 + k];
        float v1 = wret[(mb * 96 + m) * 832 + k + 1];
        split2(v0, v1, g_wret_h[idx], g_wret_l[idx]);
    }
}

// ---------------------------------------------------------------------------
// Stem: conv 3x3 stride 2 pad 1 -> bf16-split
// ---------------------------------------------------------------------------
__global__ __launch_bounds__(256) void stem_k(const float* __restrict__ x,
                                              const float* __restrict__ w,
                                              const float* __restrict__ bias)
{
    __shared__ __align__(16) float sw[54][8];

    int tid = threadIdx.x;
    int oc0 = blockIdx.y * 8;
    int b   = blockIdx.z;

    for (int i = tid; i < 432; i += 256) {
        int oc = i & 7, tap = i >> 3;
        sw[tap][oc] = w[(oc0 + oc) * 54 + tap];
    }
    __syncthreads();

    int pix = blockIdx.x * 256 + tid;
    int oy = pix >> 7, ox = pix & 127;

    float acc[8];
    #pragma unroll
    for (int j = 0; j < 8; j++) acc[j] = bias[oc0 + j];

    #pragma unroll
    for (int ic = 0; ic < 6; ic++) {
        const float* xb = x + (b * 6 + ic) * 65536;
        float in[9];
        #pragma unroll
        for (int ky = 0; ky < 3; ky++) {
            int iy = 2 * oy - 1 + ky;
            #pragma unroll
            for (int kx = 0; kx < 3; kx++) {
                int ix = 2 * ox - 1 + kx;
                bool ok = (iy >= 0) & (iy <= 255) & (ix >= 0) & (ix <= 255);
                in[ky * 3 + kx] = ok ? __ldg(&xb[iy * 256 + ix]) : 0.f;
            }
        }
        #pragma unroll
        for (int k = 0; k < 9; k++) {
            int tap = ic * 9 + k;
            float a[8];
            *(float4*)&a[0] = *(const float4*)&sw[tap][0];
            *(float4*)&a[4] = *(const float4*)&sw[tap][4];
            #pragma unroll
            for (int j = 0; j < 8; j++) acc[j] += in[k] * a[j];
        }
    }
    #pragma unroll
    for (int j = 0; j < 8; j++) acc[j] = leaky_f(acc[j]);

    int pbase = ((b * 384 + oc0) >> 1) * NPIX + pix;
    #pragma unroll
    for (int j = 0; j < 4; j++) {
        uint32_t h, l;
        split2(acc[2 * j], acc[2 * j + 1], h, l);
        g_ysbf_h[pbase + j * NPIX] = h;
        g_ysbf_l[pbase + j * NPIX] = l;
    }
}

// ---------------------------------------------------------------------------
// i2h role body (conv3x3 64->192), plain loader, writes g_i2h[buf].
// smem need: (2*5184 + 2*4416) words = 76.8 KB dynamic.
// ---------------------------------------------------------------------------
__device__ __forceinline__ void i2h_body(uint32_t* sm_u, int xt, int ocg, int b,
                                         int t, int buf, const float* __restrict__ bias)
{
    uint32_t* s_wh = sm_u;
    uint32_t* s_wl = s_wh + 5184;
    uint32_t* s_xh = s_wl + 5184;
    uint32_t* s_xl = s_xh + 4416;

    int tid = threadIdx.x;
    int lane = tid & 31;
    int g  = lane >> 2;
    int t4 = lane & 3;
    int wid = tid >> 5;
    int wm = wid >> 2;
    int wn = wid & 3;
    int ry = wn >> 1;
    int xoff = (wn & 1) * 64;

    int y0 = xt * 2;
    int m0 = ocg * 64;
    const uint32_t* inh = g_ysbf_h + (b * 192 + t * 32) * NPIX;
    const uint32_t* inl = g_ysbf_l + (b * 192 + t * 32) * NPIX;

    float acc[2][8][4];
    #pragma unroll
    for (int mt = 0; mt < 2; mt++)
        #pragma unroll
        for (int nt = 0; nt < 8; nt++)
            #pragma unroll
            for (int i = 0; i < 4; i++) acc[mt][nt][i] = 0.f;

    for (int chunk = 0; chunk < 4; chunk++) {
        __syncthreads();
        int wbase = (ocg * 4 + chunk) * 4608;
        for (int i = tid; i < 4608; i += 256) {
            int smi = (i >> 6) * 72 + (i & 63);
            s_wh[smi] = g_wi2h_h[wbase + i];
            s_wl[smi] = g_wi2h_l[wbase + i];
        }
        int pbase = chunk * 8;
        for (int i = tid; i < 4160; i += 256) {
            int col = i % 130, r = i / 130;
            int row = r & 3, kp = r >> 2;
            int gy = y0 - 1 + row, gx = col - 1;
            uint32_t vh = 0, vl = 0;
            if (gy >= 0 && gy < 128 && gx >= 0 && gx < 128) {
                int off = (pbase + kp) * NPIX + gy * 128 + gx;
                vh = inh[off]; vl = inl[off];
            }
            int si = kp * 552 + row * 136 + col;
            s_xh[si] = vh; s_xl[si] = vl;
        }
        __syncthreads();

        #pragma unroll
        for (int ky = 0; ky < 3; ky++) {
            #pragma unroll
            for (int kx = 0; kx < 3; kx++) {
                int tap = ky * 3 + kx;
                uint32_t ah[2][4], al[2][4];
                #pragma unroll
                for (int mt = 0; mt < 2; mt++) {
                    int mm = wm * 32 + mt * 16 + g;
                    int r0 = (tap * 8 + t4) * 72, r1 = (tap * 8 + t4 + 4) * 72;
                    ah[mt][0] = s_wh[r0 + mm];     ah[mt][1] = s_wh[r0 + mm + 8];
                    ah[mt][2] = s_wh[r1 + mm];     ah[mt][3] = s_wh[r1 + mm + 8];
                    al[mt][0] = s_wl[r0 + mm];     al[mt][1] = s_wl[r0 + mm + 8];
                    al[mt][2] = s_wl[r1 + mm];     al[mt][3] = s_wl[r1 + mm + 8];
                }
                int base = (ry + ky) * 136 + xoff + kx;
                #pragma unroll
                for (int nt = 0; nt < 8; nt++) {
                    int cc = base + nt * 8 + g;
                    uint32_t bh0 = s_xh[t4 * 552 + cc];
                    uint32_t bh1 = s_xh[(t4 + 4) * 552 + cc];
                    uint32_t bl0 = s_xl[t4 * 552 + cc];
                    uint32_t bl1 = s_xl[(t4 + 4) * 552 + cc];
                    #pragma unroll
                    for (int mt = 0; mt < 2; mt++) {
                        float* c = acc[mt][nt];
                        MMA_BF16(c[0], c[1], c[2], c[3],
                                 al[mt][0], al[mt][1], al[mt][2], al[mt][3], bh0, bh1);
                        MMA_BF16(c[0], c[1], c[2], c[3],
                                 ah[mt][0], ah[mt][1], ah[mt][2], ah[mt][3], bl0, bl1);
                        MMA_BF16(c[0], c[1], c[2], c[3],
                                 ah[mt][0], ah[mt][1], ah[mt][2], ah[mt][3], bh0, bh1);
                    }
                }
            }
        }
    }

    int pix0 = (y0 + ry) * 128 + xoff;
    float* ob = g_i2h[buf];
    #pragma unroll
    for (int mt = 0; mt < 2; mt++) {
        int m = m0 + wm * 32 + mt * 16 + g;
        float bb0 = bias[m], bb1 = bias[m + 8];
        float* C0 = &ob[(b * 192 + m    ) * NPIX];
        float* C1 = &ob[(b * 192 + m + 8) * NPIX];
        #pragma unroll
        for (int nt = 0; nt < 8; nt++) {
            int px = pix0 + nt * 8 + t4 * 2;
            *(float2*)&C0[px] = make_float2(acc[mt][nt][0] + bb0, acc[mt][nt][1] + bb0);
            *(float2*)&C1[px] = make_float2(acc[mt][nt][2] + bb1, acc[mt][nt][3] + bb1);
        }
    }
}

#define I2H_SMEM_BYTES ((2 * 5184 + 2 * 4416) * 4)
__global__ __launch_bounds__(256, 2) void i2h_k(int t, int buf,
                                                const float* __restrict__ bias)
{
    extern __shared__ uint32_t sm_u[];
    i2h_body(sm_u, blockIdx.x, blockIdx.y, blockIdx.z, t, buf, bias);
}

// ---------------------------------------------------------------------------
// f1 (conv5x5 64->32, both sources): grid (128, 1, 2); bid<64 src0, else src1.
// ---------------------------------------------------------------------------
#define F1_SMEM_BYTES ((2 * 1600 + 2 * 6464) * 4)
__global__ __launch_bounds__(256, 2) void f1_k(int t, int first)
{
    extern __shared__ uint32_t sm_u[];
    int bid = blockIdx.x;
    int src = bid >> 6;
    if (first && src) return;
    int xt = bid & 63;
    int b  = blockIdx.z;

    uint32_t* s_wh = sm_u;
    uint32_t* s_wl = s_wh + 1600;
    uint32_t* s_xh = s_wl + 1600;
    uint32_t* s_xl = s_xh + 6464;

    int tid = threadIdx.x;
    int lane = tid & 31;
    int g  = lane >> 2;
    int t4 = lane & 3;
    int wid = tid >> 5;
    int rw = wid >> 2;
    int xoff = (wid & 3) * 32;

    int y0 = xt * 2;
    const uint32_t* inh = src ? (g_hbf_h + b * 32 * NPIX) : (g_ysbf_h + (b * 192 + t * 32) * NPIX);
    const uint32_t* inl = src ? (g_hbf_l + b * 32 * NPIX) : (g_ysbf_l + (b * 192 + t * 32) * NPIX);

    float acc[2][4][4];
    #pragma unroll
    for (int mt = 0; mt < 2; mt++)
        #pragma unroll
        for (int nt = 0; nt < 4; nt++)
            #pragma unroll
            for (int i = 0; i < 4; i++) acc[mt][nt][i] = 0.f;

    for (int chunk = 0; chunk < 4; chunk++) {
        __syncthreads();
        int pbase = chunk * 8;
        for (int i = tid; i < 6336; i += 256) {
            int col = i % 132, r = i / 132;
            int row = r % 6, kp = r / 6;
            int gy = y0 - 2 + row, gx = col - 2;
            uint32_t vh = 0, vl = 0;
            if (gy >= 0 && gy < 128 && gx >= 0 && gx < 128) {
                int off = (pbase + kp) * NPIX + gy * 128 + gx;
                vh = inh[off]; vl = inl[off];
            }
            int si = kp * 808 + row * 132 + col;
            s_xh[si] = vh; s_xl[si] = vl;
        }
        #pragma unroll 1
        for (int ky = 0; ky < 5; ky++) {
            if (ky) __syncthreads();
            int wbase = ((src * 4 + chunk) * 25 + ky * 5) * 256;
            {
                int i = tid;
                #pragma unroll
                for (int r = 0; r < 5; r++) {
                    int smi = (i >> 5) * 40 + (i & 31);
                    s_wh[smi] = g_wf1_h[wbase + i];
                    s_wl[smi] = g_wf1_l[wbase + i];
                    i += 256;
                }
            }
            __syncthreads();

            #pragma unroll
            for (int kx = 0; kx < 5; kx++) {
                uint32_t ah[2][4], al[2][4];
                #pragma unroll
                for (int mt = 0; mt < 2; mt++) {
                    int mm = mt * 16 + g;
                    int r0 = (kx * 8 + t4) * 40, r1 = (kx * 8 + t4 + 4) * 40;
                    ah[mt][0] = s_wh[r0 + mm];     ah[mt][1] = s_wh[r0 + mm + 8];
                    ah[mt][2] = s_wh[r1 + mm];     ah[mt][3] = s_wh[r1 + mm + 8];
                    al[mt][0] = s_wl[r0 + mm];     al[mt][1] = s_wl[r0 + mm + 8];
                    al[mt][2] = s_wl[r1 + mm];     al[mt][3] = s_wl[r1 + mm + 8];
                }
                int base = (rw + ky) * 132 + xoff + kx;
                #pragma unroll
                for (int nt = 0; nt < 4; nt++) {
                    int cc = base + nt * 8 + g;
                    uint32_t bh0 = s_xh[t4 * 808 + cc];
                    uint32_t bh1 = s_xh[(t4 + 4) * 808 + cc];
                    uint32_t bl0 = s_xl[t4 * 808 + cc];
                    uint32_t bl1 = s_xl[(t4 + 4) * 808 + cc];
                    #pragma unroll
                    for (int mt = 0; mt < 2; mt++) {
                        float* c = acc[mt][nt];
                        MMA_BF16(c[0], c[1], c[2], c[3],
                                 al[mt][0], al[mt][1], al[mt][2], al[mt][3], bh0, bh1);
                        MMA_BF16(c[0], c[1], c[2], c[3],
                                 ah[mt][0], ah[mt][1], ah[mt][2], ah[mt][3], bl0, bl1);
                        MMA_BF16(c[0], c[1], c[2], c[3],
                                 ah[mt][0], ah[mt][1], ah[mt][2], ah[mt][3], bh0, bh1);
                    }
                }
            }
        }
    }

    float* op = g_f1p[src];
    int pix0 = (y0 + rw) * 128 + xoff;
    #pragma unroll
    for (int mt = 0; mt < 2; mt++) {
        int m = mt * 16 + g;
        float* C0 = &op[(b * 32 + m    ) * NPIX];
        float* C1 = &op[(b * 32 + m + 8) * NPIX];
        #pragma unroll
        for (int nt = 0; nt < 4; nt++) {
            int px = pix0 + nt * 8 + t4 * 2;
            *(float2*)&C0[px] = make_float2(acc[mt][nt][0], acc[mt][nt][1]);
            *(float2*)&C1[px] = make_float2(acc[mt][nt][2], acc[mt][nt][3]);
        }
    }
}

// ---------------------------------------------------------------------------
// flow: conv5x5 32 -> 26 (padded 32); loader fuses f1 combine. 1-row tiles.
// grid (128, 1, 2), smem 56.3 KB, 2 blocks/SM.
// ---------------------------------------------------------------------------
#define FLOW_SMEM_BYTES ((2 * 1600 + 2 * 5440) * 4)
__global__ __launch_bounds__(256, 2) void flow_k(const float* __restrict__ bias,
                                                 const float* __restrict__ bi,
                                                 const float* __restrict__ bh,
                                                 int first)
{
    extern __shared__ uint32_t sm_u[];
    uint32_t* s_wh = sm_u;
    uint32_t* s_wl = s_wh + 1600;
    uint32_t* s_xh = s_wl + 1600;
    uint32_t* s_xl = s_xh + 5440;
    __shared__ float s_cb[32];

    int tid = threadIdx.x;
    int lane = tid & 31;
    int g  = lane >> 2;
    int t4 = lane & 3;
    int wid = tid >> 5;
    int xoff = wid * 16;

    int y0 = blockIdx.x;
    int b  = blockIdx.z;
    if (tid < 32) s_cb[tid] = bi[tid] + bh[tid];

    const float* p0 = g_f1p[0] + b * 32 * NPIX;
    const float* p1 = g_f1p[1] + b * 32 * NPIX;

    float acc[2][2][4];
    #pragma unroll
    for (int mt = 0; mt < 2; mt++)
        #pragma unroll
        for (int nt = 0; nt < 2; nt++)
            #pragma unroll
            for (int i = 0; i < 4; i++) acc[mt][nt][i] = 0.f;

    for (int chunk = 0; chunk < 2; chunk++) {
        __syncthreads();
        int pbase = chunk * 8;
        for (int i = tid; i < 5280; i += 256) {
            int col = i % 132, r = i / 132;
            int row = r % 5, kp = r / 5;
            int gy = y0 - 2 + row, gx = col - 2;
            uint32_t vh = 0, vl = 0;
            if (gy >= 0 && gy < 128 && gx >= 0 && gx < 128) {
                int c0 = 2 * (pbase + kp);
                int off = gy * 128 + gx;
                const float* q0 = p0 + c0 * NPIX;
                float v0 = q0[off], v1 = q0[NPIX + off];
                if (!first) {
                    const float* q1 = p1 + c0 * NPIX;
                    v0 += q1[off]; v1 += q1[NPIX + off];
                }
                v0 = leaky_f(v0 + s_cb[c0]);
                v1 = leaky_f(v1 + s_cb[c0 + 1]);
                split2(v0, v1, vh, vl);
            }
            int si = kp * 680 + row * 132 + col;
            s_xh[si] = vh; s_xl[si] = vl;
        }
        #pragma unroll 1
        for (int ky = 0; ky < 5; ky++) {
            if (ky) __syncthreads();
            int wbase = (chunk * 25 + ky * 5) * 256;
            {
                int i = tid;
                #pragma unroll
                for (int r = 0; r < 5; r++) {
                    int smi = (i >> 5) * 40 + (i & 31);
                    s_wh[smi] = g_wfl_h[wbase + i];
                    s_wl[smi] = g_wfl_l[wbase + i];
                    i += 256;
                }
            }
            __syncthreads();

            #pragma unroll
            for (int kx = 0; kx < 5; kx++) {
                uint32_t ah[2][4], al[2][4];
                #pragma unroll
                for (int mt = 0; mt < 2; mt++) {
                    int mm = mt * 16 + g;
                    int r0 = (kx * 8 + t4) * 40, r1 = (kx * 8 + t4 + 4) * 40;
                    ah[mt][0] = s_wh[r0 + mm];     ah[mt][1] = s_wh[r0 + mm + 8];
                    ah[mt][2] = s_wh[r1 + mm];     ah[mt][3] = s_wh[r1 + mm + 8];
                    al[mt][0] = s_wl[r0 + mm];     al[mt][1] = s_wl[r0 + mm + 8];
                    al[mt][2] = s_wl[r1 + mm];     al[mt][3] = s_wl[r1 + mm + 8];
                }
                int base = ky * 132 + xoff + kx;
                #pragma unroll
                for (int nt = 0; nt < 2; nt++) {
                    int cc = base + nt * 8 + g;
                    uint32_t bh0 = s_xh[t4 * 680 + cc];
                    uint32_t bh1 = s_xh[(t4 + 4) * 680 + cc];
                    uint32_t bl0 = s_xl[t4 * 680 + cc];
                    uint32_t bl1 = s_xl[(t4 + 4) * 680 + cc];
                    #pragma unroll
                    for (int mt = 0; mt < 2; mt++) {
                        float* c = acc[mt][nt];
                        MMA_BF16(c[0], c[1], c[2], c[3],
                                 al[mt][0], al[mt][1], al[mt][2], al[mt][3], bh0, bh1);
                        MMA_BF16(c[0], c[1], c[2], c[3],
                                 ah[mt][0], ah[mt][1], ah[mt][2], ah[mt][3], bl0, bl1);
                        MMA_BF16(c[0], c[1], c[2], c[3],
                                 ah[mt][0], ah[mt][1], ah[mt][2], ah[mt][3], bh0, bh1);
                    }
                }
            }
        }
    }

    int pix0 = y0 * 128 + xoff;
    #pragma unroll
    for (int mt = 0; mt < 2; mt++) {
        int m = mt * 16 + g;
        #pragma unroll
        for (int nt = 0; nt < 2; nt++) {
            int px = pix0 + nt * 8 + t4 * 2;
            if (m < 26) {
                float bb = bias[m];
                *(float2*)&g_fl[(b * 26 + m) * NPIX + px] =
                    make_float2(acc[mt][nt][0] + bb, acc[mt][nt][1] + bb);
            }
            if (m + 8 < 26) {
                float bb = bias[m + 8];
                *(float2*)&g_fl[(b * 26 + m + 8) * NPIX + px] =
                    make_float2(acc[mt][nt][2] + bb, acc[mt][nt][3] + bb);
            }
        }
    }
}

// ---------------------------------------------------------------------------
// wreti: wret roles (bid<256) + i2h(t+1) roles (bid>=256, when t<5).
// grid (256 or 448, 1, 2), dynamic 76.8 KB + ~19.5 KB static, 2 blocks/SM.
// ---------------------------------------------------------------------------
__global__ __launch_bounds__(256, 2) void wreti_k(int t, const float* __restrict__ bias,
                                                  const float* __restrict__ bias_i2h,
                                                  const float* __restrict__ outp)
{
    __shared__ int      s_ci[4][128];
    __shared__ float    s_cw[4][128];
    __shared__ uint32_t s_wh[8 * 104], s_wl[8 * 104];
    __shared__ uint32_t s_bh[8 * 136], s_bl[8 * 136];
    extern __shared__ uint32_t sm_u[];

    int bid = blockIdx.x;
    int b   = blockIdx.z;

    if (bid >= 256) {
        // i2h for step t+1 into buffer (t+1)&1
        int r = bid - 256;
        i2h_body(sm_u, r & 63, r >> 6, b, t + 1, (t + 1) & 1, bias_i2h);
        return;
    }

    int tid = threadIdx.x;
    int lane = tid & 31;
    int g  = lane >> 2;
    int t4 = lane & 3;
    int wid = tid >> 5;
    int wm = wid >> 2;
    int wn = wid & 3;
    int mb = wm * 48;
    int nb = wn * 32;

    int n0 = (bid & 127) * 128;
    int mblk = bid >> 7;
    int m0 = mblk * 96;

    float acc[3][4][4];
    #pragma unroll
    for (int mt = 0; mt < 3; mt++)
        #pragma unroll
        for (int nt = 0; nt < 4; nt++)
            #pragma unroll
            for (int i = 0; i < 4; i++) acc[mt][nt][i] = 0.f;

    const float* hprev = outp + ((b * 6 + (t - 1)) * 64) * NPIX;

    for (int l = 0; l < 13; l++) {
        __syncthreads();
        if (tid < 128) {
            int pg = n0 + tid;
            float u = g_fl[(b * 26 + 2 * l    ) * NPIX + pg];
            float v = g_fl[(b * 26 + 2 * l + 1) * NPIX + pg];
            float sx = (float)(pg & 127) - u;
            float sy = (float)(pg >> 7)  - v;
            float fx = floorf(sx), fy = floorf(sy);
            float wx1 = sx - fx, wx0 = 1.f - wx1;
            float wy1 = sy - fy, wy0 = 1.f - wy1;
            int x0 = (int)fx, y0 = (int)fy;
            int x1 = x0 + 1,  y1 = y0 + 1;
            bool vx0 = (x0 >= 0) & (x0 <= 127);
            bool vx1 = (x1 >= 0) & (x1 <= 127);
            bool vy0 = (y0 >= 0) & (y0 <= 127);
            bool vy1 = (y1 >= 0) & (y1 <= 127);
            int cx0 = min(max(x0, 0), 127), cx1 = min(max(x1, 0), 127);
            int cy0 = min(max(y0, 0), 127), cy1 = min(max(y1, 0), 127);
            s_ci[0][tid] = cy0 * 128 + cx0;
            s_ci[1][tid] = cy0 * 128 + cx1;
            s_ci[2][tid] = cy1 * 128 + cx0;
            s_ci[3][tid] = cy1 * 128 + cx1;
            s_cw[0][tid] = (vx0 && vy0) ? wx0 * wy0 : 0.f;
            s_cw[1][tid] = (vx1 && vy0) ? wx1 * wy0 : 0.f;
            s_cw[2][tid] = (vx0 && vy1) ? wx0 * wy1 : 0.f;
            s_cw[3][tid] = (vx1 && vy1) ? wx1 * wy1 : 0.f;
        }

        for (int chunk = 0; chunk < 4; chunk++) {
            __syncthreads();
            int wbase = ((mblk * 13 + l) * 4 + chunk) * 768;
            #pragma unroll
            for (int r = 0; r < 3; r++) {
                int i = tid + r * 256;
                int smi = (i / 96) * 104 + (i % 96);
                s_wh[smi] = g_wret_h[wbase + i];
                s_wl[smi] = g_wret_l[wbase + i];
            }
            #pragma unroll
            for (int r = 0; r < 4; r++) {
                int j = tid + r * 256;
                int kp = j >> 7, px = j & 127;
                int i00 = s_ci[0][px], i10 = s_ci[1][px];
                int i01 = s_ci[2][px], i11 = s_ci[3][px];
                float w00 = s_cw[0][px], w10 = s_cw[1][px];
                float w01 = s_cw[2][px], w11 = s_cw[3][px];
                const float* h0 = hprev + (chunk * 16 + kp * 2) * NPIX;
                const float* h1 = h0 + NPIX;
                float v0 = w00 * __ldg(&h0[i00]) + w10 * __ldg(&h0[i10])
                         + w01 * __ldg(&h0[i01]) + w11 * __ldg(&h0[i11]);
                float v1 = w00 * __ldg(&h1[i00]) + w10 * __ldg(&h1[i10])
                         + w01 * __ldg(&h1[i01]) + w11 * __ldg(&h1[i11]);
                uint32_t hh, ll;
                split2(v0, v1, hh, ll);
                s_bh[kp * 136 + px] = hh;
                s_bl[kp * 136 + px] = ll;
            }
            __syncthreads();

            uint32_t ah[3][4], al[3][4], bh[4][2], bl[4][2];
            #pragma unroll
            for (int mt = 0; mt < 3; mt++) {
                int mm = mb + mt * 16 + g;
                int r0 = t4 * 104, r1 = (t4 + 4) * 104;
                ah[mt][0] = s_wh[r0 + mm];     ah[mt][1] = s_wh[r0 + mm + 8];
                ah[mt][2] = s_wh[r1 + mm];     ah[mt][3] = s_wh[r1 + mm + 8];
                al[mt][0] = s_wl[r0 + mm];     al[mt][1] = s_wl[r0 + mm + 8];
                al[mt][2] = s_wl[r1 + mm];     al[mt][3] = s_wl[r1 + mm + 8];
            }
            #pragma unroll
            for (int nt = 0; nt < 4; nt++) {
                int nn = nb + nt * 8 + g;
                bh[nt][0] = s_bh[t4 * 136 + nn];
                bh[nt][1] = s_bh[(t4 + 4) * 136 + nn];
                bl[nt][0] = s_bl[t4 * 136 + nn];
                bl[nt][1] = s_bl[(t4 + 4) * 136 + nn];
            }
            #pragma unroll
            for (int mt = 0; mt < 3; mt++)
                #pragma unroll
                for (int nt = 0; nt < 4; nt++) {
                    float* c = acc[mt][nt];
                    MMA_BF16(c[0], c[1], c[2], c[3],
                             al[mt][0], al[mt][1], al[mt][2], al[mt][3],
                             bh[nt][0], bh[nt][1]);
                    MMA_BF16(c[0], c[1], c[2], c[3],
                             ah[mt][0], ah[mt][1], ah[mt][2], ah[mt][3],
                             bl[nt][0], bl[nt][1]);
                    MMA_BF16(c[0], c[1], c[2], c[3],
                             ah[mt][0], ah[mt][1], ah[mt][2], ah[mt][3],
                             bh[nt][0], bh[nt][1]);
                }
        }
    }

    float* C = g_h2h + b * 192 * NPIX;
    #pragma unroll
    for (int mt = 0; mt < 3; mt++) {
        int m = m0 + mb + mt * 16 + g;
        float bb0 = bias[m], bb1 = bias[m + 8];
        #pragma unroll
        for (int nt = 0; nt < 4; nt++) {
            int col = n0 + nb + nt * 8 + t4 * 2;
            float2 o0 = make_float2(acc[mt][nt][0] + bb0, acc[mt][nt][1] + bb0);
            float2 o1 = make_float2(acc[mt][nt][2] + bb1, acc[mt][nt][3] + bb1);
            *(float2*)&C[m * NPIX + col]       = o0;
            *(float2*)&C[(m + 8) * NPIX + col] = o1;
        }
    }
}

// ---------------------------------------------------------------------------
// GRU update: out[b,t] fp32 + bf16-split hidden copy. t=0: h2h = b_ret.
// grid (64, 32, 2), block 256. Reads g_i2h[t&1].
// ---------------------------------------------------------------------------
__global__ void gru_k(int t, int first, const float* __restrict__ bret,
                      float* __restrict__ outp)
{
    int pix = blockIdx.x * 256 + threadIdx.x;
    int c2  = blockIdx.y;
    int b   = blockIdx.z;
    int c   = 2 * c2;
    int base = b * 192 * NPIX;
    const float* ib = g_i2h[t & 1];

    float h01[2];
    #pragma unroll
    for (int j = 0; j < 2; j++) {
        int cj = c + j;
        float ir = ib[base + (cj      ) * NPIX + pix];
        float iu = ib[base + (cj +  64) * NPIX + pix];
        float im = ib[base + (cj + 128) * NPIX + pix];
        float hr, hu, hm;
        if (first) {
            hr = bret[cj]; hu = bret[cj + 64]; hm = bret[cj + 128];
        } else {
            hr = g_h2h[base + (cj      ) * NPIX + pix];
            hu = g_h2h[base + (cj +  64) * NPIX + pix];
            hm = g_h2h[base + (cj + 128) * NPIX + pix];
        }

        float r = 1.f / (1.f + expf(-(ir + hr)));
        float z = 1.f / (1.f + expf(-(iu + hu)));
        float m = leaky_f(im + r * hm);

        float hp = first ? 0.f : outp[((b * 6 + t - 1) * 64 + cj) * NPIX + pix];
        float h  = z * hp + (1.f - z) * m;
        outp[((b * 6 + t) * 64 + cj) * NPIX + pix] = h;
        h01[j] = h;
    }
    uint32_t hw, lw;
    split2(h01[0], h01[1], hw, lw);
    int p = (b * 32 + c2) * NPIX + pix;
    g_hbf_h[p] = hw; g_hbf_l[p] = lw;
}

// ---------------------------------------------------------------------------
// Launch
// ---------------------------------------------------------------------------
extern "C" void kernel_launch(void* const* d_in, const int* in_sizes, int n_in,
                              void* d_out, int out_size)
{
    const float* x      = (const float*)d_in[0];
    const float* w_stem = (const float*)d_in[1];
    const float* b_stem = (const float*)d_in[2];
    const float* w_i2h  = (const float*)d_in[3];
    const float* b_i2h  = (const float*)d_in[4];
    const float* w_i2f  = (const float*)d_in[5];
    const float* b_i2f  = (const float*)d_in[6];
    const float* w_h2f  = (const float*)d_in[7];
    const float* b_h2f  = (const float*)d_in[8];
    const float* w_flow = (const float*)d_in[9];
    const float* b_flow = (const float*)d_in[10];
    const float* w_ret  = (const float*)d_in[11];
    const float* b_ret  = (const float*)d_in[12];
    float* outp = (float*)d_out;

    cudaFuncSetAttribute(i2h_k,  cudaFuncAttributeMaxDynamicSharedMemorySize, I2H_SMEM_BYTES);
    cudaFuncSetAttribute(f1_k,   cudaFuncAttributeMaxDynamicSharedMemorySize, F1_SMEM_BYTES);
    cudaFuncSetAttribute(flow_k, cudaFuncAttributeMaxDynamicSharedMemorySize, FLOW_SMEM_BYTES);
    cudaFuncSetAttribute(wreti_k, cudaFuncAttributeMaxDynamicSharedMemorySize, I2H_SMEM_BYTES);

    wprep_all_k<<<(199168 + 255) / 256, 256>>>(w_i2h, w_i2f, w_h2f, w_flow, w_ret);

    stem_k<<<dim3(64, 48, 2), 256>>>(x, w_stem, b_stem);

    // i2h(0) upfront into buffer 0
    i2h_k<<<dim3(64, 3, 2), 256, I2H_SMEM_BYTES>>>(0, 0, b_i2h);

    for (int t = 0; t < 6; t++) {
        int first = (t == 0) ? 1 : 0;
        f1_k  <<<dim3(128, 1, 2), 256, F1_SMEM_BYTES>>>(t, first);
        flow_k<<<dim3(128, 1, 2), 256, FLOW_SMEM_BYTES>>>(b_flow, b_i2f, b_h2f, first);
        if (first) {
            // i2h(1) into buffer 1 (fills the empty wret slot at t=0)
            i2h_k<<<dim3(64, 3, 2), 256, I2H_SMEM_BYTES>>>(1, 1, b_i2h);
        } else {
            int nblk = (t < 5) ? 448 : 256;   // append i2h(t+1) roles when needed
            wreti_k<<<dim3(nblk, 1, 2), 256, I2H_SMEM_BYTES>>>(t, b_ret, b_i2h, outp);
        }
        gru_k<<<dim3(64, 32, 2), 256>>>(t, first, b_ret, outp);
    }
}